// round 8
// baseline (speedup 1.0000x reference)
#include <cuda_runtime.h>
#include <cuda_bf16.h>
#include <math.h>
#include <stdint.h>

// Problem constants
#define BATCH 2
#define SEQ   2048
#define HID   2048
#define NH    32
#define NKV   4
#define HD    128
#define NTOK  (BATCH*SEQ)          // 4096
#define QCOLS (NH*HD)              // 4096
#define KVCOLS (NKV*HD)            // 512

typedef __nv_bfloat16 bf16;

// -------- scratch (device globals: no runtime allocation allowed) --------
__device__ float g_Q[(size_t)NTOK * QCOLS];    // 64 MiB
__device__ float g_K[(size_t)NTOK * KVCOLS];   // 8 MiB
__device__ float g_V[(size_t)NTOK * KVCOLS];   // 8 MiB
__device__ float g_CTX[(size_t)NTOK * QCOLS];  // 64 MiB
// pre-split bf16 operands
__device__ bf16 g_Hh[(size_t)NTOK * HID],   g_Hl[(size_t)NTOK * HID];     // hidden
__device__ bf16 g_Wh[(size_t)HID * QCOLS],  g_Wl[(size_t)HID * QCOLS];    // current weight
__device__ bf16 g_Ch[(size_t)NTOK * QCOLS], g_Cl[(size_t)NTOK * QCOLS];   // ctx
__device__ bf16 g_KthH[(size_t)BATCH*NKV*HD*SEQ], g_KthL[(size_t)BATCH*NKV*HD*SEQ]; // K transposed
__device__ bf16 g_VhS[(size_t)NTOK * KVCOLS], g_VlS[(size_t)NTOK * KVCOLS];

// ============================================================================
// PTX helpers
// ============================================================================
__device__ __forceinline__ uint32_t smem_u32(const void* p) {
    return (uint32_t)__cvta_generic_to_shared(p);
}
__device__ __forceinline__ void ldmatrix_x4(uint32_t* r, uint32_t addr) {
    asm volatile("ldmatrix.sync.aligned.m8n8.x4.shared.b16 {%0,%1,%2,%3}, [%4];"
                 : "=r"(r[0]), "=r"(r[1]), "=r"(r[2]), "=r"(r[3]) : "r"(addr));
}
__device__ __forceinline__ void ldmatrix_x4_trans(uint32_t* r, uint32_t addr) {
    asm volatile("ldmatrix.sync.aligned.m8n8.x4.trans.shared.b16 {%0,%1,%2,%3}, [%4];"
                 : "=r"(r[0]), "=r"(r[1]), "=r"(r[2]), "=r"(r[3]) : "r"(addr));
}
__device__ __forceinline__ void mma_bf16(float* d, const uint32_t* a, const uint32_t* b) {
    asm volatile("mma.sync.aligned.m16n8k16.row.col.f32.bf16.bf16.f32 "
                 "{%0,%1,%2,%3}, {%4,%5,%6,%7}, {%8,%9}, {%0,%1,%2,%3};"
                 : "+f"(d[0]), "+f"(d[1]), "+f"(d[2]), "+f"(d[3])
                 : "r"(a[0]), "r"(a[1]), "r"(a[2]), "r"(a[3]),
                   "r"(b[0]), "r"(b[1]));
}
__device__ __forceinline__ void split2(float x, bf16& h, bf16& l) {
    h = __float2bfloat16_rn(x);
    l = __float2bfloat16_rn(x - __bfloat162float(h));
}
__device__ __forceinline__ uint32_t pack_bf16x2(float lo, float hi) {
    __nv_bfloat162 r = __floats2bfloat162_rn(lo, hi);
    return *(uint32_t*)&r;
}
__device__ __forceinline__ void split4_pack(float4 v, uint2& hh, uint2& ll) {
    bf16 hx, lx, hy, ly, hz, lz, hw, lw;
    split2(v.x, hx, lx); split2(v.y, hy, ly);
    split2(v.z, hz, lz); split2(v.w, hw, lw);
    hh.x = pack_bf16x2(__bfloat162float(hx), __bfloat162float(hy));
    hh.y = pack_bf16x2(__bfloat162float(hz), __bfloat162float(hw));
    ll.x = pack_bf16x2(__bfloat162float(lx), __bfloat162float(ly));
    ll.y = pack_bf16x2(__bfloat162float(lz), __bfloat162float(lw));
}
__device__ __forceinline__ void cp_async16(uint32_t dst, const void* src) {
    asm volatile("cp.async.cg.shared.global [%0], [%1], 16;" :: "r"(dst), "l"(src));
}
#define CP_COMMIT asm volatile("cp.async.commit_group;")
#define CP_WAIT0  asm volatile("cp.async.wait_group 0;" ::: "memory")
#define CP_WAIT1  asm volatile("cp.async.wait_group 1;" ::: "memory")

// ============================================================================
// Split kernels (memory-bound, one-shot)
// ============================================================================
__global__ __launch_bounds__(256)
void split_mat(const float* __restrict__ src, bf16* __restrict__ dh,
               bf16* __restrict__ dl, int n4)
{
    const int i = blockIdx.x * 256 + threadIdx.x;
    if (i < n4) {
        float4 v = ((const float4*)src)[i];
        uint2 hh, ll;
        split4_pack(v, hh, ll);
        ((uint2*)dh)[i] = hh;
        ((uint2*)dl)[i] = ll;
    }
}

// K fp32 [b*S+tok][hk*128+d]  ->  Kth bf16 [(b*NKV+hk)*128+d][tok]
__global__ __launch_bounds__(256)
void split_k_trans(const float* __restrict__ Ksrc, bf16* __restrict__ dh,
                   bf16* __restrict__ dl)
{
    const int blk = blockIdx.x;          // 0..BATCH*NKV*HD-1
    const int bhk = blk >> 7;
    const int d   = blk & 127;
    const int b   = bhk >> 2, hk = bhk & 3;
    const int t0  = threadIdx.x * 8;
    const float* src = Ksrc + ((size_t)b * SEQ + t0) * KVCOLS + hk * HD + d;
    __align__(16) bf16 h8[8];
    __align__(16) bf16 l8[8];
    #pragma unroll
    for (int j = 0; j < 8; j++) split2(src[(size_t)j * KVCOLS], h8[j], l8[j]);
    const size_t o = ((size_t)bhk * HD + d) * SEQ + t0;
    *(uint4*)&dh[o] = *(uint4*)h8;
    *(uint4*)&dl[o] = *(uint4*)l8;
}

// ============================================================================
// GEMM on pre-split bf16: C[M,N] = Ah*Bh + Ah*Bl + Al*Bh  (fp32 out)
// CTA 128x128, BK=32, 128 threads (4 warps, 64x64 warp tile), cp.async
// double-buffered. 6 MMAs per LDSM (vs 4 in the 8-warp layout).
// ============================================================================
#define ASTR 40
#define BSTR 136
#define GB_A_H 0
#define GB_A_L 10240
#define GB_B_H 20480
#define GB_B_L 29184
#define GB_SZ  37888
#define GEMM_SMEM (2 * GB_SZ)

__global__ __launch_bounds__(128, 2)
void gemm_pre(const bf16* __restrict__ Ah_g, const bf16* __restrict__ Al_g,
              const bf16* __restrict__ Bh_g, const bf16* __restrict__ Bl_g,
              float* __restrict__ C, int M, int N, int K)
{
    extern __shared__ char smg[];
    const uint32_t sb = smem_u32(smg);

    const int tid  = threadIdx.x;
    const int warp = tid >> 5;
    const int lane = tid & 31;
    const int wm = (warp >> 1) * 64;     // 0 or 64
    const int wn = (warp & 1) * 64;      // 0 or 64
    const int bx = blockIdx.x * 128;
    const int by = blockIdx.y * 128;

    float acc[4][8][4];
    #pragma unroll
    for (int mi = 0; mi < 4; mi++)
        #pragma unroll
        for (int ni = 0; ni < 8; ni++)
            #pragma unroll
            for (int e = 0; e < 4; e++) acc[mi][ni][e] = 0.f;

    // loader mapping (128 threads)
    const int ar = tid;                                // A row 0..127 (32 elems each)
    const int brw = tid >> 2, bcb = (tid & 3) * 32;    // B row 0..31, col base

    auto issue_tile = [&](int k0, uint32_t bufb) {
        const bf16* a_h = Ah_g + (size_t)(by + ar) * K + k0;
        const bf16* a_l = Al_g + (size_t)(by + ar) * K + k0;
        const uint32_t da  = bufb + GB_A_H + (uint32_t)(ar * 80);
        const uint32_t dal = bufb + GB_A_L + (uint32_t)(ar * 80);
        #pragma unroll
        for (int u = 0; u < 4; u++) {
            cp_async16(da  + u * 16, a_h + u * 8);
            cp_async16(dal + u * 16, a_l + u * 8);
        }
        const bf16* b_h = Bh_g + (size_t)(k0 + brw) * N + bx + bcb;
        const bf16* b_l = Bl_g + (size_t)(k0 + brw) * N + bx + bcb;
        const uint32_t db  = bufb + GB_B_H + (uint32_t)(brw * 272 + bcb * 2);
        const uint32_t dbl = bufb + GB_B_L + (uint32_t)(brw * 272 + bcb * 2);
        #pragma unroll
        for (int u = 0; u < 4; u++) {
            cp_async16(db  + u * 16, b_h + u * 8);
            cp_async16(dbl + u * 16, b_l + u * 8);
        }
    };

    const int aoff = (wm + (lane & 15)) * ASTR + ((lane >> 4) << 3);
    const int boff = (lane & 15) * BSTR + wn + ((lane >> 4) << 3);

    const int NIT = K >> 5;
    issue_tile(0, sb);
    CP_COMMIT;

    for (int t = 0; t < NIT; t++) {
        __syncthreads();                       // buffer (t+1)&1 free (compute t-1 done)
        if (t + 1 < NIT) {
            issue_tile((t + 1) * 32, sb + ((t + 1) & 1) * GB_SZ);
            CP_COMMIT;
            CP_WAIT1;
        } else {
            CP_WAIT0;
        }
        __syncthreads();                       // buffer t&1 filled & visible

        const uint32_t bufb = sb + (t & 1) * GB_SZ;
        const uint32_t Ah_b = bufb + GB_A_H;
        const uint32_t Al_b = bufb + GB_A_L;
        const uint32_t Bh_b = bufb + GB_B_H;
        const uint32_t Bl_b = bufb + GB_B_L;

        #pragma unroll
        for (int kk = 0; kk < 32; kk += 16) {
            uint32_t ah[4][4], al[4][4];
            #pragma unroll
            for (int mi = 0; mi < 4; mi++) {
                ldmatrix_x4(ah[mi], Ah_b + (aoff + mi * 16 * ASTR + kk) * 2);
                ldmatrix_x4(al[mi], Al_b + (aoff + mi * 16 * ASTR + kk) * 2);
            }
            #pragma unroll
            for (int p = 0; p < 4; p++) {
                uint32_t bh[4], bl[4];
                const uint32_t off = (boff + kk * BSTR + p * 16) * 2;
                ldmatrix_x4_trans(bh, Bh_b + off);
                ldmatrix_x4_trans(bl, Bl_b + off);
                #pragma unroll
                for (int mi = 0; mi < 4; mi++) {
                    mma_bf16(acc[mi][2*p],   ah[mi], bh);
                    mma_bf16(acc[mi][2*p],   ah[mi], bl);
                    mma_bf16(acc[mi][2*p],   al[mi], bh);
                    mma_bf16(acc[mi][2*p+1], ah[mi], bh + 2);
                    mma_bf16(acc[mi][2*p+1], ah[mi], bl + 2);
                    mma_bf16(acc[mi][2*p+1], al[mi], bh + 2);
                }
            }
        }
    }

    const int g = lane >> 2;
    const int t = lane & 3;
    #pragma unroll
    for (int mi = 0; mi < 4; mi++) {
        #pragma unroll
        for (int ni = 0; ni < 8; ni++) {
            const size_t row0 = (size_t)(by + wm + mi * 16 + g);
            const int col = bx + wn + ni * 8 + 2 * t;
            *(float2*)(C + row0 * N + col)       = make_float2(acc[mi][ni][0], acc[mi][ni][1]);
            *(float2*)(C + (row0 + 8) * N + col) = make_float2(acc[mi][ni][2], acc[mi][ni][3]);
        }
    }
}

// ============================================================================
// RMSNorm + RoPE, one block of 128 threads per (token, head). In-place.
// ============================================================================
__global__ __launch_bounds__(128)
void rmsrope_kernel(float* __restrict__ X, const float* __restrict__ w,
                    const int* __restrict__ pos, int nheads)
{
    const int blk = blockIdx.x;
    const int token = blk / nheads;
    const int h     = blk % nheads;
    float* x = X + (size_t)token * (nheads * HD) + h * HD;

    const int i = threadIdx.x;
    float v = x[i];

    float ss = v * v;
    #pragma unroll
    for (int m = 16; m; m >>= 1) ss += __shfl_xor_sync(0xffffffffu, ss, m);
    __shared__ float wsum[4];
    if ((i & 31) == 0) wsum[i >> 5] = ss;
    __syncthreads();
    float tot = wsum[0] + wsum[1] + wsum[2] + wsum[3];
    float inv = rsqrtf(tot * (1.0f / 128.0f) + 1e-6f);

    __shared__ float xs[128];
    xs[i] = v * inv * w[i];
    __syncthreads();

    const int p = pos[token];
    const int j = i & 63;
    float invf = (float)pow(1.0e6, -(double)j / 64.0);
    float f = (float)p * invf;
    float c, s;
    sincosf(f, &s, &c);
    float xi = xs[i];
    float partner = (i < 64) ? -xs[i + 64] : xs[i - 64];
    x[i] = xi * c + partner * s;
}

// ============================================================================
// Tensor-core flash attention on pre-split K/V; Q split in-kernel.
// Br=128 (8 warps x 16 rows), Bc=64, 256 threads, cp.async double-buffered.
// ============================================================================
#define QSTR 136
#define KSTR 72
#define VSTR 136
#define AT_Q_H   0
#define AT_Q_L   (128*QSTR*2)
#define AT_BUF0  (2*128*QSTR*2)
#define AT_KH    0
#define AT_KL    (128*KSTR*2)
#define AT_VH    (2*128*KSTR*2)
#define AT_VL    (2*128*KSTR*2 + 64*VSTR*2)
#define AT_BUFSZ (2*128*KSTR*2 + 2*64*VSTR*2)
#define ATTN_SMEM (AT_BUF0 + 2*AT_BUFSZ)

__global__ __launch_bounds__(256, 1)
void attn_tc_kernel(const float* __restrict__ Q,
                    const bf16* __restrict__ KthH, const bf16* __restrict__ KthL,
                    const bf16* __restrict__ VhG,  const bf16* __restrict__ VlG,
                    float* __restrict__ CTX)
{
    extern __shared__ char sma[];
    const uint32_t sb = smem_u32(sma);
    bf16* Qh = (bf16*)(sma + AT_Q_H);
    bf16* Ql = (bf16*)(sma + AT_Q_L);

    const int qt = gridDim.x - 1 - blockIdx.x;
    const int h  = blockIdx.y;
    const int b  = blockIdx.z;
    const int hk = h >> 3;

    const int tid  = threadIdx.x;
    const int warp = tid >> 5;
    const int lane = tid & 31;
    const int g  = lane >> 2;
    const int t4 = lane & 3;

    const float scale = 0.08838834764831845f;
    const int ntiles = 2 * qt + 2;

    // per-(b,hk) base pointers
    const bf16* kh_g = KthH + (size_t)(b * NKV + hk) * HD * SEQ;
    const bf16* kl_g = KthL + (size_t)(b * NKV + hk) * HD * SEQ;
    const bf16* vh_g = VhG + (size_t)b * SEQ * KVCOLS + hk * HD;
    const bf16* vl_g = VlG + (size_t)b * SEQ * KVCOLS + hk * HD;

    // loader mappings
    const int kd = tid >> 1, kc0 = (tid & 1) * 32;    // K: d-row (0..127), token base
    const int vc = tid >> 2, vd0 = (tid & 3) * 32;    // V: token-row (0..63), d base

    auto issue_kv = [&](int jt, uint32_t bufb) {
        const bf16* kh = kh_g + (size_t)kd * SEQ + jt * 64 + kc0;
        const bf16* kl = kl_g + (size_t)kd * SEQ + jt * 64 + kc0;
        const uint32_t dk  = bufb + AT_KH + (uint32_t)(kd * 144 + kc0 * 2);
        const uint32_t dkl = bufb + AT_KL + (uint32_t)(kd * 144 + kc0 * 2);
        #pragma unroll
        for (int u = 0; u < 4; u++) {
            cp_async16(dk  + u * 16, kh + u * 8);
            cp_async16(dkl + u * 16, kl + u * 8);
        }
        const bf16* vh = vh_g + (size_t)(jt * 64 + vc) * KVCOLS + vd0;
        const bf16* vl = vl_g + (size_t)(jt * 64 + vc) * KVCOLS + vd0;
        const uint32_t dv  = bufb + AT_VH + (uint32_t)(vc * 272 + vd0 * 2);
        const uint32_t dvl = bufb + AT_VL + (uint32_t)(vc * 272 + vd0 * 2);
        #pragma unroll
        for (int u = 0; u < 4; u++) {
            cp_async16(dv  + u * 16, vh + u * 8);
            cp_async16(dvl + u * 16, vl + u * 8);
        }
    };

    // prefetch tile 0, then load+split Q (overlaps cp.async)
    issue_kv(0, sb + AT_BUF0);
    CP_COMMIT;
    {
        const int r  = tid >> 1;
        const int c0 = (tid & 1) * 64;
        const float* src = Q + ((size_t)(b * SEQ + qt * 128 + r)) * QCOLS + h * HD + c0;
        #pragma unroll
        for (int u = 0; u < 16; u++) {
            float4 v = *(const float4*)(src + 4 * u);
            const int c = c0 + 4 * u;
            split2(v.x * scale, Qh[r*QSTR + c+0], Ql[r*QSTR + c+0]);
            split2(v.y * scale, Qh[r*QSTR + c+1], Ql[r*QSTR + c+1]);
            split2(v.z * scale, Qh[r*QSTR + c+2], Ql[r*QSTR + c+2]);
            split2(v.w * scale, Qh[r*QSTR + c+3], Ql[r*QSTR + c+3]);
        }
    }

    float oacc[16][4];
    #pragma unroll
    for (int nt = 0; nt < 16; nt++)
        #pragma unroll
        for (int e = 0; e < 4; e++) oacc[nt][e] = 0.f;
    float mrow0 = -1e30f, mrow1 = -1e30f, lrow0 = 0.f, lrow1 = 0.f;

    const int qrow0 = qt * 128 + warp * 16 + g;
    const int qrow1 = qrow0 + 8;
    const int warp_maxrow = qt * 128 + warp * 16 + 15;

    const uint32_t qh_base = sb + AT_Q_H + ((warp*16 + (lane & 15)) * QSTR + ((lane >> 4) << 3)) * 2;
    const uint32_t ql_base = sb + AT_Q_L + ((warp*16 + (lane & 15)) * QSTR + ((lane >> 4) << 3)) * 2;
    const uint32_t koffB = ((lane & 15) * KSTR + ((lane >> 4) << 3)) * 2;
    const uint32_t voffB = ((lane & 15) * VSTR + ((lane >> 4) << 3)) * 2;

    for (int jt = 0; jt < ntiles; jt++) {
        __syncthreads();                       // buffer (jt+1)&1 free; Q-split visible
        if (jt + 1 < ntiles) {
            issue_kv(jt + 1, sb + AT_BUF0 + ((jt + 1) & 1) * AT_BUFSZ);
            CP_COMMIT;
            CP_WAIT1;
        } else {
            CP_WAIT0;
        }
        __syncthreads();                       // buffer jt&1 ready

        if (jt * 64 > warp_maxrow) continue;   // fully masked for this warp

        const uint32_t bufb = sb + AT_BUF0 + (jt & 1) * AT_BUFSZ;
        const uint32_t kth_b = bufb + AT_KH + koffB;
        const uint32_t ktl_b = bufb + AT_KL + koffB;
        const uint32_t vh_b  = bufb + AT_VH + voffB;
        const uint32_t vl_b  = bufb + AT_VL + voffB;

        // ---- S = Q @ Kt ----
        float sacc[8][4];
        #pragma unroll
        for (int nt = 0; nt < 8; nt++)
            #pragma unroll
            for (int e = 0; e < 4; e++) sacc[nt][e] = 0.f;

        #pragma unroll
        for (int kk = 0; kk < 8; kk++) {
            uint32_t ah[4], al[4];
            ldmatrix_x4(ah, qh_base + kk * 16 * sizeof(bf16));
            ldmatrix_x4(al, ql_base + kk * 16 * sizeof(bf16));
            #pragma unroll
            for (int p = 0; p < 4; p++) {
                uint32_t bh[4], bl[4];
                const uint32_t off = (kk * 16 * KSTR + p * 16) * sizeof(bf16);
                ldmatrix_x4_trans(bh, kth_b + off);
                ldmatrix_x4_trans(bl, ktl_b + off);
                mma_bf16(sacc[2*p],   ah, bh);
                mma_bf16(sacc[2*p],   ah, bl);
                mma_bf16(sacc[2*p],   al, bh);
                mma_bf16(sacc[2*p+1], ah, bh + 2);
                mma_bf16(sacc[2*p+1], ah, bl + 2);
                mma_bf16(sacc[2*p+1], al, bh + 2);
            }
        }

        // ---- causal mask + online softmax ----
        float mx0 = -1e30f, mx1 = -1e30f;
        #pragma unroll
        for (int nt = 0; nt < 8; nt++) {
            const int col = jt * 64 + nt * 8 + 2 * t4;
            if (col     > qrow0) sacc[nt][0] = -1e30f;
            if (col + 1 > qrow0) sacc[nt][1] = -1e30f;
            if (col     > qrow1) sacc[nt][2] = -1e30f;
            if (col + 1 > qrow1) sacc[nt][3] = -1e30f;
            mx0 = fmaxf(mx0, fmaxf(sacc[nt][0], sacc[nt][1]));
            mx1 = fmaxf(mx1, fmaxf(sacc[nt][2], sacc[nt][3]));
        }
        mx0 = fmaxf(mx0, __shfl_xor_sync(0xffffffffu, mx0, 1));
        mx0 = fmaxf(mx0, __shfl_xor_sync(0xffffffffu, mx0, 2));
        mx1 = fmaxf(mx1, __shfl_xor_sync(0xffffffffu, mx1, 1));
        mx1 = fmaxf(mx1, __shfl_xor_sync(0xffffffffu, mx1, 2));

        const float mnew0 = fmaxf(mrow0, mx0);
        const float mnew1 = fmaxf(mrow1, mx1);
        const float alpha0 = __expf(mrow0 - mnew0);
        const float alpha1 = __expf(mrow1 - mnew1);

        float rs0 = 0.f, rs1 = 0.f;
        #pragma unroll
        for (int nt = 0; nt < 8; nt++) {
            sacc[nt][0] = __expf(sacc[nt][0] - mnew0);
            sacc[nt][1] = __expf(sacc[nt][1] - mnew0);
            sacc[nt][2] = __expf(sacc[nt][2] - mnew1);
            sacc[nt][3] = __expf(sacc[nt][3] - mnew1);
            rs0 += sacc[nt][0] + sacc[nt][1];
            rs1 += sacc[nt][2] + sacc[nt][3];
        }
        rs0 += __shfl_xor_sync(0xffffffffu, rs0, 1);
        rs0 += __shfl_xor_sync(0xffffffffu, rs0, 2);
        rs1 += __shfl_xor_sync(0xffffffffu, rs1, 1);
        rs1 += __shfl_xor_sync(0xffffffffu, rs1, 2);

        lrow0 = lrow0 * alpha0 + rs0;
        lrow1 = lrow1 * alpha1 + rs1;
        mrow0 = mnew0;
        mrow1 = mnew1;

        #pragma unroll
        for (int nt = 0; nt < 16; nt++) {
            oacc[nt][0] *= alpha0;
            oacc[nt][1] *= alpha0;
            oacc[nt][2] *= alpha1;
            oacc[nt][3] *= alpha1;
        }

        // ---- O += P @ V ----
        #pragma unroll
        for (int c = 0; c < 4; c++) {
            uint32_t ph[4], pl[4];
            {
                bf16 h00, l00, h01, l01, h02, l02, h03, l03;
                bf16 h10, l10, h11, l11, h12, l12, h13, l13;
                split2(sacc[2*c][0],   h00, l00); split2(sacc[2*c][1],   h01, l01);
                split2(sacc[2*c][2],   h02, l02); split2(sacc[2*c][3],   h03, l03);
                split2(sacc[2*c+1][0], h10, l10); split2(sacc[2*c+1][1], h11, l11);
                split2(sacc[2*c+1][2], h12, l12); split2(sacc[2*c+1][3], h13, l13);
                ph[0] = pack_bf16x2(__bfloat162float(h00), __bfloat162float(h01));
                ph[1] = pack_bf16x2(__bfloat162float(h02), __bfloat162float(h03));
                ph[2] = pack_bf16x2(__bfloat162float(h10), __bfloat162float(h11));
                ph[3] = pack_bf16x2(__bfloat162float(h12), __bfloat162float(h13));
                pl[0] = pack_bf16x2(__bfloat162float(l00), __bfloat162float(l01));
                pl[1] = pack_bf16x2(__bfloat162float(l02), __bfloat162float(l03));
                pl[2] = pack_bf16x2(__bfloat162float(l10), __bfloat162float(l11));
                pl[3] = pack_bf16x2(__bfloat162float(l12), __bfloat162float(l13));
            }
            #pragma unroll
            for (int p = 0; p < 8; p++) {
                uint32_t vh[4], vl[4];
                const uint32_t off = (c * 16 * VSTR + p * 16) * sizeof(bf16);
                ldmatrix_x4_trans(vh, vh_b + off);
                ldmatrix_x4_trans(vl, vl_b + off);
                mma_bf16(oacc[2*p],   ph, vh);
                mma_bf16(oacc[2*p],   pl, vh);
                mma_bf16(oacc[2*p],   ph, vl);
                mma_bf16(oacc[2*p+1], ph, vh + 2);
                mma_bf16(oacc[2*p+1], pl, vh + 2);
                mma_bf16(oacc[2*p+1], ph, vl + 2);
            }
        }
    }

    const float inv0 = 1.0f / lrow0;
    const float inv1 = 1.0f / lrow1;
    float* dst0 = CTX + ((size_t)(b * SEQ + qrow0)) * QCOLS + h * HD;
    float* dst1 = CTX + ((size_t)(b * SEQ + qrow1)) * QCOLS + h * HD;
    #pragma unroll
    for (int nt = 0; nt < 16; nt++) {
        const int col = nt * 8 + 2 * t4;
        *(float2*)(dst0 + col) = make_float2(oacc[nt][0] * inv0, oacc[nt][1] * inv0);
        *(float2*)(dst1 + col) = make_float2(oacc[nt][2] * inv1, oacc[nt][3] * inv1);
    }
}

// ============================================================================
// Launch
// ============================================================================
extern "C" void kernel_launch(void* const* d_in, const int* in_sizes, int n_in,
                              void* d_out, int out_size)
{
    const float* hidden = (const float*)d_in[0];
    const int*   pos    = (const int*)  d_in[2];
    const float* Wq     = (const float*)d_in[3];
    const float* Wk     = (const float*)d_in[4];
    const float* Wv     = (const float*)d_in[5];
    const float* Wo     = (const float*)d_in[6];
    const float* qw     = (const float*)d_in[7];
    const float* kw     = (const float*)d_in[8];
    float* out = (float*)d_out;

    float *Qp, *Kp, *Vp, *Cp;
    bf16 *Hh, *Hl, *Wh, *Wl, *Ch, *Cl, *KtH, *KtL, *Vh, *Vl;
    cudaGetSymbolAddress((void**)&Qp, g_Q);
    cudaGetSymbolAddress((void**)&Kp, g_K);
    cudaGetSymbolAddress((void**)&Vp, g_V);
    cudaGetSymbolAddress((void**)&Cp, g_CTX);
    cudaGetSymbolAddress((void**)&Hh, g_Hh);
    cudaGetSymbolAddress((void**)&Hl, g_Hl);
    cudaGetSymbolAddress((void**)&Wh, g_Wh);
    cudaGetSymbolAddress((void**)&Wl, g_Wl);
    cudaGetSymbolAddress((void**)&Ch, g_Ch);
    cudaGetSymbolAddress((void**)&Cl, g_Cl);
    cudaGetSymbolAddress((void**)&KtH, g_KthH);
    cudaGetSymbolAddress((void**)&KtL, g_KthL);
    cudaGetSymbolAddress((void**)&Vh, g_VhS);
    cudaGetSymbolAddress((void**)&Vl, g_VlS);

    cudaFuncSetAttribute(gemm_pre, cudaFuncAttributeMaxDynamicSharedMemorySize, GEMM_SMEM);
    cudaFuncSetAttribute(attn_tc_kernel, cudaFuncAttributeMaxDynamicSharedMemorySize, ATTN_SMEM);

    // pre-split hidden
    split_mat<<<(NTOK*HID/4 + 255)/256, 256>>>(hidden, Hh, Hl, NTOK*HID/4);

    // Q projection
    split_mat<<<(HID*QCOLS/4 + 255)/256, 256>>>(Wq, Wh, Wl, HID*QCOLS/4);
    gemm_pre<<<dim3(QCOLS/128, NTOK/128), 128, GEMM_SMEM>>>(Hh, Hl, Wh, Wl, Qp, NTOK, QCOLS, HID);
    // K projection
    split_mat<<<(HID*KVCOLS/4 + 255)/256, 256>>>(Wk, Wh, Wl, HID*KVCOLS/4);
    gemm_pre<<<dim3(KVCOLS/128, NTOK/128), 128, GEMM_SMEM>>>(Hh, Hl, Wh, Wl, Kp, NTOK, KVCOLS, HID);
    // V projection
    split_mat<<<(HID*KVCOLS/4 + 255)/256, 256>>>(Wv, Wh, Wl, HID*KVCOLS/4);
    gemm_pre<<<dim3(KVCOLS/128, NTOK/128), 128, GEMM_SMEM>>>(Hh, Hl, Wh, Wl, Vp, NTOK, KVCOLS, HID);

    // RMSNorm + RoPE (fp32 in-place)
    rmsrope_kernel<<<NTOK * NH, 128>>>(Qp, qw, pos, NH);
    rmsrope_kernel<<<NTOK * NKV, 128>>>(Kp, kw, pos, NKV);

    // pre-split K (transposed) and V
    split_k_trans<<<BATCH*NKV*HD, 256>>>(Kp, KtH, KtL);
    split_mat<<<(NTOK*KVCOLS/4 + 255)/256, 256>>>(Vp, Vh, Vl, NTOK*KVCOLS/4);

    // flash attention
    attn_tc_kernel<<<dim3(SEQ/128, NH, BATCH), 256, ATTN_SMEM>>>(Qp, KtH, KtL, Vh, Vl, Cp);

    // output projection
    split_mat<<<(NTOK*QCOLS/4 + 255)/256, 256>>>(Cp, Ch, Cl, NTOK*QCOLS/4);
    split_mat<<<(QCOLS*HID/4 + 255)/256, 256>>>(Wo, Wh, Wl, QCOLS*HID/4);
    gemm_pre<<<dim3(HID/128, NTOK/128), 128, GEMM_SMEM>>>(Ch, Cl, Wh, Wl, out, NTOK, HID, QCOLS);
}

// round 9
// speedup vs baseline: 1.0778x; 1.0778x over previous
#include <cuda_runtime.h>
#include <cuda_bf16.h>
#include <math.h>
#include <stdint.h>

// Problem constants
#define BATCH 2
#define SEQ   2048
#define HID   2048
#define NH    32
#define NKV   4
#define HD    128
#define NTOK  (BATCH*SEQ)          // 4096
#define QCOLS (NH*HD)              // 4096
#define KVCOLS (NKV*HD)            // 512
#define KVW   (2*KVCOLS)           // 1024 (K|V concatenated)

typedef __nv_bfloat16 bf16;

// -------- scratch (device globals) --------
__device__ float g_Q [(size_t)NTOK * QCOLS];    // Q projection out (fp32, pre-norm)
__device__ float g_KV[(size_t)NTOK * KVW];      // K|V projection out (fp32)
__device__ bf16 g_Hh[(size_t)NTOK * HID],   g_Hl[(size_t)NTOK * HID];
__device__ bf16 g_Wh[(size_t)HID * QCOLS],  g_Wl[(size_t)HID * QCOLS];
__device__ bf16 g_Qbh[(size_t)NTOK * QCOLS], g_Qbl[(size_t)NTOK * QCOLS]; // normed+roped+scaled Q
__device__ bf16 g_Ch[(size_t)NTOK * QCOLS], g_Cl[(size_t)NTOK * QCOLS];   // ctx split
__device__ bf16 g_KthH[(size_t)BATCH*NKV*HD*SEQ], g_KthL[(size_t)BATCH*NKV*HD*SEQ];
__device__ bf16 g_VhS[(size_t)NTOK * KVCOLS], g_VlS[(size_t)NTOK * KVCOLS];

// ============================================================================
// PTX helpers
// ============================================================================
__device__ __forceinline__ uint32_t smem_u32(const void* p) {
    return (uint32_t)__cvta_generic_to_shared(p);
}
__device__ __forceinline__ void ldmatrix_x4(uint32_t* r, uint32_t addr) {
    asm volatile("ldmatrix.sync.aligned.m8n8.x4.shared.b16 {%0,%1,%2,%3}, [%4];"
                 : "=r"(r[0]), "=r"(r[1]), "=r"(r[2]), "=r"(r[3]) : "r"(addr));
}
__device__ __forceinline__ void ldmatrix_x4_trans(uint32_t* r, uint32_t addr) {
    asm volatile("ldmatrix.sync.aligned.m8n8.x4.trans.shared.b16 {%0,%1,%2,%3}, [%4];"
                 : "=r"(r[0]), "=r"(r[1]), "=r"(r[2]), "=r"(r[3]) : "r"(addr));
}
__device__ __forceinline__ void mma_bf16(float* d, const uint32_t* a, const uint32_t* b) {
    asm volatile("mma.sync.aligned.m16n8k16.row.col.f32.bf16.bf16.f32 "
                 "{%0,%1,%2,%3}, {%4,%5,%6,%7}, {%8,%9}, {%0,%1,%2,%3};"
                 : "+f"(d[0]), "+f"(d[1]), "+f"(d[2]), "+f"(d[3])
                 : "r"(a[0]), "r"(a[1]), "r"(a[2]), "r"(a[3]),
                   "r"(b[0]), "r"(b[1]));
}
__device__ __forceinline__ void split2(float x, bf16& h, bf16& l) {
    h = __float2bfloat16_rn(x);
    l = __float2bfloat16_rn(x - __bfloat162float(h));
}
__device__ __forceinline__ uint32_t pack_bf16x2(float lo, float hi) {
    __nv_bfloat162 r = __floats2bfloat162_rn(lo, hi);
    return *(uint32_t*)&r;
}
__device__ __forceinline__ void split4_pack(float4 v, uint2& hh, uint2& ll) {
    bf16 hx, lx, hy, ly, hz, lz, hw, lw;
    split2(v.x, hx, lx); split2(v.y, hy, ly);
    split2(v.z, hz, lz); split2(v.w, hw, lw);
    hh.x = pack_bf16x2(__bfloat162float(hx), __bfloat162float(hy));
    hh.y = pack_bf16x2(__bfloat162float(hz), __bfloat162float(hw));
    ll.x = pack_bf16x2(__bfloat162float(lx), __bfloat162float(ly));
    ll.y = pack_bf16x2(__bfloat162float(lz), __bfloat162float(lw));
}
__device__ __forceinline__ void cp_async16(uint32_t dst, const void* src) {
    asm volatile("cp.async.cg.shared.global [%0], [%1], 16;" :: "r"(dst), "l"(src));
}
#define CP_COMMIT asm volatile("cp.async.commit_group;")
#define CP_WAIT0  asm volatile("cp.async.wait_group 0;" ::: "memory")
#define CP_WAIT1  asm volatile("cp.async.wait_group 1;" ::: "memory")

// ============================================================================
// Elementwise kernels
// ============================================================================
__global__ __launch_bounds__(256)
void split_mat(const float* __restrict__ src, bf16* __restrict__ dh,
               bf16* __restrict__ dl, int n4)
{
    const int i = blockIdx.x * 256 + threadIdx.x;
    if (i < n4) {
        float4 v = ((const float4*)src)[i];
        uint2 hh, ll;
        split4_pack(v, hh, ll);
        ((uint2*)dh)[i] = hh;
        ((uint2*)dl)[i] = ll;
    }
}

// Wk[K][512], Wv[K][512] -> combined split [K][1024] (K cols then V cols)
__global__ __launch_bounds__(256)
void split_kv_w(const float* __restrict__ Wk, const float* __restrict__ Wv,
                bf16* __restrict__ dh, bf16* __restrict__ dl)
{
    const int i = blockIdx.x * 256 + threadIdx.x;          // over HID*KVW/4
    if (i >= HID * KVW / 4) return;
    const int row = i / (KVW / 4);
    const int c4  = (i % (KVW / 4)) * 4;
    float4 v;
    if (c4 < KVCOLS) v = *(const float4*)(Wk + (size_t)row * KVCOLS + c4);
    else             v = *(const float4*)(Wv + (size_t)row * KVCOLS + (c4 - KVCOLS));
    uint2 hh, ll;
    split4_pack(v, hh, ll);
    *(uint2*)(dh + (size_t)row * KVW + c4) = hh;
    *(uint2*)(dl + (size_t)row * KVW + c4) = ll;
}

// V part of g_KV (cols 512..1023) -> Vh/Vl [tok][512]
__global__ __launch_bounds__(256)
void split_v(const float* __restrict__ KV, bf16* __restrict__ dh,
             bf16* __restrict__ dl)
{
    const int i = blockIdx.x * 256 + threadIdx.x;          // over NTOK*512/4
    if (i >= NTOK * KVCOLS / 4) return;
    const int tok = i / (KVCOLS / 4);
    const int c4  = (i % (KVCOLS / 4)) * 4;
    float4 v = *(const float4*)(KV + (size_t)tok * KVW + KVCOLS + c4);
    uint2 hh, ll;
    split4_pack(v, hh, ll);
    *(uint2*)(dh + (size_t)tok * KVCOLS + c4) = hh;
    *(uint2*)(dl + (size_t)tok * KVCOLS + c4) = ll;
}

// K part of g_KV -> Kth bf16 [(b*NKV+hk)*128+d][tok]
__global__ __launch_bounds__(256)
void split_k_trans(const float* __restrict__ KV, bf16* __restrict__ dh,
                   bf16* __restrict__ dl)
{
    const int blk = blockIdx.x;          // 0..BATCH*NKV*HD-1
    const int bhk = blk >> 7;
    const int d   = blk & 127;
    const int b   = bhk >> 2, hk = bhk & 3;
    const int t0  = threadIdx.x * 8;
    const float* src = KV + ((size_t)b * SEQ + t0) * KVW + hk * HD + d;
    __align__(16) bf16 h8[8];
    __align__(16) bf16 l8[8];
    #pragma unroll
    for (int j = 0; j < 8; j++) split2(src[(size_t)j * KVW], h8[j], l8[j]);
    const size_t o = ((size_t)bhk * HD + d) * SEQ + t0;
    *(uint4*)&dh[o] = *(uint4*)h8;
    *(uint4*)&dl[o] = *(uint4*)l8;
}

// ============================================================================
// GEMM on pre-split bf16 (round-7 proven config: 256 thr, 32x64 warp tile)
// ============================================================================
#define ASTR 40
#define BSTR 136
#define GB_A_H 0
#define GB_A_L 10240
#define GB_B_H 20480
#define GB_B_L 29184
#define GB_SZ  37888
#define GEMM_SMEM (2 * GB_SZ)

__global__ __launch_bounds__(256, 2)
void gemm_pre(const bf16* __restrict__ Ah_g, const bf16* __restrict__ Al_g,
              const bf16* __restrict__ Bh_g, const bf16* __restrict__ Bl_g,
              float* __restrict__ C, int M, int N, int K)
{
    extern __shared__ char smg[];
    const uint32_t sb = smem_u32(smg);

    const int tid  = threadIdx.x;
    const int warp = tid >> 5;
    const int lane = tid & 31;
    const int wm = (warp >> 1) * 32;
    const int wn = (warp & 1) * 64;
    const int bx = blockIdx.x * 128;
    const int by = blockIdx.y * 128;

    float acc[2][8][4];
    #pragma unroll
    for (int mi = 0; mi < 2; mi++)
        #pragma unroll
        for (int ni = 0; ni < 8; ni++)
            #pragma unroll
            for (int e = 0; e < 4; e++) acc[mi][ni][e] = 0.f;

    const int ar = tid >> 1, acb = (tid & 1) * 16;
    const int brw = tid >> 3, bcb = (tid & 7) * 16;

    auto issue_tile = [&](int k0, uint32_t bufb) {
        const bf16* a_h = Ah_g + (size_t)(by + ar) * K + k0 + acb;
        const bf16* a_l = Al_g + (size_t)(by + ar) * K + k0 + acb;
        const uint32_t da = bufb + GB_A_H + (uint32_t)(ar * 80 + acb * 2);
        const uint32_t dal = bufb + GB_A_L + (uint32_t)(ar * 80 + acb * 2);
        cp_async16(da,       a_h);
        cp_async16(da + 16,  a_h + 8);
        cp_async16(dal,      a_l);
        cp_async16(dal + 16, a_l + 8);
        const bf16* b_h = Bh_g + (size_t)(k0 + brw) * N + bx + bcb;
        const bf16* b_l = Bl_g + (size_t)(k0 + brw) * N + bx + bcb;
        const uint32_t db  = bufb + GB_B_H + (uint32_t)(brw * 272 + bcb * 2);
        const uint32_t dbl = bufb + GB_B_L + (uint32_t)(brw * 272 + bcb * 2);
        cp_async16(db,       b_h);
        cp_async16(db + 16,  b_h + 8);
        cp_async16(dbl,      b_l);
        cp_async16(dbl + 16, b_l + 8);
    };

    const int aoff = (wm + (lane & 15)) * ASTR + ((lane >> 4) << 3);
    const int boff = (lane & 15) * BSTR + wn + ((lane >> 4) << 3);

    const int NIT = K >> 5;
    issue_tile(0, sb);
    CP_COMMIT;

    for (int t = 0; t < NIT; t++) {
        __syncthreads();
        if (t + 1 < NIT) {
            issue_tile((t + 1) * 32, sb + ((t + 1) & 1) * GB_SZ);
            CP_COMMIT;
            CP_WAIT1;
        } else {
            CP_WAIT0;
        }
        __syncthreads();

        const uint32_t bufb = sb + (t & 1) * GB_SZ;
        const uint32_t Ah_b = bufb + GB_A_H;
        const uint32_t Al_b = bufb + GB_A_L;
        const uint32_t Bh_b = bufb + GB_B_H;
        const uint32_t Bl_b = bufb + GB_B_L;

        #pragma unroll
        for (int kk = 0; kk < 32; kk += 16) {
            uint32_t ah[2][4], al[2][4];
            #pragma unroll
            for (int mi = 0; mi < 2; mi++) {
                ldmatrix_x4(ah[mi], Ah_b + (aoff + mi * 16 * ASTR + kk) * 2);
                ldmatrix_x4(al[mi], Al_b + (aoff + mi * 16 * ASTR + kk) * 2);
            }
            #pragma unroll
            for (int p = 0; p < 4; p++) {
                uint32_t bh[4], bl[4];
                const uint32_t off = (boff + kk * BSTR + p * 16) * 2;
                ldmatrix_x4_trans(bh, Bh_b + off);
                ldmatrix_x4_trans(bl, Bl_b + off);
                #pragma unroll
                for (int mi = 0; mi < 2; mi++) {
                    mma_bf16(acc[mi][2*p],   ah[mi], bh);
                    mma_bf16(acc[mi][2*p],   ah[mi], bl);
                    mma_bf16(acc[mi][2*p],   al[mi], bh);
                    mma_bf16(acc[mi][2*p+1], ah[mi], bh + 2);
                    mma_bf16(acc[mi][2*p+1], ah[mi], bl + 2);
                    mma_bf16(acc[mi][2*p+1], al[mi], bh + 2);
                }
            }
        }
    }

    const int g = lane >> 2;
    const int t = lane & 3;
    #pragma unroll
    for (int mi = 0; mi < 2; mi++) {
        #pragma unroll
        for (int ni = 0; ni < 8; ni++) {
            const size_t row0 = (size_t)(by + wm + mi * 16 + g);
            const int col = bx + wn + ni * 8 + 2 * t;
            *(float2*)(C + row0 * N + col)       = make_float2(acc[mi][ni][0], acc[mi][ni][1]);
            *(float2*)(C + (row0 + 8) * N + col) = make_float2(acc[mi][ni][2], acc[mi][ni][3]);
        }
    }
}

// ============================================================================
// RMSNorm + RoPE for Q: fp32 in -> pre-scaled split bf16 out.
// One block of 128 threads per (token, head).
// ============================================================================
__global__ __launch_bounds__(128)
void rmsrope_q_kernel(const float* __restrict__ X, const float* __restrict__ w,
                      const int* __restrict__ pos,
                      bf16* __restrict__ Qh, bf16* __restrict__ Ql)
{
    const int blk = blockIdx.x;
    const int token = blk / NH;
    const int h     = blk % NH;
    const float* x = X + (size_t)token * QCOLS + h * HD;

    const int i = threadIdx.x;
    float v = x[i];

    float ss = v * v;
    #pragma unroll
    for (int m = 16; m; m >>= 1) ss += __shfl_xor_sync(0xffffffffu, ss, m);
    __shared__ float wsum[4];
    if ((i & 31) == 0) wsum[i >> 5] = ss;
    __syncthreads();
    float tot = wsum[0] + wsum[1] + wsum[2] + wsum[3];
    float inv = rsqrtf(tot * (1.0f / 128.0f) + 1e-6f);

    __shared__ float xs[128];
    xs[i] = v * inv * w[i];
    __syncthreads();

    const int p = pos[token];
    const int j = i & 63;
    float invf = (float)pow(1.0e6, -(double)j / 64.0);
    float f = (float)p * invf;
    float c, s;
    sincosf(f, &s, &c);
    float xi = xs[i];
    float partner = (i < 64) ? -xs[i + 64] : xs[i - 64];
    const float scale = 0.08838834764831845f;    // 1/sqrt(128)
    bf16 hh, ll;
    split2((xi * c + partner * s) * scale, hh, ll);
    const size_t o = (size_t)token * QCOLS + h * HD + i;
    Qh[o] = hh;
    Ql[o] = ll;
}

// RMSNorm + RoPE for K, in-place on g_KV (row stride KVW, cols hk*128..).
__global__ __launch_bounds__(128)
void rmsrope_k_kernel(float* __restrict__ KV, const float* __restrict__ w,
                      const int* __restrict__ pos)
{
    const int blk = blockIdx.x;
    const int token = blk / NKV;
    const int hk    = blk % NKV;
    float* x = KV + (size_t)token * KVW + hk * HD;

    const int i = threadIdx.x;
    float v = x[i];

    float ss = v * v;
    #pragma unroll
    for (int m = 16; m; m >>= 1) ss += __shfl_xor_sync(0xffffffffu, ss, m);
    __shared__ float wsum[4];
    if ((i & 31) == 0) wsum[i >> 5] = ss;
    __syncthreads();
    float tot = wsum[0] + wsum[1] + wsum[2] + wsum[3];
    float inv = rsqrtf(tot * (1.0f / 128.0f) + 1e-6f);

    __shared__ float xs[128];
    xs[i] = v * inv * w[i];
    __syncthreads();

    const int p = pos[token];
    const int j = i & 63;
    float invf = (float)pow(1.0e6, -(double)j / 64.0);
    float f = (float)p * invf;
    float c, s;
    sincosf(f, &s, &c);
    float xi = xs[i];
    float partner = (i < 64) ? -xs[i + 64] : xs[i - 64];
    x[i] = xi * c + partner * s;
}

// ============================================================================
// Tensor-core flash attention, fully pre-split operands, cp.async pipelined.
// Br=128 (8 warps x 16 rows), Bc=64, 256 threads.
// ============================================================================
#define QSTR 136
#define KSTR 72
#define VSTR 136
#define AT_Q_H   0
#define AT_Q_L   (128*QSTR*2)
#define AT_BUF0  (2*128*QSTR*2)
#define AT_KH    0
#define AT_KL    (128*KSTR*2)
#define AT_VH    (2*128*KSTR*2)
#define AT_VL    (2*128*KSTR*2 + 64*VSTR*2)
#define AT_BUFSZ (2*128*KSTR*2 + 2*64*VSTR*2)
#define ATTN_SMEM (AT_BUF0 + 2*AT_BUFSZ)

__global__ __launch_bounds__(256, 1)
void attn_tc_kernel(const bf16* __restrict__ QhG, const bf16* __restrict__ QlG,
                    const bf16* __restrict__ KthH, const bf16* __restrict__ KthL,
                    const bf16* __restrict__ VhG,  const bf16* __restrict__ VlG,
                    bf16* __restrict__ Ch, bf16* __restrict__ Cl)
{
    extern __shared__ char sma[];
    const uint32_t sb = smem_u32(sma);

    const int qt = gridDim.x - 1 - blockIdx.x;
    const int h  = blockIdx.y;
    const int b  = blockIdx.z;
    const int hk = h >> 3;

    const int tid  = threadIdx.x;
    const int warp = tid >> 5;
    const int lane = tid & 31;
    const int g  = lane >> 2;
    const int t4 = lane & 3;

    const int ntiles = 2 * qt + 2;

    const bf16* kh_g = KthH + (size_t)(b * NKV + hk) * HD * SEQ;
    const bf16* kl_g = KthL + (size_t)(b * NKV + hk) * HD * SEQ;
    const bf16* vh_g = VhG + (size_t)b * SEQ * KVCOLS + hk * HD;
    const bf16* vl_g = VlG + (size_t)b * SEQ * KVCOLS + hk * HD;

    const int kd = tid >> 1, kc0 = (tid & 1) * 32;    // K: d-row (0..127)
    const int vc = tid >> 2, vd0 = (tid & 3) * 32;    // V: token-row (0..63)

    auto issue_kv = [&](int jt, uint32_t bufb) {
        const bf16* kh = kh_g + (size_t)kd * SEQ + jt * 64 + kc0;
        const bf16* kl = kl_g + (size_t)kd * SEQ + jt * 64 + kc0;
        const uint32_t dk  = bufb + AT_KH + (uint32_t)(kd * 144 + kc0 * 2);
        const uint32_t dkl = bufb + AT_KL + (uint32_t)(kd * 144 + kc0 * 2);
        #pragma unroll
        for (int u = 0; u < 4; u++) {
            cp_async16(dk  + u * 16, kh + u * 8);
            cp_async16(dkl + u * 16, kl + u * 8);
        }
        const bf16* vh = vh_g + (size_t)(jt * 64 + vc) * KVCOLS + vd0;
        const bf16* vl = vl_g + (size_t)(jt * 64 + vc) * KVCOLS + vd0;
        const uint32_t dv  = bufb + AT_VH + (uint32_t)(vc * 272 + vd0 * 2);
        const uint32_t dvl = bufb + AT_VL + (uint32_t)(vc * 272 + vd0 * 2);
        #pragma unroll
        for (int u = 0; u < 4; u++) {
            cp_async16(dv  + u * 16, vh + u * 8);
            cp_async16(dvl + u * 16, vl + u * 8);
        }
    };

    // ---- prefetch Q (bf16, pre-scaled) + KV tile 0 in one group ----
    {
        const int r  = tid >> 1;
        const int c0 = (tid & 1) * 64;
        const bf16* qh = QhG + ((size_t)(b * SEQ + qt * 128 + r)) * QCOLS + h * HD + c0;
        const bf16* ql = QlG + ((size_t)(b * SEQ + qt * 128 + r)) * QCOLS + h * HD + c0;
        const uint32_t dqh = sb + AT_Q_H + (uint32_t)(r * QSTR * 2 + c0 * 2);
        const uint32_t dql = sb + AT_Q_L + (uint32_t)(r * QSTR * 2 + c0 * 2);
        #pragma unroll
        for (int u = 0; u < 8; u++) {
            cp_async16(dqh + u * 16, qh + u * 8);
            cp_async16(dql + u * 16, ql + u * 8);
        }
    }
    issue_kv(0, sb + AT_BUF0);
    CP_COMMIT;

    float oacc[16][4];
    #pragma unroll
    for (int nt = 0; nt < 16; nt++)
        #pragma unroll
        for (int e = 0; e < 4; e++) oacc[nt][e] = 0.f;
    float mrow0 = -1e30f, mrow1 = -1e30f, lrow0 = 0.f, lrow1 = 0.f;

    const int qrow0 = qt * 128 + warp * 16 + g;
    const int qrow1 = qrow0 + 8;
    const int warp_maxrow = qt * 128 + warp * 16 + 15;

    const uint32_t qh_base = sb + AT_Q_H + ((warp*16 + (lane & 15)) * QSTR + ((lane >> 4) << 3)) * 2;
    const uint32_t ql_base = sb + AT_Q_L + ((warp*16 + (lane & 15)) * QSTR + ((lane >> 4) << 3)) * 2;
    const uint32_t koffB = ((lane & 15) * KSTR + ((lane >> 4) << 3)) * 2;
    const uint32_t voffB = ((lane & 15) * VSTR + ((lane >> 4) << 3)) * 2;

    for (int jt = 0; jt < ntiles; jt++) {
        __syncthreads();
        if (jt + 1 < ntiles) {
            issue_kv(jt + 1, sb + AT_BUF0 + ((jt + 1) & 1) * AT_BUFSZ);
            CP_COMMIT;
            CP_WAIT1;
        } else {
            CP_WAIT0;
        }
        __syncthreads();

        if (jt * 64 > warp_maxrow) continue;

        const uint32_t bufb = sb + AT_BUF0 + (jt & 1) * AT_BUFSZ;
        const uint32_t kth_b = bufb + AT_KH + koffB;
        const uint32_t ktl_b = bufb + AT_KL + koffB;
        const uint32_t vh_b  = bufb + AT_VH + voffB;
        const uint32_t vl_b  = bufb + AT_VL + voffB;

        // ---- S = Q @ Kt ----
        float sacc[8][4];
        #pragma unroll
        for (int nt = 0; nt < 8; nt++)
            #pragma unroll
            for (int e = 0; e < 4; e++) sacc[nt][e] = 0.f;

        #pragma unroll
        for (int kk = 0; kk < 8; kk++) {
            uint32_t ah[4], al[4];
            ldmatrix_x4(ah, qh_base + kk * 16 * sizeof(bf16));
            ldmatrix_x4(al, ql_base + kk * 16 * sizeof(bf16));
            #pragma unroll
            for (int p = 0; p < 4; p++) {
                uint32_t bh[4], bl[4];
                const uint32_t off = (kk * 16 * KSTR + p * 16) * sizeof(bf16);
                ldmatrix_x4_trans(bh, kth_b + off);
                ldmatrix_x4_trans(bl, ktl_b + off);
                mma_bf16(sacc[2*p],   ah, bh);
                mma_bf16(sacc[2*p],   ah, bl);
                mma_bf16(sacc[2*p],   al, bh);
                mma_bf16(sacc[2*p+1], ah, bh + 2);
                mma_bf16(sacc[2*p+1], ah, bl + 2);
                mma_bf16(sacc[2*p+1], al, bh + 2);
            }
        }

        // ---- causal mask + online softmax ----
        float mx0 = -1e30f, mx1 = -1e30f;
        #pragma unroll
        for (int nt = 0; nt < 8; nt++) {
            const int col = jt * 64 + nt * 8 + 2 * t4;
            if (col     > qrow0) sacc[nt][0] = -1e30f;
            if (col + 1 > qrow0) sacc[nt][1] = -1e30f;
            if (col     > qrow1) sacc[nt][2] = -1e30f;
            if (col + 1 > qrow1) sacc[nt][3] = -1e30f;
            mx0 = fmaxf(mx0, fmaxf(sacc[nt][0], sacc[nt][1]));
            mx1 = fmaxf(mx1, fmaxf(sacc[nt][2], sacc[nt][3]));
        }
        mx0 = fmaxf(mx0, __shfl_xor_sync(0xffffffffu, mx0, 1));
        mx0 = fmaxf(mx0, __shfl_xor_sync(0xffffffffu, mx0, 2));
        mx1 = fmaxf(mx1, __shfl_xor_sync(0xffffffffu, mx1, 1));
        mx1 = fmaxf(mx1, __shfl_xor_sync(0xffffffffu, mx1, 2));

        const float mnew0 = fmaxf(mrow0, mx0);
        const float mnew1 = fmaxf(mrow1, mx1);
        const float alpha0 = __expf(mrow0 - mnew0);
        const float alpha1 = __expf(mrow1 - mnew1);

        float rs0 = 0.f, rs1 = 0.f;
        #pragma unroll
        for (int nt = 0; nt < 8; nt++) {
            sacc[nt][0] = __expf(sacc[nt][0] - mnew0);
            sacc[nt][1] = __expf(sacc[nt][1] - mnew0);
            sacc[nt][2] = __expf(sacc[nt][2] - mnew1);
            sacc[nt][3] = __expf(sacc[nt][3] - mnew1);
            rs0 += sacc[nt][0] + sacc[nt][1];
            rs1 += sacc[nt][2] + sacc[nt][3];
        }
        rs0 += __shfl_xor_sync(0xffffffffu, rs0, 1);
        rs0 += __shfl_xor_sync(0xffffffffu, rs0, 2);
        rs1 += __shfl_xor_sync(0xffffffffu, rs1, 1);
        rs1 += __shfl_xor_sync(0xffffffffu, rs1, 2);

        lrow0 = lrow0 * alpha0 + rs0;
        lrow1 = lrow1 * alpha1 + rs1;
        mrow0 = mnew0;
        mrow1 = mnew1;

        #pragma unroll
        for (int nt = 0; nt < 16; nt++) {
            oacc[nt][0] *= alpha0;
            oacc[nt][1] *= alpha0;
            oacc[nt][2] *= alpha1;
            oacc[nt][3] *= alpha1;
        }

        // ---- O += P @ V ----
        #pragma unroll
        for (int c = 0; c < 4; c++) {
            uint32_t ph[4], pl[4];
            {
                bf16 h00, l00, h01, l01, h02, l02, h03, l03;
                bf16 h10, l10, h11, l11, h12, l12, h13, l13;
                split2(sacc[2*c][0],   h00, l00); split2(sacc[2*c][1],   h01, l01);
                split2(sacc[2*c][2],   h02, l02); split2(sacc[2*c][3],   h03, l03);
                split2(sacc[2*c+1][0], h10, l10); split2(sacc[2*c+1][1], h11, l11);
                split2(sacc[2*c+1][2], h12, l12); split2(sacc[2*c+1][3], h13, l13);
                ph[0] = pack_bf16x2(__bfloat162float(h00), __bfloat162float(h01));
                ph[1] = pack_bf16x2(__bfloat162float(h02), __bfloat162float(h03));
                ph[2] = pack_bf16x2(__bfloat162float(h10), __bfloat162float(h11));
                ph[3] = pack_bf16x2(__bfloat162float(h12), __bfloat162float(h13));
                pl[0] = pack_bf16x2(__bfloat162float(l00), __bfloat162float(l01));
                pl[1] = pack_bf16x2(__bfloat162float(l02), __bfloat162float(l03));
                pl[2] = pack_bf16x2(__bfloat162float(l10), __bfloat162float(l11));
                pl[3] = pack_bf16x2(__bfloat162float(l12), __bfloat162float(l13));
            }
            #pragma unroll
            for (int p = 0; p < 8; p++) {
                uint32_t vh[4], vl[4];
                const uint32_t off = (c * 16 * VSTR + p * 16) * sizeof(bf16);
                ldmatrix_x4_trans(vh, vh_b + off);
                ldmatrix_x4_trans(vl, vl_b + off);
                mma_bf16(oacc[2*p],   ph, vh);
                mma_bf16(oacc[2*p],   pl, vh);
                mma_bf16(oacc[2*p],   ph, vl);
                mma_bf16(oacc[2*p+1], ph, vh + 2);
                mma_bf16(oacc[2*p+1], pl, vh + 2);
                mma_bf16(oacc[2*p+1], ph, vl + 2);
            }
        }
    }

    // ---- epilogue: write split ctx directly ----
    const float inv0 = 1.0f / lrow0;
    const float inv1 = 1.0f / lrow1;
    const size_t o0 = ((size_t)(b * SEQ + qrow0)) * QCOLS + h * HD;
    const size_t o1 = ((size_t)(b * SEQ + qrow1)) * QCOLS + h * HD;
    #pragma unroll
    for (int nt = 0; nt < 16; nt++) {
        const int col = nt * 8 + 2 * t4;
        bf16 h0, l0, h1, l1;
        split2(oacc[nt][0] * inv0, h0, l0);
        split2(oacc[nt][1] * inv0, h1, l1);
        *(uint32_t*)(Ch + o0 + col) = pack_bf16x2(__bfloat162float(h0), __bfloat162float(h1));
        *(uint32_t*)(Cl + o0 + col) = pack_bf16x2(__bfloat162float(l0), __bfloat162float(l1));
        split2(oacc[nt][2] * inv1, h0, l0);
        split2(oacc[nt][3] * inv1, h1, l1);
        *(uint32_t*)(Ch + o1 + col) = pack_bf16x2(__bfloat162float(h0), __bfloat162float(h1));
        *(uint32_t*)(Cl + o1 + col) = pack_bf16x2(__bfloat162float(l0), __bfloat162float(l1));
    }
}

// ============================================================================
// Launch
// ============================================================================
extern "C" void kernel_launch(void* const* d_in, const int* in_sizes, int n_in,
                              void* d_out, int out_size)
{
    const float* hidden = (const float*)d_in[0];
    const int*   pos    = (const int*)  d_in[2];
    const float* Wq     = (const float*)d_in[3];
    const float* Wk     = (const float*)d_in[4];
    const float* Wv     = (const float*)d_in[5];
    const float* Wo     = (const float*)d_in[6];
    const float* qw     = (const float*)d_in[7];
    const float* kw     = (const float*)d_in[8];
    float* out = (float*)d_out;

    float *Qp, *KVp;
    bf16 *Hh, *Hl, *Wh, *Wl, *Qbh, *Qbl, *Ch, *Cl, *KtH, *KtL, *Vh, *Vl;
    cudaGetSymbolAddress((void**)&Qp,  g_Q);
    cudaGetSymbolAddress((void**)&KVp, g_KV);
    cudaGetSymbolAddress((void**)&Hh,  g_Hh);
    cudaGetSymbolAddress((void**)&Hl,  g_Hl);
    cudaGetSymbolAddress((void**)&Wh,  g_Wh);
    cudaGetSymbolAddress((void**)&Wl,  g_Wl);
    cudaGetSymbolAddress((void**)&Qbh, g_Qbh);
    cudaGetSymbolAddress((void**)&Qbl, g_Qbl);
    cudaGetSymbolAddress((void**)&Ch,  g_Ch);
    cudaGetSymbolAddress((void**)&Cl,  g_Cl);
    cudaGetSymbolAddress((void**)&KtH, g_KthH);
    cudaGetSymbolAddress((void**)&KtL, g_KthL);
    cudaGetSymbolAddress((void**)&Vh,  g_VhS);
    cudaGetSymbolAddress((void**)&Vl,  g_VlS);

    cudaFuncSetAttribute(gemm_pre, cudaFuncAttributeMaxDynamicSharedMemorySize, GEMM_SMEM);
    cudaFuncSetAttribute(attn_tc_kernel, cudaFuncAttributeMaxDynamicSharedMemorySize, ATTN_SMEM);

    // pre-split hidden
    split_mat<<<(NTOK*HID/4 + 255)/256, 256>>>(hidden, Hh, Hl, NTOK*HID/4);

    // Q projection
    split_mat<<<(HID*QCOLS/4 + 255)/256, 256>>>(Wq, Wh, Wl, HID*QCOLS/4);
    gemm_pre<<<dim3(QCOLS/128, NTOK/128), 256, GEMM_SMEM>>>(Hh, Hl, Wh, Wl, Qp, NTOK, QCOLS, HID);

    // combined K|V projection (one launch, 256 CTAs)
    split_kv_w<<<(HID*KVW/4 + 255)/256, 256>>>(Wk, Wv, Wh, Wl);
    gemm_pre<<<dim3(KVW/128, NTOK/128), 256, GEMM_SMEM>>>(Hh, Hl, Wh, Wl, KVp, NTOK, KVW, HID);

    // RMSNorm + RoPE (Q emits pre-scaled split bf16; K in-place fp32)
    rmsrope_q_kernel<<<NTOK * NH, 128>>>(Qp, qw, pos, Qbh, Qbl);
    rmsrope_k_kernel<<<NTOK * NKV, 128>>>(KVp, kw, pos);

    // pre-split K (transposed) and V
    split_k_trans<<<BATCH*NKV*HD, 256>>>(KVp, KtH, KtL);
    split_v<<<(NTOK*KVCOLS/4 + 255)/256, 256>>>(KVp, Vh, Vl);

    // flash attention (writes split ctx)
    attn_tc_kernel<<<dim3(SEQ/128, NH, BATCH), 256, ATTN_SMEM>>>(Qbh, Qbl, KtH, KtL, Vh, Vl, Ch, Cl);

    // output projection
    split_mat<<<(QCOLS*HID/4 + 255)/256, 256>>>(Wo, Wh, Wl, QCOLS*HID/4);
    gemm_pre<<<dim3(HID/128, NTOK/128), 256, GEMM_SMEM>>>(Ch, Cl, Wh, Wl, out, NTOK, HID, QCOLS);
}

// round 10
// speedup vs baseline: 1.1515x; 1.0684x over previous
#include <cuda_runtime.h>
#include <cuda_bf16.h>
#include <cuda_fp16.h>
#include <math.h>
#include <stdint.h>

// Problem constants
#define BATCH 2
#define SEQ   2048
#define HID   2048
#define NH    32
#define NKV   4
#define HD    128
#define NTOK  (BATCH*SEQ)          // 4096
#define QCOLS (NH*HD)              // 4096
#define KVCOLS (NKV*HD)            // 512
#define KVW   (2*KVCOLS)           // 1024 (K|V concatenated)

typedef __nv_bfloat16 bf16;
typedef __half f16;

// -------- scratch (device globals) --------
__device__ float g_Q [(size_t)NTOK * QCOLS];    // Q projection out (fp32, pre-norm)
__device__ float g_KV[(size_t)NTOK * KVW];      // K|V projection out (fp32)
__device__ bf16 g_Hh[(size_t)NTOK * HID],   g_Hl[(size_t)NTOK * HID];
__device__ bf16 g_Wh[(size_t)HID * QCOLS],  g_Wl[(size_t)HID * QCOLS]; // also aliased as f16 Wo
__device__ bf16 g_Qbh[(size_t)NTOK * QCOLS], g_Qbl[(size_t)NTOK * QCOLS];
__device__ f16  g_Ch[(size_t)NTOK * QCOLS], g_Cl[(size_t)NTOK * QCOLS];   // ctx split (fp16)
__device__ bf16 g_KthH[(size_t)BATCH*NKV*HD*SEQ], g_KthL[(size_t)BATCH*NKV*HD*SEQ];
__device__ f16  g_V16[(size_t)NTOK * KVCOLS];   // V rounded to fp16

// ============================================================================
// PTX helpers
// ============================================================================
__device__ __forceinline__ uint32_t smem_u32(const void* p) {
    return (uint32_t)__cvta_generic_to_shared(p);
}
__device__ __forceinline__ void ldmatrix_x4(uint32_t* r, uint32_t addr) {
    asm volatile("ldmatrix.sync.aligned.m8n8.x4.shared.b16 {%0,%1,%2,%3}, [%4];"
                 : "=r"(r[0]), "=r"(r[1]), "=r"(r[2]), "=r"(r[3]) : "r"(addr));
}
__device__ __forceinline__ void ldmatrix_x4_trans(uint32_t* r, uint32_t addr) {
    asm volatile("ldmatrix.sync.aligned.m8n8.x4.trans.shared.b16 {%0,%1,%2,%3}, [%4];"
                 : "=r"(r[0]), "=r"(r[1]), "=r"(r[2]), "=r"(r[3]) : "r"(addr));
}
__device__ __forceinline__ void mma_bf16(float* d, const uint32_t* a, const uint32_t* b) {
    asm volatile("mma.sync.aligned.m16n8k16.row.col.f32.bf16.bf16.f32 "
                 "{%0,%1,%2,%3}, {%4,%5,%6,%7}, {%8,%9}, {%0,%1,%2,%3};"
                 : "+f"(d[0]), "+f"(d[1]), "+f"(d[2]), "+f"(d[3])
                 : "r"(a[0]), "r"(a[1]), "r"(a[2]), "r"(a[3]),
                   "r"(b[0]), "r"(b[1]));
}
__device__ __forceinline__ void mma_f16(float* d, const uint32_t* a, const uint32_t* b) {
    asm volatile("mma.sync.aligned.m16n8k16.row.col.f32.f16.f16.f32 "
                 "{%0,%1,%2,%3}, {%4,%5,%6,%7}, {%8,%9}, {%0,%1,%2,%3};"
                 : "+f"(d[0]), "+f"(d[1]), "+f"(d[2]), "+f"(d[3])
                 : "r"(a[0]), "r"(a[1]), "r"(a[2]), "r"(a[3]),
                   "r"(b[0]), "r"(b[1]));
}
__device__ __forceinline__ void split2(float x, bf16& h, bf16& l) {
    h = __float2bfloat16_rn(x);
    l = __float2bfloat16_rn(x - __bfloat162float(h));
}
__device__ __forceinline__ void split2h(float x, f16& h, f16& l) {
    h = __float2half_rn(x);
    l = __float2half_rn(x - __half2float(h));
}
__device__ __forceinline__ uint32_t pack_bf16x2(float lo, float hi) {
    __nv_bfloat162 r = __floats2bfloat162_rn(lo, hi);
    return *(uint32_t*)&r;
}
__device__ __forceinline__ uint32_t pack_h2(f16 lo, f16 hi) {
    __half2 r = __halves2half2(lo, hi);
    return *(uint32_t*)&r;
}
__device__ __forceinline__ void split4_pack(float4 v, uint2& hh, uint2& ll) {
    bf16 hx, lx, hy, ly, hz, lz, hw, lw;
    split2(v.x, hx, lx); split2(v.y, hy, ly);
    split2(v.z, hz, lz); split2(v.w, hw, lw);
    hh.x = pack_bf16x2(__bfloat162float(hx), __bfloat162float(hy));
    hh.y = pack_bf16x2(__bfloat162float(hz), __bfloat162float(hw));
    ll.x = pack_bf16x2(__bfloat162float(lx), __bfloat162float(ly));
    ll.y = pack_bf16x2(__bfloat162float(lz), __bfloat162float(lw));
}
__device__ __forceinline__ uint2 round4_f16(float4 v) {
    uint2 r;
    __half2 a = __floats2half2_rn(v.x, v.y);
    __half2 b = __floats2half2_rn(v.z, v.w);
    r.x = *(uint32_t*)&a;
    r.y = *(uint32_t*)&b;
    return r;
}
__device__ __forceinline__ void cp_async16(uint32_t dst, const void* src) {
    asm volatile("cp.async.cg.shared.global [%0], [%1], 16;" :: "r"(dst), "l"(src));
}
#define CP_COMMIT asm volatile("cp.async.commit_group;")
#define CP_WAIT0  asm volatile("cp.async.wait_group 0;" ::: "memory")
#define CP_WAIT1  asm volatile("cp.async.wait_group 1;" ::: "memory")

// ============================================================================
// Elementwise kernels
// ============================================================================
__global__ __launch_bounds__(256)
void split_mat(const float* __restrict__ src, bf16* __restrict__ dh,
               bf16* __restrict__ dl, int n4)
{
    const int i = blockIdx.x * 256 + threadIdx.x;
    if (i < n4) {
        float4 v = ((const float4*)src)[i];
        uint2 hh, ll;
        split4_pack(v, hh, ll);
        ((uint2*)dh)[i] = hh;
        ((uint2*)dl)[i] = ll;
    }
}

__global__ __launch_bounds__(256)
void round_f16_mat(const float* __restrict__ src, f16* __restrict__ d, int n4)
{
    const int i = blockIdx.x * 256 + threadIdx.x;
    if (i < n4) ((uint2*)d)[i] = round4_f16(((const float4*)src)[i]);
}

// Wk[K][512], Wv[K][512] -> combined split [K][1024]
__global__ __launch_bounds__(256)
void split_kv_w(const float* __restrict__ Wk, const float* __restrict__ Wv,
                bf16* __restrict__ dh, bf16* __restrict__ dl)
{
    const int i = blockIdx.x * 256 + threadIdx.x;
    if (i >= HID * KVW / 4) return;
    const int row = i / (KVW / 4);
    const int c4  = (i % (KVW / 4)) * 4;
    float4 v;
    if (c4 < KVCOLS) v = *(const float4*)(Wk + (size_t)row * KVCOLS + c4);
    else             v = *(const float4*)(Wv + (size_t)row * KVCOLS + (c4 - KVCOLS));
    uint2 hh, ll;
    split4_pack(v, hh, ll);
    *(uint2*)(dh + (size_t)row * KVW + c4) = hh;
    *(uint2*)(dl + (size_t)row * KVW + c4) = ll;
}

// V part of g_KV -> single fp16 [tok][512]
__global__ __launch_bounds__(256)
void split_v16(const float* __restrict__ KV, f16* __restrict__ d)
{
    const int i = blockIdx.x * 256 + threadIdx.x;
    if (i >= NTOK * KVCOLS / 4) return;
    const int tok = i / (KVCOLS / 4);
    const int c4  = (i % (KVCOLS / 4)) * 4;
    float4 v = *(const float4*)(KV + (size_t)tok * KVW + KVCOLS + c4);
    *(uint2*)(d + (size_t)tok * KVCOLS + c4) = round4_f16(v);
}

// K part of g_KV -> Kth bf16 [(b*NKV+hk)*128+d][tok]
__global__ __launch_bounds__(256)
void split_k_trans(const float* __restrict__ KV, bf16* __restrict__ dh,
                   bf16* __restrict__ dl)
{
    const int blk = blockIdx.x;
    const int bhk = blk >> 7;
    const int d   = blk & 127;
    const int b   = bhk >> 2, hk = bhk & 3;
    const int t0  = threadIdx.x * 8;
    const float* src = KV + ((size_t)b * SEQ + t0) * KVW + hk * HD + d;
    __align__(16) bf16 h8[8];
    __align__(16) bf16 l8[8];
    #pragma unroll
    for (int j = 0; j < 8; j++) split2(src[(size_t)j * KVW], h8[j], l8[j]);
    const size_t o = ((size_t)bhk * HD + d) * SEQ + t0;
    *(uint4*)&dh[o] = *(uint4*)h8;
    *(uint4*)&dl[o] = *(uint4*)l8;
}

// ============================================================================
// GEMM bf16 3-term (Q/KV projections) — proven round-7 config.
// ============================================================================
#define ASTR 40
#define BSTR 136
#define GB_A_H 0
#define GB_A_L 10240
#define GB_B_H 20480
#define GB_B_L 29184
#define GB_SZ  37888
#define GEMM_SMEM (2 * GB_SZ)

__global__ __launch_bounds__(256, 2)
void gemm_pre(const bf16* __restrict__ Ah_g, const bf16* __restrict__ Al_g,
              const bf16* __restrict__ Bh_g, const bf16* __restrict__ Bl_g,
              float* __restrict__ C, int M, int N, int K)
{
    extern __shared__ char smg[];
    const uint32_t sb = smem_u32(smg);

    const int tid  = threadIdx.x;
    const int warp = tid >> 5;
    const int lane = tid & 31;
    const int wm = (warp >> 1) * 32;
    const int wn = (warp & 1) * 64;
    const int bx = blockIdx.x * 128;
    const int by = blockIdx.y * 128;

    float acc[2][8][4];
    #pragma unroll
    for (int mi = 0; mi < 2; mi++)
        #pragma unroll
        for (int ni = 0; ni < 8; ni++)
            #pragma unroll
            for (int e = 0; e < 4; e++) acc[mi][ni][e] = 0.f;

    const int ar = tid >> 1, acb = (tid & 1) * 16;
    const int brw = tid >> 3, bcb = (tid & 7) * 16;

    auto issue_tile = [&](int k0, uint32_t bufb) {
        const bf16* a_h = Ah_g + (size_t)(by + ar) * K + k0 + acb;
        const bf16* a_l = Al_g + (size_t)(by + ar) * K + k0 + acb;
        const uint32_t da = bufb + GB_A_H + (uint32_t)(ar * 80 + acb * 2);
        const uint32_t dal = bufb + GB_A_L + (uint32_t)(ar * 80 + acb * 2);
        cp_async16(da,       a_h);
        cp_async16(da + 16,  a_h + 8);
        cp_async16(dal,      a_l);
        cp_async16(dal + 16, a_l + 8);
        const bf16* b_h = Bh_g + (size_t)(k0 + brw) * N + bx + bcb;
        const bf16* b_l = Bl_g + (size_t)(k0 + brw) * N + bx + bcb;
        const uint32_t db  = bufb + GB_B_H + (uint32_t)(brw * 272 + bcb * 2);
        const uint32_t dbl = bufb + GB_B_L + (uint32_t)(brw * 272 + bcb * 2);
        cp_async16(db,       b_h);
        cp_async16(db + 16,  b_h + 8);
        cp_async16(dbl,      b_l);
        cp_async16(dbl + 16, b_l + 8);
    };

    const int aoff = (wm + (lane & 15)) * ASTR + ((lane >> 4) << 3);
    const int boff = (lane & 15) * BSTR + wn + ((lane >> 4) << 3);

    const int NIT = K >> 5;
    issue_tile(0, sb);
    CP_COMMIT;

    for (int t = 0; t < NIT; t++) {
        __syncthreads();
        if (t + 1 < NIT) {
            issue_tile((t + 1) * 32, sb + ((t + 1) & 1) * GB_SZ);
            CP_COMMIT;
            CP_WAIT1;
        } else {
            CP_WAIT0;
        }
        __syncthreads();

        const uint32_t bufb = sb + (t & 1) * GB_SZ;
        const uint32_t Ah_b = bufb + GB_A_H;
        const uint32_t Al_b = bufb + GB_A_L;
        const uint32_t Bh_b = bufb + GB_B_H;
        const uint32_t Bl_b = bufb + GB_B_L;

        #pragma unroll
        for (int kk = 0; kk < 32; kk += 16) {
            uint32_t ah[2][4], al[2][4];
            #pragma unroll
            for (int mi = 0; mi < 2; mi++) {
                ldmatrix_x4(ah[mi], Ah_b + (aoff + mi * 16 * ASTR + kk) * 2);
                ldmatrix_x4(al[mi], Al_b + (aoff + mi * 16 * ASTR + kk) * 2);
            }
            #pragma unroll
            for (int p = 0; p < 4; p++) {
                uint32_t bh[4], bl[4];
                const uint32_t off = (boff + kk * BSTR + p * 16) * 2;
                ldmatrix_x4_trans(bh, Bh_b + off);
                ldmatrix_x4_trans(bl, Bl_b + off);
                #pragma unroll
                for (int mi = 0; mi < 2; mi++) {
                    mma_bf16(acc[mi][2*p],   ah[mi], bh);
                    mma_bf16(acc[mi][2*p],   ah[mi], bl);
                    mma_bf16(acc[mi][2*p],   al[mi], bh);
                    mma_bf16(acc[mi][2*p+1], ah[mi], bh + 2);
                    mma_bf16(acc[mi][2*p+1], ah[mi], bl + 2);
                    mma_bf16(acc[mi][2*p+1], al[mi], bh + 2);
                }
            }
        }
    }

    const int g = lane >> 2;
    const int t = lane & 3;
    #pragma unroll
    for (int mi = 0; mi < 2; mi++) {
        #pragma unroll
        for (int ni = 0; ni < 8; ni++) {
            const size_t row0 = (size_t)(by + wm + mi * 16 + g);
            const int col = bx + wn + ni * 8 + 2 * t;
            *(float2*)(C + row0 * N + col)       = make_float2(acc[mi][ni][0], acc[mi][ni][1]);
            *(float2*)(C + (row0 + 8) * N + col) = make_float2(acc[mi][ni][2], acc[mi][ni][3]);
        }
    }
}

// ============================================================================
// GEMM fp16 2-term (O projection): C = (Ah+Al) @ Bh,  A split fp16, B single.
// ============================================================================
#define GO_A_H 0
#define GO_A_L 10240
#define GO_B_H 20480
#define GO_SZ  29184
#define GEMM_O_SMEM (2 * GO_SZ)

__global__ __launch_bounds__(256, 2)
void gemm_o_f16(const f16* __restrict__ Ah_g, const f16* __restrict__ Al_g,
                const f16* __restrict__ Bh_g,
                float* __restrict__ C, int M, int N, int K)
{
    extern __shared__ char smg[];
    const uint32_t sb = smem_u32(smg);

    const int tid  = threadIdx.x;
    const int warp = tid >> 5;
    const int lane = tid & 31;
    const int wm = (warp >> 1) * 32;
    const int wn = (warp & 1) * 64;
    const int bx = blockIdx.x * 128;
    const int by = blockIdx.y * 128;

    float acc[2][8][4];
    #pragma unroll
    for (int mi = 0; mi < 2; mi++)
        #pragma unroll
        for (int ni = 0; ni < 8; ni++)
            #pragma unroll
            for (int e = 0; e < 4; e++) acc[mi][ni][e] = 0.f;

    const int ar = tid >> 1, acb = (tid & 1) * 16;
    const int brw = tid >> 3, bcb = (tid & 7) * 16;

    auto issue_tile = [&](int k0, uint32_t bufb) {
        const f16* a_h = Ah_g + (size_t)(by + ar) * K + k0 + acb;
        const f16* a_l = Al_g + (size_t)(by + ar) * K + k0 + acb;
        const uint32_t da = bufb + GO_A_H + (uint32_t)(ar * 80 + acb * 2);
        const uint32_t dal = bufb + GO_A_L + (uint32_t)(ar * 80 + acb * 2);
        cp_async16(da,       a_h);
        cp_async16(da + 16,  a_h + 8);
        cp_async16(dal,      a_l);
        cp_async16(dal + 16, a_l + 8);
        const f16* b_h = Bh_g + (size_t)(k0 + brw) * N + bx + bcb;
        const uint32_t db = bufb + GO_B_H + (uint32_t)(brw * 272 + bcb * 2);
        cp_async16(db,      b_h);
        cp_async16(db + 16, b_h + 8);
    };

    const int aoff = (wm + (lane & 15)) * ASTR + ((lane >> 4) << 3);
    const int boff = (lane & 15) * BSTR + wn + ((lane >> 4) << 3);

    const int NIT = K >> 5;
    issue_tile(0, sb);
    CP_COMMIT;

    for (int t = 0; t < NIT; t++) {
        __syncthreads();
        if (t + 1 < NIT) {
            issue_tile((t + 1) * 32, sb + ((t + 1) & 1) * GO_SZ);
            CP_COMMIT;
            CP_WAIT1;
        } else {
            CP_WAIT0;
        }
        __syncthreads();

        const uint32_t bufb = sb + (t & 1) * GO_SZ;
        const uint32_t Ah_b = bufb + GO_A_H;
        const uint32_t Al_b = bufb + GO_A_L;
        const uint32_t Bh_b = bufb + GO_B_H;

        #pragma unroll
        for (int kk = 0; kk < 32; kk += 16) {
            uint32_t ah[2][4], al[2][4];
            #pragma unroll
            for (int mi = 0; mi < 2; mi++) {
                ldmatrix_x4(ah[mi], Ah_b + (aoff + mi * 16 * ASTR + kk) * 2);
                ldmatrix_x4(al[mi], Al_b + (aoff + mi * 16 * ASTR + kk) * 2);
            }
            #pragma unroll
            for (int p = 0; p < 4; p++) {
                uint32_t bh[4];
                const uint32_t off = (boff + kk * BSTR + p * 16) * 2;
                ldmatrix_x4_trans(bh, Bh_b + off);
                #pragma unroll
                for (int mi = 0; mi < 2; mi++) {
                    mma_f16(acc[mi][2*p],   ah[mi], bh);
                    mma_f16(acc[mi][2*p],   al[mi], bh);
                    mma_f16(acc[mi][2*p+1], ah[mi], bh + 2);
                    mma_f16(acc[mi][2*p+1], al[mi], bh + 2);
                }
            }
        }
    }

    const int g = lane >> 2;
    const int t = lane & 3;
    #pragma unroll
    for (int mi = 0; mi < 2; mi++) {
        #pragma unroll
        for (int ni = 0; ni < 8; ni++) {
            const size_t row0 = (size_t)(by + wm + mi * 16 + g);
            const int col = bx + wn + ni * 8 + 2 * t;
            *(float2*)(C + row0 * N + col)       = make_float2(acc[mi][ni][0], acc[mi][ni][1]);
            *(float2*)(C + (row0 + 8) * N + col) = make_float2(acc[mi][ni][2], acc[mi][ni][3]);
        }
    }
}

// ============================================================================
// RMSNorm + RoPE (Q: fp32 -> pre-scaled split bf16; K: in-place)
// ============================================================================
__global__ __launch_bounds__(128)
void rmsrope_q_kernel(const float* __restrict__ X, const float* __restrict__ w,
                      const int* __restrict__ pos,
                      bf16* __restrict__ Qh, bf16* __restrict__ Ql)
{
    const int blk = blockIdx.x;
    const int token = blk / NH;
    const int h     = blk % NH;
    const float* x = X + (size_t)token * QCOLS + h * HD;

    const int i = threadIdx.x;
    float v = x[i];

    float ss = v * v;
    #pragma unroll
    for (int m = 16; m; m >>= 1) ss += __shfl_xor_sync(0xffffffffu, ss, m);
    __shared__ float wsum[4];
    if ((i & 31) == 0) wsum[i >> 5] = ss;
    __syncthreads();
    float tot = wsum[0] + wsum[1] + wsum[2] + wsum[3];
    float inv = rsqrtf(tot * (1.0f / 128.0f) + 1e-6f);

    __shared__ float xs[128];
    xs[i] = v * inv * w[i];
    __syncthreads();

    const int p = pos[token];
    const int j = i & 63;
    float invf = (float)pow(1.0e6, -(double)j / 64.0);
    float f = (float)p * invf;
    float c, s;
    sincosf(f, &s, &c);
    float xi = xs[i];
    float partner = (i < 64) ? -xs[i + 64] : xs[i - 64];
    const float scale = 0.08838834764831845f;
    bf16 hh, ll;
    split2((xi * c + partner * s) * scale, hh, ll);
    const size_t o = (size_t)token * QCOLS + h * HD + i;
    Qh[o] = hh;
    Ql[o] = ll;
}

__global__ __launch_bounds__(128)
void rmsrope_k_kernel(float* __restrict__ KV, const float* __restrict__ w,
                      const int* __restrict__ pos)
{
    const int blk = blockIdx.x;
    const int token = blk / NKV;
    const int hk    = blk % NKV;
    float* x = KV + (size_t)token * KVW + hk * HD;

    const int i = threadIdx.x;
    float v = x[i];

    float ss = v * v;
    #pragma unroll
    for (int m = 16; m; m >>= 1) ss += __shfl_xor_sync(0xffffffffu, ss, m);
    __shared__ float wsum[4];
    if ((i & 31) == 0) wsum[i >> 5] = ss;
    __syncthreads();
    float tot = wsum[0] + wsum[1] + wsum[2] + wsum[3];
    float inv = rsqrtf(tot * (1.0f / 128.0f) + 1e-6f);

    __shared__ float xs[128];
    xs[i] = v * inv * w[i];
    __syncthreads();

    const int p = pos[token];
    const int j = i & 63;
    float invf = (float)pow(1.0e6, -(double)j / 64.0);
    float f = (float)p * invf;
    float c, s;
    sincosf(f, &s, &c);
    float xi = xs[i];
    float partner = (i < 64) ? -xs[i + 64] : xs[i - 64];
    x[i] = xi * c + partner * s;
}

// ============================================================================
// Flash attention: S = bf16 3-term; PV = fp16 (split P x single V).
// Br=128 (8 warps x 16 rows), Bc=64, 256 threads, cp.async double-buffered.
// ============================================================================
#define QSTR 136
#define KSTR 72
#define VSTR 136
#define AT_Q_H   0
#define AT_Q_L   (128*QSTR*2)
#define AT_BUF0  (2*128*QSTR*2)
#define AT_KH    0
#define AT_KL    (128*KSTR*2)
#define AT_VH    (2*128*KSTR*2)
#define AT_BUFSZ (2*128*KSTR*2 + 64*VSTR*2)
#define ATTN_SMEM (AT_BUF0 + 2*AT_BUFSZ)

__global__ __launch_bounds__(256, 1)
void attn_tc_kernel(const bf16* __restrict__ QhG, const bf16* __restrict__ QlG,
                    const bf16* __restrict__ KthH, const bf16* __restrict__ KthL,
                    const f16* __restrict__ VG,
                    f16* __restrict__ Ch, f16* __restrict__ Cl)
{
    extern __shared__ char sma[];
    const uint32_t sb = smem_u32(sma);

    const int qt = gridDim.x - 1 - blockIdx.x;
    const int h  = blockIdx.y;
    const int b  = blockIdx.z;
    const int hk = h >> 3;

    const int tid  = threadIdx.x;
    const int warp = tid >> 5;
    const int lane = tid & 31;
    const int g  = lane >> 2;
    const int t4 = lane & 3;

    const int ntiles = 2 * qt + 2;

    const bf16* kh_g = KthH + (size_t)(b * NKV + hk) * HD * SEQ;
    const bf16* kl_g = KthL + (size_t)(b * NKV + hk) * HD * SEQ;
    const f16*  v_g  = VG + (size_t)b * SEQ * KVCOLS + hk * HD;

    const int kd = tid >> 1, kc0 = (tid & 1) * 32;    // K: d-row (0..127)
    const int vc = tid >> 2, vd0 = (tid & 3) * 32;    // V: token-row (0..63)

    auto issue_kv = [&](int jt, uint32_t bufb) {
        const bf16* kh = kh_g + (size_t)kd * SEQ + jt * 64 + kc0;
        const bf16* kl = kl_g + (size_t)kd * SEQ + jt * 64 + kc0;
        const uint32_t dk  = bufb + AT_KH + (uint32_t)(kd * 144 + kc0 * 2);
        const uint32_t dkl = bufb + AT_KL + (uint32_t)(kd * 144 + kc0 * 2);
        #pragma unroll
        for (int u = 0; u < 4; u++) {
            cp_async16(dk  + u * 16, kh + u * 8);
            cp_async16(dkl + u * 16, kl + u * 8);
        }
        const f16* vv = v_g + (size_t)(jt * 64 + vc) * KVCOLS + vd0;
        const uint32_t dv = bufb + AT_VH + (uint32_t)(vc * 272 + vd0 * 2);
        #pragma unroll
        for (int u = 0; u < 4; u++)
            cp_async16(dv + u * 16, vv + u * 8);
    };

    // prefetch Q (pre-scaled bf16) + KV tile 0
    {
        const int r  = tid >> 1;
        const int c0 = (tid & 1) * 64;
        const bf16* qh = QhG + ((size_t)(b * SEQ + qt * 128 + r)) * QCOLS + h * HD + c0;
        const bf16* ql = QlG + ((size_t)(b * SEQ + qt * 128 + r)) * QCOLS + h * HD + c0;
        const uint32_t dqh = sb + AT_Q_H + (uint32_t)(r * QSTR * 2 + c0 * 2);
        const uint32_t dql = sb + AT_Q_L + (uint32_t)(r * QSTR * 2 + c0 * 2);
        #pragma unroll
        for (int u = 0; u < 8; u++) {
            cp_async16(dqh + u * 16, qh + u * 8);
            cp_async16(dql + u * 16, ql + u * 8);
        }
    }
    issue_kv(0, sb + AT_BUF0);
    CP_COMMIT;

    float oacc[16][4];
    #pragma unroll
    for (int nt = 0; nt < 16; nt++)
        #pragma unroll
        for (int e = 0; e < 4; e++) oacc[nt][e] = 0.f;
    float mrow0 = -1e30f, mrow1 = -1e30f, lrow0 = 0.f, lrow1 = 0.f;

    const int qrow0 = qt * 128 + warp * 16 + g;
    const int qrow1 = qrow0 + 8;
    const int warp_maxrow = qt * 128 + warp * 16 + 15;

    const uint32_t qh_base = sb + AT_Q_H + ((warp*16 + (lane & 15)) * QSTR + ((lane >> 4) << 3)) * 2;
    const uint32_t ql_base = sb + AT_Q_L + ((warp*16 + (lane & 15)) * QSTR + ((lane >> 4) << 3)) * 2;
    const uint32_t koffB = ((lane & 15) * KSTR + ((lane >> 4) << 3)) * 2;
    const uint32_t voffB = ((lane & 15) * VSTR + ((lane >> 4) << 3)) * 2;

    for (int jt = 0; jt < ntiles; jt++) {
        __syncthreads();
        if (jt + 1 < ntiles) {
            issue_kv(jt + 1, sb + AT_BUF0 + ((jt + 1) & 1) * AT_BUFSZ);
            CP_COMMIT;
            CP_WAIT1;
        } else {
            CP_WAIT0;
        }
        __syncthreads();

        if (jt * 64 > warp_maxrow) continue;

        const uint32_t bufb = sb + AT_BUF0 + (jt & 1) * AT_BUFSZ;
        const uint32_t kth_b = bufb + AT_KH + koffB;
        const uint32_t ktl_b = bufb + AT_KL + koffB;
        const uint32_t vh_b  = bufb + AT_VH + voffB;

        // ---- S = Q @ Kt (bf16 3-term) ----
        float sacc[8][4];
        #pragma unroll
        for (int nt = 0; nt < 8; nt++)
            #pragma unroll
            for (int e = 0; e < 4; e++) sacc[nt][e] = 0.f;

        #pragma unroll
        for (int kk = 0; kk < 8; kk++) {
            uint32_t ah[4], al[4];
            ldmatrix_x4(ah, qh_base + kk * 16 * sizeof(bf16));
            ldmatrix_x4(al, ql_base + kk * 16 * sizeof(bf16));
            #pragma unroll
            for (int p = 0; p < 4; p++) {
                uint32_t bh[4], bl[4];
                const uint32_t off = (kk * 16 * KSTR + p * 16) * sizeof(bf16);
                ldmatrix_x4_trans(bh, kth_b + off);
                ldmatrix_x4_trans(bl, ktl_b + off);
                mma_bf16(sacc[2*p],   ah, bh);
                mma_bf16(sacc[2*p],   ah, bl);
                mma_bf16(sacc[2*p],   al, bh);
                mma_bf16(sacc[2*p+1], ah, bh + 2);
                mma_bf16(sacc[2*p+1], ah, bl + 2);
                mma_bf16(sacc[2*p+1], al, bh + 2);
            }
        }

        // ---- causal mask + online softmax ----
        float mx0 = -1e30f, mx1 = -1e30f;
        #pragma unroll
        for (int nt = 0; nt < 8; nt++) {
            const int col = jt * 64 + nt * 8 + 2 * t4;
            if (col     > qrow0) sacc[nt][0] = -1e30f;
            if (col + 1 > qrow0) sacc[nt][1] = -1e30f;
            if (col     > qrow1) sacc[nt][2] = -1e30f;
            if (col + 1 > qrow1) sacc[nt][3] = -1e30f;
            mx0 = fmaxf(mx0, fmaxf(sacc[nt][0], sacc[nt][1]));
            mx1 = fmaxf(mx1, fmaxf(sacc[nt][2], sacc[nt][3]));
        }
        mx0 = fmaxf(mx0, __shfl_xor_sync(0xffffffffu, mx0, 1));
        mx0 = fmaxf(mx0, __shfl_xor_sync(0xffffffffu, mx0, 2));
        mx1 = fmaxf(mx1, __shfl_xor_sync(0xffffffffu, mx1, 1));
        mx1 = fmaxf(mx1, __shfl_xor_sync(0xffffffffu, mx1, 2));

        const float mnew0 = fmaxf(mrow0, mx0);
        const float mnew1 = fmaxf(mrow1, mx1);
        const float alpha0 = __expf(mrow0 - mnew0);
        const float alpha1 = __expf(mrow1 - mnew1);

        float rs0 = 0.f, rs1 = 0.f;
        #pragma unroll
        for (int nt = 0; nt < 8; nt++) {
            sacc[nt][0] = __expf(sacc[nt][0] - mnew0);
            sacc[nt][1] = __expf(sacc[nt][1] - mnew0);
            sacc[nt][2] = __expf(sacc[nt][2] - mnew1);
            sacc[nt][3] = __expf(sacc[nt][3] - mnew1);
            rs0 += sacc[nt][0] + sacc[nt][1];
            rs1 += sacc[nt][2] + sacc[nt][3];
        }
        rs0 += __shfl_xor_sync(0xffffffffu, rs0, 1);
        rs0 += __shfl_xor_sync(0xffffffffu, rs0, 2);
        rs1 += __shfl_xor_sync(0xffffffffu, rs1, 1);
        rs1 += __shfl_xor_sync(0xffffffffu, rs1, 2);

        lrow0 = lrow0 * alpha0 + rs0;
        lrow1 = lrow1 * alpha1 + rs1;
        mrow0 = mnew0;
        mrow1 = mnew1;

        #pragma unroll
        for (int nt = 0; nt < 16; nt++) {
            oacc[nt][0] *= alpha0;
            oacc[nt][1] *= alpha0;
            oacc[nt][2] *= alpha1;
            oacc[nt][3] *= alpha1;
        }

        // ---- O += P @ V (fp16: split P, single V) ----
        #pragma unroll
        for (int c = 0; c < 4; c++) {
            uint32_t ph[4], pl[4];
            {
                f16 h00, l00, h01, l01, h02, l02, h03, l03;
                f16 h10, l10, h11, l11, h12, l12, h13, l13;
                split2h(sacc[2*c][0],   h00, l00); split2h(sacc[2*c][1],   h01, l01);
                split2h(sacc[2*c][2],   h02, l02); split2h(sacc[2*c][3],   h03, l03);
                split2h(sacc[2*c+1][0], h10, l10); split2h(sacc[2*c+1][1], h11, l11);
                split2h(sacc[2*c+1][2], h12, l12); split2h(sacc[2*c+1][3], h13, l13);
                ph[0] = pack_h2(h00, h01);
                ph[1] = pack_h2(h02, h03);
                ph[2] = pack_h2(h10, h11);
                ph[3] = pack_h2(h12, h13);
                pl[0] = pack_h2(l00, l01);
                pl[1] = pack_h2(l02, l03);
                pl[2] = pack_h2(l10, l11);
                pl[3] = pack_h2(l12, l13);
            }
            #pragma unroll
            for (int p = 0; p < 8; p++) {
                uint32_t vh[4];
                const uint32_t off = (c * 16 * VSTR + p * 16) * sizeof(f16);
                ldmatrix_x4_trans(vh, vh_b + off);
                mma_f16(oacc[2*p],   ph, vh);
                mma_f16(oacc[2*p],   pl, vh);
                mma_f16(oacc[2*p+1], ph, vh + 2);
                mma_f16(oacc[2*p+1], pl, vh + 2);
            }
        }
    }

    // ---- epilogue: write split fp16 ctx ----
    const float inv0 = 1.0f / lrow0;
    const float inv1 = 1.0f / lrow1;
    const size_t o0 = ((size_t)(b * SEQ + qrow0)) * QCOLS + h * HD;
    const size_t o1 = ((size_t)(b * SEQ + qrow1)) * QCOLS + h * HD;
    #pragma unroll
    for (int nt = 0; nt < 16; nt++) {
        const int col = nt * 8 + 2 * t4;
        f16 h0, l0, h1, l1;
        split2h(oacc[nt][0] * inv0, h0, l0);
        split2h(oacc[nt][1] * inv0, h1, l1);
        *(uint32_t*)(Ch + o0 + col) = pack_h2(h0, h1);
        *(uint32_t*)(Cl + o0 + col) = pack_h2(l0, l1);
        split2h(oacc[nt][2] * inv1, h0, l0);
        split2h(oacc[nt][3] * inv1, h1, l1);
        *(uint32_t*)(Ch + o1 + col) = pack_h2(h0, h1);
        *(uint32_t*)(Cl + o1 + col) = pack_h2(l0, l1);
    }
}

// ============================================================================
// Launch
// ============================================================================
extern "C" void kernel_launch(void* const* d_in, const int* in_sizes, int n_in,
                              void* d_out, int out_size)
{
    const float* hidden = (const float*)d_in[0];
    const int*   pos    = (const int*)  d_in[2];
    const float* Wq     = (const float*)d_in[3];
    const float* Wk     = (const float*)d_in[4];
    const float* Wv     = (const float*)d_in[5];
    const float* Wo     = (const float*)d_in[6];
    const float* qw     = (const float*)d_in[7];
    const float* kw     = (const float*)d_in[8];
    float* out = (float*)d_out;

    float *Qp, *KVp;
    bf16 *Hh, *Hl, *Wh, *Wl, *Qbh, *Qbl, *KtH, *KtL;
    f16 *Ch, *Cl, *V16;
    cudaGetSymbolAddress((void**)&Qp,  g_Q);
    cudaGetSymbolAddress((void**)&KVp, g_KV);
    cudaGetSymbolAddress((void**)&Hh,  g_Hh);
    cudaGetSymbolAddress((void**)&Hl,  g_Hl);
    cudaGetSymbolAddress((void**)&Wh,  g_Wh);
    cudaGetSymbolAddress((void**)&Wl,  g_Wl);
    cudaGetSymbolAddress((void**)&Qbh, g_Qbh);
    cudaGetSymbolAddress((void**)&Qbl, g_Qbl);
    cudaGetSymbolAddress((void**)&Ch,  g_Ch);
    cudaGetSymbolAddress((void**)&Cl,  g_Cl);
    cudaGetSymbolAddress((void**)&KtH, g_KthH);
    cudaGetSymbolAddress((void**)&KtL, g_KthL);
    cudaGetSymbolAddress((void**)&V16, g_V16);
    f16* WoH = (f16*)Wh;   // reuse g_Wh storage for fp16 Wo (after bf16 GEMMs done)

    cudaFuncSetAttribute(gemm_pre, cudaFuncAttributeMaxDynamicSharedMemorySize, GEMM_SMEM);
    cudaFuncSetAttribute(gemm_o_f16, cudaFuncAttributeMaxDynamicSharedMemorySize, GEMM_O_SMEM);
    cudaFuncSetAttribute(attn_tc_kernel, cudaFuncAttributeMaxDynamicSharedMemorySize, ATTN_SMEM);

    // pre-split hidden
    split_mat<<<(NTOK*HID/4 + 255)/256, 256>>>(hidden, Hh, Hl, NTOK*HID/4);

    // Q projection (bf16 3-term)
    split_mat<<<(HID*QCOLS/4 + 255)/256, 256>>>(Wq, Wh, Wl, HID*QCOLS/4);
    gemm_pre<<<dim3(QCOLS/128, NTOK/128), 256, GEMM_SMEM>>>(Hh, Hl, Wh, Wl, Qp, NTOK, QCOLS, HID);

    // combined K|V projection (bf16 3-term)
    split_kv_w<<<(HID*KVW/4 + 255)/256, 256>>>(Wk, Wv, Wh, Wl);
    gemm_pre<<<dim3(KVW/128, NTOK/128), 256, GEMM_SMEM>>>(Hh, Hl, Wh, Wl, KVp, NTOK, KVW, HID);

    // RMSNorm + RoPE
    rmsrope_q_kernel<<<NTOK * NH, 128>>>(Qp, qw, pos, Qbh, Qbl);
    rmsrope_k_kernel<<<NTOK * NKV, 128>>>(KVp, kw, pos);

    // pre-split K (transposed, bf16) and V (single fp16)
    split_k_trans<<<BATCH*NKV*HD, 256>>>(KVp, KtH, KtL);
    split_v16<<<(NTOK*KVCOLS/4 + 255)/256, 256>>>(KVp, V16);

    // flash attention (S bf16 3-term, PV fp16 2-term; writes fp16 split ctx)
    attn_tc_kernel<<<dim3(SEQ/128, NH, BATCH), 256, ATTN_SMEM>>>(Qbh, Qbl, KtH, KtL, V16, Ch, Cl);

    // output projection (fp16 2-term: split ctx x rounded Wo)
    round_f16_mat<<<(QCOLS*HID/4 + 255)/256, 256>>>(Wo, WoH, QCOLS*HID/4);
    gemm_o_f16<<<dim3(HID/128, NTOK/128), 256, GEMM_O_SMEM>>>(Ch, Cl, WoH, out, NTOK, HID, QCOLS);
}

// round 11
// speedup vs baseline: 1.2241x; 1.0630x over previous
#include <cuda_runtime.h>
#include <cuda_bf16.h>
#include <cuda_fp16.h>
#include <math.h>
#include <stdint.h>

// Problem constants
#define BATCH 2
#define SEQ   2048
#define HID   2048
#define NH    32
#define NKV   4
#define HD    128
#define NTOK  (BATCH*SEQ)          // 4096
#define QCOLS (NH*HD)              // 4096
#define KVCOLS (NKV*HD)            // 512
#define KVW   (2*KVCOLS)           // 1024 (K|V concatenated)

typedef __nv_bfloat16 bf16;
typedef __half f16;

// -------- scratch (device globals) --------
__device__ float g_Q [(size_t)NTOK * QCOLS];    // Q projection out (fp32)
__device__ float g_KV[(size_t)NTOK * KVW];      // K|V projection out (fp32)
__device__ f16  g_Hh16[(size_t)NTOK * HID], g_Hl16[(size_t)NTOK * HID];   // hidden f16 split
__device__ bf16 g_Hhb[(size_t)NTOK * HID],  g_Hlb[(size_t)NTOK * HID];    // hidden bf16 split
__device__ bf16 g_Wbh[(size_t)HID * KVW],   g_Wbl[(size_t)HID * KVW];     // KV weights bf16 split
__device__ f16  g_W16[(size_t)HID * QCOLS];                               // Wq / Wo single f16
__device__ f16  g_Qbh[(size_t)NTOK * QCOLS], g_Qbl[(size_t)NTOK * QCOLS]; // Q normed+roped f16 split
__device__ f16  g_Ch[(size_t)NTOK * QCOLS], g_Cl[(size_t)NTOK * QCOLS];   // ctx split (fp16)
__device__ f16  g_Kt16[(size_t)BATCH*NKV*HD*SEQ];                         // K transposed single f16
__device__ f16  g_V16[(size_t)NTOK * KVCOLS];                             // V single f16

// ============================================================================
// PTX helpers
// ============================================================================
__device__ __forceinline__ uint32_t smem_u32(const void* p) {
    return (uint32_t)__cvta_generic_to_shared(p);
}
__device__ __forceinline__ void ldmatrix_x4(uint32_t* r, uint32_t addr) {
    asm volatile("ldmatrix.sync.aligned.m8n8.x4.shared.b16 {%0,%1,%2,%3}, [%4];"
                 : "=r"(r[0]), "=r"(r[1]), "=r"(r[2]), "=r"(r[3]) : "r"(addr));
}
__device__ __forceinline__ void ldmatrix_x4_trans(uint32_t* r, uint32_t addr) {
    asm volatile("ldmatrix.sync.aligned.m8n8.x4.trans.shared.b16 {%0,%1,%2,%3}, [%4];"
                 : "=r"(r[0]), "=r"(r[1]), "=r"(r[2]), "=r"(r[3]) : "r"(addr));
}
__device__ __forceinline__ void mma_bf16(float* d, const uint32_t* a, const uint32_t* b) {
    asm volatile("mma.sync.aligned.m16n8k16.row.col.f32.bf16.bf16.f32 "
                 "{%0,%1,%2,%3}, {%4,%5,%6,%7}, {%8,%9}, {%0,%1,%2,%3};"
                 : "+f"(d[0]), "+f"(d[1]), "+f"(d[2]), "+f"(d[3])
                 : "r"(a[0]), "r"(a[1]), "r"(a[2]), "r"(a[3]),
                   "r"(b[0]), "r"(b[1]));
}
__device__ __forceinline__ void mma_f16(float* d, const uint32_t* a, const uint32_t* b) {
    asm volatile("mma.sync.aligned.m16n8k16.row.col.f32.f16.f16.f32 "
                 "{%0,%1,%2,%3}, {%4,%5,%6,%7}, {%8,%9}, {%0,%1,%2,%3};"
                 : "+f"(d[0]), "+f"(d[1]), "+f"(d[2]), "+f"(d[3])
                 : "r"(a[0]), "r"(a[1]), "r"(a[2]), "r"(a[3]),
                   "r"(b[0]), "r"(b[1]));
}
__device__ __forceinline__ void split2(float x, bf16& h, bf16& l) {
    h = __float2bfloat16_rn(x);
    l = __float2bfloat16_rn(x - __bfloat162float(h));
}
__device__ __forceinline__ void split2h(float x, f16& h, f16& l) {
    h = __float2half_rn(x);
    l = __float2half_rn(x - __half2float(h));
}
__device__ __forceinline__ uint32_t pack_bf16x2(float lo, float hi) {
    __nv_bfloat162 r = __floats2bfloat162_rn(lo, hi);
    return *(uint32_t*)&r;
}
__device__ __forceinline__ uint32_t pack_h2(f16 lo, f16 hi) {
    __half2 r = __halves2half2(lo, hi);
    return *(uint32_t*)&r;
}
__device__ __forceinline__ void split4_pack_b(float4 v, uint2& hh, uint2& ll) {
    bf16 hx, lx, hy, ly, hz, lz, hw, lw;
    split2(v.x, hx, lx); split2(v.y, hy, ly);
    split2(v.z, hz, lz); split2(v.w, hw, lw);
    hh.x = pack_bf16x2(__bfloat162float(hx), __bfloat162float(hy));
    hh.y = pack_bf16x2(__bfloat162float(hz), __bfloat162float(hw));
    ll.x = pack_bf16x2(__bfloat162float(lx), __bfloat162float(ly));
    ll.y = pack_bf16x2(__bfloat162float(lz), __bfloat162float(lw));
}
__device__ __forceinline__ void split4_pack_h(float4 v, uint2& hh, uint2& ll) {
    f16 hx, lx, hy, ly, hz, lz, hw, lw;
    split2h(v.x, hx, lx); split2h(v.y, hy, ly);
    split2h(v.z, hz, lz); split2h(v.w, hw, lw);
    hh.x = pack_h2(hx, hy);
    hh.y = pack_h2(hz, hw);
    ll.x = pack_h2(lx, ly);
    ll.y = pack_h2(lz, lw);
}
__device__ __forceinline__ uint2 round4_f16(float4 v) {
    uint2 r;
    __half2 a = __floats2half2_rn(v.x, v.y);
    __half2 b = __floats2half2_rn(v.z, v.w);
    r.x = *(uint32_t*)&a;
    r.y = *(uint32_t*)&b;
    return r;
}
__device__ __forceinline__ void cp_async16(uint32_t dst, const void* src) {
    asm volatile("cp.async.cg.shared.global [%0], [%1], 16;" :: "r"(dst), "l"(src));
}
#define CP_COMMIT asm volatile("cp.async.commit_group;")
#define CP_WAIT0  asm volatile("cp.async.wait_group 0;" ::: "memory")
#define CP_WAIT1  asm volatile("cp.async.wait_group 1;" ::: "memory")

// ============================================================================
// Elementwise kernels
// ============================================================================
// hidden -> f16 split AND bf16 split in one pass
__global__ __launch_bounds__(256)
void split_hidden_dual(const float* __restrict__ src,
                       f16* __restrict__ dh16, f16* __restrict__ dl16,
                       bf16* __restrict__ dhb, bf16* __restrict__ dlb, int n4)
{
    const int i = blockIdx.x * 256 + threadIdx.x;
    if (i < n4) {
        float4 v = ((const float4*)src)[i];
        uint2 hh, ll;
        split4_pack_h(v, hh, ll);
        ((uint2*)dh16)[i] = hh;
        ((uint2*)dl16)[i] = ll;
        split4_pack_b(v, hh, ll);
        ((uint2*)dhb)[i] = hh;
        ((uint2*)dlb)[i] = ll;
    }
}

__global__ __launch_bounds__(256)
void round_f16_mat(const float* __restrict__ src, f16* __restrict__ d, int n4)
{
    const int i = blockIdx.x * 256 + threadIdx.x;
    if (i < n4) ((uint2*)d)[i] = round4_f16(((const float4*)src)[i]);
}

// Wk[K][512], Wv[K][512] -> combined bf16 split [K][1024]
__global__ __launch_bounds__(256)
void split_kv_w(const float* __restrict__ Wk, const float* __restrict__ Wv,
                bf16* __restrict__ dh, bf16* __restrict__ dl)
{
    const int i = blockIdx.x * 256 + threadIdx.x;
    if (i >= HID * KVW / 4) return;
    const int row = i / (KVW / 4);
    const int c4  = (i % (KVW / 4)) * 4;
    float4 v;
    if (c4 < KVCOLS) v = *(const float4*)(Wk + (size_t)row * KVCOLS + c4);
    else             v = *(const float4*)(Wv + (size_t)row * KVCOLS + (c4 - KVCOLS));
    uint2 hh, ll;
    split4_pack_b(v, hh, ll);
    *(uint2*)(dh + (size_t)row * KVW + c4) = hh;
    *(uint2*)(dl + (size_t)row * KVW + c4) = ll;
}

// V part of g_KV -> single fp16 [tok][512]
__global__ __launch_bounds__(256)
void split_v16(const float* __restrict__ KV, f16* __restrict__ d)
{
    const int i = blockIdx.x * 256 + threadIdx.x;
    if (i >= NTOK * KVCOLS / 4) return;
    const int tok = i / (KVCOLS / 4);
    const int c4  = (i % (KVCOLS / 4)) * 4;
    float4 v = *(const float4*)(KV + (size_t)tok * KVW + KVCOLS + c4);
    *(uint2*)(d + (size_t)tok * KVCOLS + c4) = round4_f16(v);
}

// K part of g_KV -> single f16 transposed [(b*NKV+hk)*128+d][tok]
__global__ __launch_bounds__(256)
void round_k_trans(const float* __restrict__ KV, f16* __restrict__ d)
{
    const int blk = blockIdx.x;
    const int bhk = blk >> 7;
    const int dd  = blk & 127;
    const int b   = bhk >> 2, hk = bhk & 3;
    const int t0  = threadIdx.x * 8;
    const float* src = KV + ((size_t)b * SEQ + t0) * KVW + hk * HD + dd;
    __align__(16) f16 h8[8];
    #pragma unroll
    for (int j = 0; j < 8; j++) h8[j] = __float2half_rn(src[(size_t)j * KVW]);
    const size_t o = ((size_t)bhk * HD + dd) * SEQ + t0;
    *(uint4*)&d[o] = *(uint4*)h8;
}

// ============================================================================
// GEMM bf16 3-term (KV projection only)
// ============================================================================
#define ASTR 40
#define BSTR 136
#define GB_A_H 0
#define GB_A_L 10240
#define GB_B_H 20480
#define GB_B_L 29184
#define GB_SZ  37888
#define GEMM_SMEM (2 * GB_SZ)

__global__ __launch_bounds__(256, 2)
void gemm_pre(const bf16* __restrict__ Ah_g, const bf16* __restrict__ Al_g,
              const bf16* __restrict__ Bh_g, const bf16* __restrict__ Bl_g,
              float* __restrict__ C, int M, int N, int K)
{
    extern __shared__ char smg[];
    const uint32_t sb = smem_u32(smg);

    const int tid  = threadIdx.x;
    const int warp = tid >> 5;
    const int lane = tid & 31;
    const int wm = (warp >> 1) * 32;
    const int wn = (warp & 1) * 64;
    const int bx = blockIdx.x * 128;
    const int by = blockIdx.y * 128;

    float acc[2][8][4];
    #pragma unroll
    for (int mi = 0; mi < 2; mi++)
        #pragma unroll
        for (int ni = 0; ni < 8; ni++)
            #pragma unroll
            for (int e = 0; e < 4; e++) acc[mi][ni][e] = 0.f;

    const int ar = tid >> 1, acb = (tid & 1) * 16;
    const int brw = tid >> 3, bcb = (tid & 7) * 16;

    auto issue_tile = [&](int k0, uint32_t bufb) {
        const bf16* a_h = Ah_g + (size_t)(by + ar) * K + k0 + acb;
        const bf16* a_l = Al_g + (size_t)(by + ar) * K + k0 + acb;
        const uint32_t da = bufb + GB_A_H + (uint32_t)(ar * 80 + acb * 2);
        const uint32_t dal = bufb + GB_A_L + (uint32_t)(ar * 80 + acb * 2);
        cp_async16(da,       a_h);
        cp_async16(da + 16,  a_h + 8);
        cp_async16(dal,      a_l);
        cp_async16(dal + 16, a_l + 8);
        const bf16* b_h = Bh_g + (size_t)(k0 + brw) * N + bx + bcb;
        const bf16* b_l = Bl_g + (size_t)(k0 + brw) * N + bx + bcb;
        const uint32_t db  = bufb + GB_B_H + (uint32_t)(brw * 272 + bcb * 2);
        const uint32_t dbl = bufb + GB_B_L + (uint32_t)(brw * 272 + bcb * 2);
        cp_async16(db,       b_h);
        cp_async16(db + 16,  b_h + 8);
        cp_async16(dbl,      b_l);
        cp_async16(dbl + 16, b_l + 8);
    };

    const int aoff = (wm + (lane & 15)) * ASTR + ((lane >> 4) << 3);
    const int boff = (lane & 15) * BSTR + wn + ((lane >> 4) << 3);

    const int NIT = K >> 5;
    issue_tile(0, sb);
    CP_COMMIT;

    for (int t = 0; t < NIT; t++) {
        __syncthreads();
        if (t + 1 < NIT) {
            issue_tile((t + 1) * 32, sb + ((t + 1) & 1) * GB_SZ);
            CP_COMMIT;
            CP_WAIT1;
        } else {
            CP_WAIT0;
        }
        __syncthreads();

        const uint32_t bufb = sb + (t & 1) * GB_SZ;
        const uint32_t Ah_b = bufb + GB_A_H;
        const uint32_t Al_b = bufb + GB_A_L;
        const uint32_t Bh_b = bufb + GB_B_H;
        const uint32_t Bl_b = bufb + GB_B_L;

        #pragma unroll
        for (int kk = 0; kk < 32; kk += 16) {
            uint32_t ah[2][4], al[2][4];
            #pragma unroll
            for (int mi = 0; mi < 2; mi++) {
                ldmatrix_x4(ah[mi], Ah_b + (aoff + mi * 16 * ASTR + kk) * 2);
                ldmatrix_x4(al[mi], Al_b + (aoff + mi * 16 * ASTR + kk) * 2);
            }
            #pragma unroll
            for (int p = 0; p < 4; p++) {
                uint32_t bh[4], bl[4];
                const uint32_t off = (boff + kk * BSTR + p * 16) * 2;
                ldmatrix_x4_trans(bh, Bh_b + off);
                ldmatrix_x4_trans(bl, Bl_b + off);
                #pragma unroll
                for (int mi = 0; mi < 2; mi++) {
                    mma_bf16(acc[mi][2*p],   ah[mi], bh);
                    mma_bf16(acc[mi][2*p],   ah[mi], bl);
                    mma_bf16(acc[mi][2*p],   al[mi], bh);
                    mma_bf16(acc[mi][2*p+1], ah[mi], bh + 2);
                    mma_bf16(acc[mi][2*p+1], ah[mi], bl + 2);
                    mma_bf16(acc[mi][2*p+1], al[mi], bh + 2);
                }
            }
        }
    }

    const int g = lane >> 2;
    const int t = lane & 3;
    #pragma unroll
    for (int mi = 0; mi < 2; mi++) {
        #pragma unroll
        for (int ni = 0; ni < 8; ni++) {
            const size_t row0 = (size_t)(by + wm + mi * 16 + g);
            const int col = bx + wn + ni * 8 + 2 * t;
            *(float2*)(C + row0 * N + col)       = make_float2(acc[mi][ni][0], acc[mi][ni][1]);
            *(float2*)(C + (row0 + 8) * N + col) = make_float2(acc[mi][ni][2], acc[mi][ni][3]);
        }
    }
}

// ============================================================================
// GEMM fp16 2-term: C = (Ah+Al) @ Bh   (Q projection + O projection)
// ============================================================================
#define GO_A_H 0
#define GO_A_L 10240
#define GO_B_H 20480
#define GO_SZ  29184
#define GEMM_O_SMEM (2 * GO_SZ)

__global__ __launch_bounds__(256, 2)
void gemm_2t_f16(const f16* __restrict__ Ah_g, const f16* __restrict__ Al_g,
                 const f16* __restrict__ Bh_g,
                 float* __restrict__ C, int M, int N, int K)
{
    extern __shared__ char smg[];
    const uint32_t sb = smem_u32(smg);

    const int tid  = threadIdx.x;
    const int warp = tid >> 5;
    const int lane = tid & 31;
    const int wm = (warp >> 1) * 32;
    const int wn = (warp & 1) * 64;
    const int bx = blockIdx.x * 128;
    const int by = blockIdx.y * 128;

    float acc[2][8][4];
    #pragma unroll
    for (int mi = 0; mi < 2; mi++)
        #pragma unroll
        for (int ni = 0; ni < 8; ni++)
            #pragma unroll
            for (int e = 0; e < 4; e++) acc[mi][ni][e] = 0.f;

    const int ar = tid >> 1, acb = (tid & 1) * 16;
    const int brw = tid >> 3, bcb = (tid & 7) * 16;

    auto issue_tile = [&](int k0, uint32_t bufb) {
        const f16* a_h = Ah_g + (size_t)(by + ar) * K + k0 + acb;
        const f16* a_l = Al_g + (size_t)(by + ar) * K + k0 + acb;
        const uint32_t da = bufb + GO_A_H + (uint32_t)(ar * 80 + acb * 2);
        const uint32_t dal = bufb + GO_A_L + (uint32_t)(ar * 80 + acb * 2);
        cp_async16(da,       a_h);
        cp_async16(da + 16,  a_h + 8);
        cp_async16(dal,      a_l);
        cp_async16(dal + 16, a_l + 8);
        const f16* b_h = Bh_g + (size_t)(k0 + brw) * N + bx + bcb;
        const uint32_t db = bufb + GO_B_H + (uint32_t)(brw * 272 + bcb * 2);
        cp_async16(db,      b_h);
        cp_async16(db + 16, b_h + 8);
    };

    const int aoff = (wm + (lane & 15)) * ASTR + ((lane >> 4) << 3);
    const int boff = (lane & 15) * BSTR + wn + ((lane >> 4) << 3);

    const int NIT = K >> 5;
    issue_tile(0, sb);
    CP_COMMIT;

    for (int t = 0; t < NIT; t++) {
        __syncthreads();
        if (t + 1 < NIT) {
            issue_tile((t + 1) * 32, sb + ((t + 1) & 1) * GO_SZ);
            CP_COMMIT;
            CP_WAIT1;
        } else {
            CP_WAIT0;
        }
        __syncthreads();

        const uint32_t bufb = sb + (t & 1) * GO_SZ;
        const uint32_t Ah_b = bufb + GO_A_H;
        const uint32_t Al_b = bufb + GO_A_L;
        const uint32_t Bh_b = bufb + GO_B_H;

        #pragma unroll
        for (int kk = 0; kk < 32; kk += 16) {
            uint32_t ah[2][4], al[2][4];
            #pragma unroll
            for (int mi = 0; mi < 2; mi++) {
                ldmatrix_x4(ah[mi], Ah_b + (aoff + mi * 16 * ASTR + kk) * 2);
                ldmatrix_x4(al[mi], Al_b + (aoff + mi * 16 * ASTR + kk) * 2);
            }
            #pragma unroll
            for (int p = 0; p < 4; p++) {
                uint32_t bh[4];
                const uint32_t off = (boff + kk * BSTR + p * 16) * 2;
                ldmatrix_x4_trans(bh, Bh_b + off);
                #pragma unroll
                for (int mi = 0; mi < 2; mi++) {
                    mma_f16(acc[mi][2*p],   ah[mi], bh);
                    mma_f16(acc[mi][2*p],   al[mi], bh);
                    mma_f16(acc[mi][2*p+1], ah[mi], bh + 2);
                    mma_f16(acc[mi][2*p+1], al[mi], bh + 2);
                }
            }
        }
    }

    const int g = lane >> 2;
    const int t = lane & 3;
    #pragma unroll
    for (int mi = 0; mi < 2; mi++) {
        #pragma unroll
        for (int ni = 0; ni < 8; ni++) {
            const size_t row0 = (size_t)(by + wm + mi * 16 + g);
            const int col = bx + wn + ni * 8 + 2 * t;
            *(float2*)(C + row0 * N + col)       = make_float2(acc[mi][ni][0], acc[mi][ni][1]);
            *(float2*)(C + (row0 + 8) * N + col) = make_float2(acc[mi][ni][2], acc[mi][ni][3]);
        }
    }
}

// ============================================================================
// RMSNorm + RoPE (Q: fp32 -> UNSCALED split fp16; K: in-place)
// ============================================================================
__global__ __launch_bounds__(128)
void rmsrope_q_kernel(const float* __restrict__ X, const float* __restrict__ w,
                      const int* __restrict__ pos,
                      f16* __restrict__ Qh, f16* __restrict__ Ql)
{
    const int blk = blockIdx.x;
    const int token = blk / NH;
    const int h     = blk % NH;
    const float* x = X + (size_t)token * QCOLS + h * HD;

    const int i = threadIdx.x;
    float v = x[i];

    float ss = v * v;
    #pragma unroll
    for (int m = 16; m; m >>= 1) ss += __shfl_xor_sync(0xffffffffu, ss, m);
    __shared__ float wsum[4];
    if ((i & 31) == 0) wsum[i >> 5] = ss;
    __syncthreads();
    float tot = wsum[0] + wsum[1] + wsum[2] + wsum[3];
    float inv = rsqrtf(tot * (1.0f / 128.0f) + 1e-6f);

    __shared__ float xs[128];
    xs[i] = v * inv * w[i];
    __syncthreads();

    const int p = pos[token];
    const int j = i & 63;
    float invf = (float)pow(1.0e6, -(double)j / 64.0);
    float f = (float)p * invf;
    float c, s;
    sincosf(f, &s, &c);
    float xi = xs[i];
    float partner = (i < 64) ? -xs[i + 64] : xs[i - 64];
    f16 hh, ll;
    split2h(xi * c + partner * s, hh, ll);
    const size_t o = (size_t)token * QCOLS + h * HD + i;
    Qh[o] = hh;
    Ql[o] = ll;
}

__global__ __launch_bounds__(128)
void rmsrope_k_kernel(float* __restrict__ KV, const float* __restrict__ w,
                      const int* __restrict__ pos)
{
    const int blk = blockIdx.x;
    const int token = blk / NKV;
    const int hk    = blk % NKV;
    float* x = KV + (size_t)token * KVW + hk * HD;

    const int i = threadIdx.x;
    float v = x[i];

    float ss = v * v;
    #pragma unroll
    for (int m = 16; m; m >>= 1) ss += __shfl_xor_sync(0xffffffffu, ss, m);
    __shared__ float wsum[4];
    if ((i & 31) == 0) wsum[i >> 5] = ss;
    __syncthreads();
    float tot = wsum[0] + wsum[1] + wsum[2] + wsum[3];
    float inv = rsqrtf(tot * (1.0f / 128.0f) + 1e-6f);

    __shared__ float xs[128];
    xs[i] = v * inv * w[i];
    __syncthreads();

    const int p = pos[token];
    const int j = i & 63;
    float invf = (float)pow(1.0e6, -(double)j / 64.0);
    float f = (float)p * invf;
    float c, s;
    sincosf(f, &s, &c);
    float xi = xs[i];
    float partner = (i < 64) ? -xs[i + 64] : xs[i - 64];
    x[i] = xi * c + partner * s;
}

// ============================================================================
// Flash attention: S = fp16 2-term (split Q x single K); PV = fp16 2-term.
// Scale applied post-S in fp32. Br=128 (8 warps), Bc=64, 256 threads.
// ============================================================================
#define QSTR 136
#define KSTR 72
#define VSTR 136
#define AT_Q_H   0
#define AT_Q_L   (128*QSTR*2)
#define AT_BUF0  (2*128*QSTR*2)
#define AT_KH    0
#define AT_VH    (128*KSTR*2)
#define AT_BUFSZ (128*KSTR*2 + 64*VSTR*2)
#define ATTN_SMEM (AT_BUF0 + 2*AT_BUFSZ)

__global__ __launch_bounds__(256, 1)
void attn_tc_kernel(const f16* __restrict__ QhG, const f16* __restrict__ QlG,
                    const f16* __restrict__ KtG, const f16* __restrict__ VG,
                    f16* __restrict__ Ch, f16* __restrict__ Cl)
{
    extern __shared__ char sma[];
    const uint32_t sb = smem_u32(sma);

    const int qt = gridDim.x - 1 - blockIdx.x;
    const int h  = blockIdx.y;
    const int b  = blockIdx.z;
    const int hk = h >> 3;

    const int tid  = threadIdx.x;
    const int warp = tid >> 5;
    const int lane = tid & 31;
    const int g  = lane >> 2;
    const int t4 = lane & 3;

    const float scale = 0.08838834764831845f;
    const int ntiles = 2 * qt + 2;

    const f16* kt_g = KtG + (size_t)(b * NKV + hk) * HD * SEQ;
    const f16* v_g  = VG + (size_t)b * SEQ * KVCOLS + hk * HD;

    const int kd = tid >> 1, kc0 = (tid & 1) * 32;    // K: d-row (0..127)
    const int vc = tid >> 2, vd0 = (tid & 3) * 32;    // V: token-row (0..63)

    auto issue_kv = [&](int jt, uint32_t bufb) {
        const f16* kh = kt_g + (size_t)kd * SEQ + jt * 64 + kc0;
        const uint32_t dk = bufb + AT_KH + (uint32_t)(kd * 144 + kc0 * 2);
        #pragma unroll
        for (int u = 0; u < 4; u++)
            cp_async16(dk + u * 16, kh + u * 8);
        const f16* vv = v_g + (size_t)(jt * 64 + vc) * KVCOLS + vd0;
        const uint32_t dv = bufb + AT_VH + (uint32_t)(vc * 272 + vd0 * 2);
        #pragma unroll
        for (int u = 0; u < 4; u++)
            cp_async16(dv + u * 16, vv + u * 8);
    };

    // prefetch Q (unscaled f16 split) + KV tile 0
    {
        const int r  = tid >> 1;
        const int c0 = (tid & 1) * 64;
        const f16* qh = QhG + ((size_t)(b * SEQ + qt * 128 + r)) * QCOLS + h * HD + c0;
        const f16* ql = QlG + ((size_t)(b * SEQ + qt * 128 + r)) * QCOLS + h * HD + c0;
        const uint32_t dqh = sb + AT_Q_H + (uint32_t)(r * QSTR * 2 + c0 * 2);
        const uint32_t dql = sb + AT_Q_L + (uint32_t)(r * QSTR * 2 + c0 * 2);
        #pragma unroll
        for (int u = 0; u < 8; u++) {
            cp_async16(dqh + u * 16, qh + u * 8);
            cp_async16(dql + u * 16, ql + u * 8);
        }
    }
    issue_kv(0, sb + AT_BUF0);
    CP_COMMIT;

    float oacc[16][4];
    #pragma unroll
    for (int nt = 0; nt < 16; nt++)
        #pragma unroll
        for (int e = 0; e < 4; e++) oacc[nt][e] = 0.f;
    float mrow0 = -1e30f, mrow1 = -1e30f, lrow0 = 0.f, lrow1 = 0.f;

    const int qrow0 = qt * 128 + warp * 16 + g;
    const int qrow1 = qrow0 + 8;
    const int warp_maxrow = qt * 128 + warp * 16 + 15;

    const uint32_t qh_base = sb + AT_Q_H + ((warp*16 + (lane & 15)) * QSTR + ((lane >> 4) << 3)) * 2;
    const uint32_t ql_base = sb + AT_Q_L + ((warp*16 + (lane & 15)) * QSTR + ((lane >> 4) << 3)) * 2;
    const uint32_t koffB = ((lane & 15) * KSTR + ((lane >> 4) << 3)) * 2;
    const uint32_t voffB = ((lane & 15) * VSTR + ((lane >> 4) << 3)) * 2;

    for (int jt = 0; jt < ntiles; jt++) {
        __syncthreads();
        if (jt + 1 < ntiles) {
            issue_kv(jt + 1, sb + AT_BUF0 + ((jt + 1) & 1) * AT_BUFSZ);
            CP_COMMIT;
            CP_WAIT1;
        } else {
            CP_WAIT0;
        }
        __syncthreads();

        if (jt * 64 > warp_maxrow) continue;

        const uint32_t bufb = sb + AT_BUF0 + (jt & 1) * AT_BUFSZ;
        const uint32_t kt_b = bufb + AT_KH + koffB;
        const uint32_t vh_b = bufb + AT_VH + voffB;

        // ---- S = Q @ Kt (fp16 2-term: split Q x single K) ----
        float sacc[8][4];
        #pragma unroll
        for (int nt = 0; nt < 8; nt++)
            #pragma unroll
            for (int e = 0; e < 4; e++) sacc[nt][e] = 0.f;

        #pragma unroll
        for (int kk = 0; kk < 8; kk++) {
            uint32_t ah[4], al[4];
            ldmatrix_x4(ah, qh_base + kk * 16 * sizeof(f16));
            ldmatrix_x4(al, ql_base + kk * 16 * sizeof(f16));
            #pragma unroll
            for (int p = 0; p < 4; p++) {
                uint32_t bh[4];
                const uint32_t off = (kk * 16 * KSTR + p * 16) * sizeof(f16);
                ldmatrix_x4_trans(bh, kt_b + off);
                mma_f16(sacc[2*p],   ah, bh);
                mma_f16(sacc[2*p],   al, bh);
                mma_f16(sacc[2*p+1], ah, bh + 2);
                mma_f16(sacc[2*p+1], al, bh + 2);
            }
        }

        // ---- apply scale, causal mask, online softmax ----
        float mx0 = -1e30f, mx1 = -1e30f;
        #pragma unroll
        for (int nt = 0; nt < 8; nt++) {
            sacc[nt][0] *= scale;
            sacc[nt][1] *= scale;
            sacc[nt][2] *= scale;
            sacc[nt][3] *= scale;
            const int col = jt * 64 + nt * 8 + 2 * t4;
            if (col     > qrow0) sacc[nt][0] = -1e30f;
            if (col + 1 > qrow0) sacc[nt][1] = -1e30f;
            if (col     > qrow1) sacc[nt][2] = -1e30f;
            if (col + 1 > qrow1) sacc[nt][3] = -1e30f;
            mx0 = fmaxf(mx0, fmaxf(sacc[nt][0], sacc[nt][1]));
            mx1 = fmaxf(mx1, fmaxf(sacc[nt][2], sacc[nt][3]));
        }
        mx0 = fmaxf(mx0, __shfl_xor_sync(0xffffffffu, mx0, 1));
        mx0 = fmaxf(mx0, __shfl_xor_sync(0xffffffffu, mx0, 2));
        mx1 = fmaxf(mx1, __shfl_xor_sync(0xffffffffu, mx1, 1));
        mx1 = fmaxf(mx1, __shfl_xor_sync(0xffffffffu, mx1, 2));

        const float mnew0 = fmaxf(mrow0, mx0);
        const float mnew1 = fmaxf(mrow1, mx1);
        const float alpha0 = __expf(mrow0 - mnew0);
        const float alpha1 = __expf(mrow1 - mnew1);

        float rs0 = 0.f, rs1 = 0.f;
        #pragma unroll
        for (int nt = 0; nt < 8; nt++) {
            sacc[nt][0] = __expf(sacc[nt][0] - mnew0);
            sacc[nt][1] = __expf(sacc[nt][1] - mnew0);
            sacc[nt][2] = __expf(sacc[nt][2] - mnew1);
            sacc[nt][3] = __expf(sacc[nt][3] - mnew1);
            rs0 += sacc[nt][0] + sacc[nt][1];
            rs1 += sacc[nt][2] + sacc[nt][3];
        }
        rs0 += __shfl_xor_sync(0xffffffffu, rs0, 1);
        rs0 += __shfl_xor_sync(0xffffffffu, rs0, 2);
        rs1 += __shfl_xor_sync(0xffffffffu, rs1, 1);
        rs1 += __shfl_xor_sync(0xffffffffu, rs1, 2);

        lrow0 = lrow0 * alpha0 + rs0;
        lrow1 = lrow1 * alpha1 + rs1;
        mrow0 = mnew0;
        mrow1 = mnew1;

        #pragma unroll
        for (int nt = 0; nt < 16; nt++) {
            oacc[nt][0] *= alpha0;
            oacc[nt][1] *= alpha0;
            oacc[nt][2] *= alpha1;
            oacc[nt][3] *= alpha1;
        }

        // ---- O += P @ V (fp16: split P, single V) ----
        #pragma unroll
        for (int c = 0; c < 4; c++) {
            uint32_t ph[4], pl[4];
            {
                f16 h00, l00, h01, l01, h02, l02, h03, l03;
                f16 h10, l10, h11, l11, h12, l12, h13, l13;
                split2h(sacc[2*c][0],   h00, l00); split2h(sacc[2*c][1],   h01, l01);
                split2h(sacc[2*c][2],   h02, l02); split2h(sacc[2*c][3],   h03, l03);
                split2h(sacc[2*c+1][0], h10, l10); split2h(sacc[2*c+1][1], h11, l11);
                split2h(sacc[2*c+1][2], h12, l12); split2h(sacc[2*c+1][3], h13, l13);
                ph[0] = pack_h2(h00, h01);
                ph[1] = pack_h2(h02, h03);
                ph[2] = pack_h2(h10, h11);
                ph[3] = pack_h2(h12, h13);
                pl[0] = pack_h2(l00, l01);
                pl[1] = pack_h2(l02, l03);
                pl[2] = pack_h2(l10, l11);
                pl[3] = pack_h2(l12, l13);
            }
            #pragma unroll
            for (int p = 0; p < 8; p++) {
                uint32_t vh[4];
                const uint32_t off = (c * 16 * VSTR + p * 16) * sizeof(f16);
                ldmatrix_x4_trans(vh, vh_b + off);
                mma_f16(oacc[2*p],   ph, vh);
                mma_f16(oacc[2*p],   pl, vh);
                mma_f16(oacc[2*p+1], ph, vh + 2);
                mma_f16(oacc[2*p+1], pl, vh + 2);
            }
        }
    }

    // ---- epilogue: write split fp16 ctx ----
    const float inv0 = 1.0f / lrow0;
    const float inv1 = 1.0f / lrow1;
    const size_t o0 = ((size_t)(b * SEQ + qrow0)) * QCOLS + h * HD;
    const size_t o1 = ((size_t)(b * SEQ + qrow1)) * QCOLS + h * HD;
    #pragma unroll
    for (int nt = 0; nt < 16; nt++) {
        const int col = nt * 8 + 2 * t4;
        f16 h0, l0, h1, l1;
        split2h(oacc[nt][0] * inv0, h0, l0);
        split2h(oacc[nt][1] * inv0, h1, l1);
        *(uint32_t*)(Ch + o0 + col) = pack_h2(h0, h1);
        *(uint32_t*)(Cl + o0 + col) = pack_h2(l0, l1);
        split2h(oacc[nt][2] * inv1, h0, l0);
        split2h(oacc[nt][3] * inv1, h1, l1);
        *(uint32_t*)(Ch + o1 + col) = pack_h2(h0, h1);
        *(uint32_t*)(Cl + o1 + col) = pack_h2(l0, l1);
    }
}

// ============================================================================
// Launch
// ============================================================================
extern "C" void kernel_launch(void* const* d_in, const int* in_sizes, int n_in,
                              void* d_out, int out_size)
{
    const float* hidden = (const float*)d_in[0];
    const int*   pos    = (const int*)  d_in[2];
    const float* Wq     = (const float*)d_in[3];
    const float* Wk     = (const float*)d_in[4];
    const float* Wv     = (const float*)d_in[5];
    const float* Wo     = (const float*)d_in[6];
    const float* qw     = (const float*)d_in[7];
    const float* kw     = (const float*)d_in[8];
    float* out = (float*)d_out;

    float *Qp, *KVp;
    f16 *Hh16, *Hl16, *W16, *Qbh, *Qbl, *Ch, *Cl, *Kt16, *V16;
    bf16 *Hhb, *Hlb, *Wbh, *Wbl;
    cudaGetSymbolAddress((void**)&Qp,   g_Q);
    cudaGetSymbolAddress((void**)&KVp,  g_KV);
    cudaGetSymbolAddress((void**)&Hh16, g_Hh16);
    cudaGetSymbolAddress((void**)&Hl16, g_Hl16);
    cudaGetSymbolAddress((void**)&Hhb,  g_Hhb);
    cudaGetSymbolAddress((void**)&Hlb,  g_Hlb);
    cudaGetSymbolAddress((void**)&Wbh,  g_Wbh);
    cudaGetSymbolAddress((void**)&Wbl,  g_Wbl);
    cudaGetSymbolAddress((void**)&W16,  g_W16);
    cudaGetSymbolAddress((void**)&Qbh,  g_Qbh);
    cudaGetSymbolAddress((void**)&Qbl,  g_Qbl);
    cudaGetSymbolAddress((void**)&Ch,   g_Ch);
    cudaGetSymbolAddress((void**)&Cl,   g_Cl);
    cudaGetSymbolAddress((void**)&Kt16, g_Kt16);
    cudaGetSymbolAddress((void**)&V16,  g_V16);

    cudaFuncSetAttribute(gemm_pre, cudaFuncAttributeMaxDynamicSharedMemorySize, GEMM_SMEM);
    cudaFuncSetAttribute(gemm_2t_f16, cudaFuncAttributeMaxDynamicSharedMemorySize, GEMM_O_SMEM);
    cudaFuncSetAttribute(attn_tc_kernel, cudaFuncAttributeMaxDynamicSharedMemorySize, ATTN_SMEM);

    // pre-split hidden (f16 + bf16 in one pass)
    split_hidden_dual<<<(NTOK*HID/4 + 255)/256, 256>>>(hidden, Hh16, Hl16, Hhb, Hlb, NTOK*HID/4);

    // Q projection (fp16 2-term)
    round_f16_mat<<<(HID*QCOLS/4 + 255)/256, 256>>>(Wq, W16, HID*QCOLS/4);
    gemm_2t_f16<<<dim3(QCOLS/128, NTOK/128), 256, GEMM_O_SMEM>>>(Hh16, Hl16, W16, Qp, NTOK, QCOLS, HID);

    // combined K|V projection (bf16 3-term, full precision)
    split_kv_w<<<(HID*KVW/4 + 255)/256, 256>>>(Wk, Wv, Wbh, Wbl);
    gemm_pre<<<dim3(KVW/128, NTOK/128), 256, GEMM_SMEM>>>(Hhb, Hlb, Wbh, Wbl, KVp, NTOK, KVW, HID);

    // RMSNorm + RoPE
    rmsrope_q_kernel<<<NTOK * NH, 128>>>(Qp, qw, pos, Qbh, Qbl);
    rmsrope_k_kernel<<<NTOK * NKV, 128>>>(KVp, kw, pos);

    // K -> single f16 transposed; V -> single f16
    round_k_trans<<<BATCH*NKV*HD, 256>>>(KVp, Kt16);
    split_v16<<<(NTOK*KVCOLS/4 + 255)/256, 256>>>(KVp, V16);

    // flash attention (S fp16 2-term, PV fp16 2-term)
    attn_tc_kernel<<<dim3(SEQ/128, NH, BATCH), 256, ATTN_SMEM>>>(Qbh, Qbl, Kt16, V16, Ch, Cl);

    // output projection (fp16 2-term)
    round_f16_mat<<<(QCOLS*HID/4 + 255)/256, 256>>>(Wo, W16, QCOLS*HID/4);
    gemm_2t_f16<<<dim3(HID/128, NTOK/128), 256, GEMM_O_SMEM>>>(Ch, Cl, W16, out, NTOK, HID, QCOLS);
}

// round 12
// speedup vs baseline: 1.2993x; 1.0614x over previous
#include <cuda_runtime.h>
#include <cuda_bf16.h>
#include <cuda_fp16.h>
#include <math.h>
#include <stdint.h>

// Problem constants
#define BATCH 2
#define SEQ   2048
#define HID   2048
#define NH    32
#define NKV   4
#define HD    128
#define NTOK  (BATCH*SEQ)          // 4096
#define QCOLS (NH*HD)              // 4096
#define KVCOLS (NKV*HD)            // 512
#define KVW   (2*KVCOLS)           // 1024 (K|V concatenated)

typedef __nv_bfloat16 bf16;
typedef __half f16;

// -------- scratch (device globals) --------
__device__ float g_Q [(size_t)NTOK * QCOLS];    // Q projection out (fp32)
__device__ float g_KV[(size_t)NTOK * KVW];      // K|V projection out (fp32)
__device__ f16  g_Hh16[(size_t)NTOK * HID], g_Hl16[(size_t)NTOK * HID];   // hidden f16 split
__device__ bf16 g_Hhb[(size_t)NTOK * HID],  g_Hlb[(size_t)NTOK * HID];    // hidden bf16 split
__device__ bf16 g_Wbh[(size_t)HID * KVW],   g_Wbl[(size_t)HID * KVW];     // KV weights bf16 split
__device__ f16  g_W16[(size_t)HID * QCOLS];                               // Wq / Wo single f16
__device__ f16  g_Qbh[(size_t)NTOK * QCOLS], g_Qbl[(size_t)NTOK * QCOLS]; // Q normed+roped f16 split
__device__ f16  g_Ch[(size_t)NTOK * QCOLS];                               // ctx single f16
__device__ f16  g_Kt16[(size_t)BATCH*NKV*HD*SEQ];                         // K transposed single f16
__device__ f16  g_V16[(size_t)NTOK * KVCOLS];                             // V single f16

// ============================================================================
// PTX helpers
// ============================================================================
__device__ __forceinline__ uint32_t smem_u32(const void* p) {
    return (uint32_t)__cvta_generic_to_shared(p);
}
__device__ __forceinline__ void ldmatrix_x4(uint32_t* r, uint32_t addr) {
    asm volatile("ldmatrix.sync.aligned.m8n8.x4.shared.b16 {%0,%1,%2,%3}, [%4];"
                 : "=r"(r[0]), "=r"(r[1]), "=r"(r[2]), "=r"(r[3]) : "r"(addr));
}
__device__ __forceinline__ void ldmatrix_x4_trans(uint32_t* r, uint32_t addr) {
    asm volatile("ldmatrix.sync.aligned.m8n8.x4.trans.shared.b16 {%0,%1,%2,%3}, [%4];"
                 : "=r"(r[0]), "=r"(r[1]), "=r"(r[2]), "=r"(r[3]) : "r"(addr));
}
__device__ __forceinline__ void mma_bf16(float* d, const uint32_t* a, const uint32_t* b) {
    asm volatile("mma.sync.aligned.m16n8k16.row.col.f32.bf16.bf16.f32 "
                 "{%0,%1,%2,%3}, {%4,%5,%6,%7}, {%8,%9}, {%0,%1,%2,%3};"
                 : "+f"(d[0]), "+f"(d[1]), "+f"(d[2]), "+f"(d[3])
                 : "r"(a[0]), "r"(a[1]), "r"(a[2]), "r"(a[3]),
                   "r"(b[0]), "r"(b[1]));
}
__device__ __forceinline__ void mma_f16(float* d, const uint32_t* a, const uint32_t* b) {
    asm volatile("mma.sync.aligned.m16n8k16.row.col.f32.f16.f16.f32 "
                 "{%0,%1,%2,%3}, {%4,%5,%6,%7}, {%8,%9}, {%0,%1,%2,%3};"
                 : "+f"(d[0]), "+f"(d[1]), "+f"(d[2]), "+f"(d[3])
                 : "r"(a[0]), "r"(a[1]), "r"(a[2]), "r"(a[3]),
                   "r"(b[0]), "r"(b[1]));
}
__device__ __forceinline__ void split2(float x, bf16& h, bf16& l) {
    h = __float2bfloat16_rn(x);
    l = __float2bfloat16_rn(x - __bfloat162float(h));
}
__device__ __forceinline__ void split2h(float x, f16& h, f16& l) {
    h = __float2half_rn(x);
    l = __float2half_rn(x - __half2float(h));
}
__device__ __forceinline__ uint32_t pack_bf16x2(float lo, float hi) {
    __nv_bfloat162 r = __floats2bfloat162_rn(lo, hi);
    return *(uint32_t*)&r;
}
__device__ __forceinline__ uint32_t pack_h2(f16 lo, f16 hi) {
    __half2 r = __halves2half2(lo, hi);
    return *(uint32_t*)&r;
}
__device__ __forceinline__ void split4_pack_b(float4 v, uint2& hh, uint2& ll) {
    bf16 hx, lx, hy, ly, hz, lz, hw, lw;
    split2(v.x, hx, lx); split2(v.y, hy, ly);
    split2(v.z, hz, lz); split2(v.w, hw, lw);
    hh.x = pack_bf16x2(__bfloat162float(hx), __bfloat162float(hy));
    hh.y = pack_bf16x2(__bfloat162float(hz), __bfloat162float(hw));
    ll.x = pack_bf16x2(__bfloat162float(lx), __bfloat162float(ly));
    ll.y = pack_bf16x2(__bfloat162float(lz), __bfloat162float(lw));
}
__device__ __forceinline__ void split4_pack_h(float4 v, uint2& hh, uint2& ll) {
    f16 hx, lx, hy, ly, hz, lz, hw, lw;
    split2h(v.x, hx, lx); split2h(v.y, hy, ly);
    split2h(v.z, hz, lz); split2h(v.w, hw, lw);
    hh.x = pack_h2(hx, hy);
    hh.y = pack_h2(hz, hw);
    ll.x = pack_h2(lx, ly);
    ll.y = pack_h2(lz, lw);
}
__device__ __forceinline__ uint2 round4_f16(float4 v) {
    uint2 r;
    __half2 a = __floats2half2_rn(v.x, v.y);
    __half2 b = __floats2half2_rn(v.z, v.w);
    r.x = *(uint32_t*)&a;
    r.y = *(uint32_t*)&b;
    return r;
}
__device__ __forceinline__ void cp_async16(uint32_t dst, const void* src) {
    asm volatile("cp.async.cg.shared.global [%0], [%1], 16;" :: "r"(dst), "l"(src));
}
#define CP_COMMIT asm volatile("cp.async.commit_group;")
#define CP_WAIT0  asm volatile("cp.async.wait_group 0;" ::: "memory")
#define CP_WAIT1  asm volatile("cp.async.wait_group 1;" ::: "memory")

// ============================================================================
// Elementwise kernels
// ============================================================================
__global__ __launch_bounds__(256)
void split_hidden_dual(const float* __restrict__ src,
                       f16* __restrict__ dh16, f16* __restrict__ dl16,
                       bf16* __restrict__ dhb, bf16* __restrict__ dlb, int n4)
{
    const int i = blockIdx.x * 256 + threadIdx.x;
    if (i < n4) {
        float4 v = ((const float4*)src)[i];
        uint2 hh, ll;
        split4_pack_h(v, hh, ll);
        ((uint2*)dh16)[i] = hh;
        ((uint2*)dl16)[i] = ll;
        split4_pack_b(v, hh, ll);
        ((uint2*)dhb)[i] = hh;
        ((uint2*)dlb)[i] = ll;
    }
}

__global__ __launch_bounds__(256)
void round_f16_mat(const float* __restrict__ src, f16* __restrict__ d, int n4)
{
    const int i = blockIdx.x * 256 + threadIdx.x;
    if (i < n4) ((uint2*)d)[i] = round4_f16(((const float4*)src)[i]);
}

// Wk[K][512], Wv[K][512] -> combined bf16 split [K][1024]
__global__ __launch_bounds__(256)
void split_kv_w(const float* __restrict__ Wk, const float* __restrict__ Wv,
                bf16* __restrict__ dh, bf16* __restrict__ dl)
{
    const int i = blockIdx.x * 256 + threadIdx.x;
    if (i >= HID * KVW / 4) return;
    const int row = i / (KVW / 4);
    const int c4  = (i % (KVW / 4)) * 4;
    float4 v;
    if (c4 < KVCOLS) v = *(const float4*)(Wk + (size_t)row * KVCOLS + c4);
    else             v = *(const float4*)(Wv + (size_t)row * KVCOLS + (c4 - KVCOLS));
    uint2 hh, ll;
    split4_pack_b(v, hh, ll);
    *(uint2*)(dh + (size_t)row * KVW + c4) = hh;
    *(uint2*)(dl + (size_t)row * KVW + c4) = ll;
}

// V part of g_KV -> single fp16 [tok][512]
__global__ __launch_bounds__(256)
void split_v16(const float* __restrict__ KV, f16* __restrict__ d)
{
    const int i = blockIdx.x * 256 + threadIdx.x;
    if (i >= NTOK * KVCOLS / 4) return;
    const int tok = i / (KVCOLS / 4);
    const int c4  = (i % (KVCOLS / 4)) * 4;
    float4 v = *(const float4*)(KV + (size_t)tok * KVW + KVCOLS + c4);
    *(uint2*)(d + (size_t)tok * KVCOLS + c4) = round4_f16(v);
}

// K part of g_KV -> single f16 transposed [(b*NKV+hk)*128+d][tok]
__global__ __launch_bounds__(256)
void round_k_trans(const float* __restrict__ KV, f16* __restrict__ d)
{
    const int blk = blockIdx.x;
    const int bhk = blk >> 7;
    const int dd  = blk & 127;
    const int b   = bhk >> 2, hk = bhk & 3;
    const int t0  = threadIdx.x * 8;
    const float* src = KV + ((size_t)b * SEQ + t0) * KVW + hk * HD + dd;
    __align__(16) f16 h8[8];
    #pragma unroll
    for (int j = 0; j < 8; j++) h8[j] = __float2half_rn(src[(size_t)j * KVW]);
    const size_t o = ((size_t)bhk * HD + dd) * SEQ + t0;
    *(uint4*)&d[o] = *(uint4*)h8;
}

// ============================================================================
// GEMM bf16 3-term (KV projection only)
// ============================================================================
#define ASTR 40
#define BSTR 136
#define GB_A_H 0
#define GB_A_L 10240
#define GB_B_H 20480
#define GB_B_L 29184
#define GB_SZ  37888
#define GEMM_SMEM (2 * GB_SZ)

__global__ __launch_bounds__(256, 2)
void gemm_pre(const bf16* __restrict__ Ah_g, const bf16* __restrict__ Al_g,
              const bf16* __restrict__ Bh_g, const bf16* __restrict__ Bl_g,
              float* __restrict__ C, int M, int N, int K)
{
    extern __shared__ char smg[];
    const uint32_t sb = smem_u32(smg);

    const int tid  = threadIdx.x;
    const int warp = tid >> 5;
    const int lane = tid & 31;
    const int wm = (warp >> 1) * 32;
    const int wn = (warp & 1) * 64;
    const int bx = blockIdx.x * 128;
    const int by = blockIdx.y * 128;

    float acc[2][8][4];
    #pragma unroll
    for (int mi = 0; mi < 2; mi++)
        #pragma unroll
        for (int ni = 0; ni < 8; ni++)
            #pragma unroll
            for (int e = 0; e < 4; e++) acc[mi][ni][e] = 0.f;

    const int ar = tid >> 1, acb = (tid & 1) * 16;
    const int brw = tid >> 3, bcb = (tid & 7) * 16;

    auto issue_tile = [&](int k0, uint32_t bufb) {
        const bf16* a_h = Ah_g + (size_t)(by + ar) * K + k0 + acb;
        const bf16* a_l = Al_g + (size_t)(by + ar) * K + k0 + acb;
        const uint32_t da = bufb + GB_A_H + (uint32_t)(ar * 80 + acb * 2);
        const uint32_t dal = bufb + GB_A_L + (uint32_t)(ar * 80 + acb * 2);
        cp_async16(da,       a_h);
        cp_async16(da + 16,  a_h + 8);
        cp_async16(dal,      a_l);
        cp_async16(dal + 16, a_l + 8);
        const bf16* b_h = Bh_g + (size_t)(k0 + brw) * N + bx + bcb;
        const bf16* b_l = Bl_g + (size_t)(k0 + brw) * N + bx + bcb;
        const uint32_t db  = bufb + GB_B_H + (uint32_t)(brw * 272 + bcb * 2);
        const uint32_t dbl = bufb + GB_B_L + (uint32_t)(brw * 272 + bcb * 2);
        cp_async16(db,       b_h);
        cp_async16(db + 16,  b_h + 8);
        cp_async16(dbl,      b_l);
        cp_async16(dbl + 16, b_l + 8);
    };

    const int aoff = (wm + (lane & 15)) * ASTR + ((lane >> 4) << 3);
    const int boff = (lane & 15) * BSTR + wn + ((lane >> 4) << 3);

    const int NIT = K >> 5;
    issue_tile(0, sb);
    CP_COMMIT;

    for (int t = 0; t < NIT; t++) {
        __syncthreads();
        if (t + 1 < NIT) {
            issue_tile((t + 1) * 32, sb + ((t + 1) & 1) * GB_SZ);
            CP_COMMIT;
            CP_WAIT1;
        } else {
            CP_WAIT0;
        }
        __syncthreads();

        const uint32_t bufb = sb + (t & 1) * GB_SZ;
        const uint32_t Ah_b = bufb + GB_A_H;
        const uint32_t Al_b = bufb + GB_A_L;
        const uint32_t Bh_b = bufb + GB_B_H;
        const uint32_t Bl_b = bufb + GB_B_L;

        #pragma unroll
        for (int kk = 0; kk < 32; kk += 16) {
            uint32_t ah[2][4], al[2][4];
            #pragma unroll
            for (int mi = 0; mi < 2; mi++) {
                ldmatrix_x4(ah[mi], Ah_b + (aoff + mi * 16 * ASTR + kk) * 2);
                ldmatrix_x4(al[mi], Al_b + (aoff + mi * 16 * ASTR + kk) * 2);
            }
            #pragma unroll
            for (int p = 0; p < 4; p++) {
                uint32_t bh[4], bl[4];
                const uint32_t off = (boff + kk * BSTR + p * 16) * 2;
                ldmatrix_x4_trans(bh, Bh_b + off);
                ldmatrix_x4_trans(bl, Bl_b + off);
                #pragma unroll
                for (int mi = 0; mi < 2; mi++) {
                    mma_bf16(acc[mi][2*p],   ah[mi], bh);
                    mma_bf16(acc[mi][2*p],   ah[mi], bl);
                    mma_bf16(acc[mi][2*p],   al[mi], bh);
                    mma_bf16(acc[mi][2*p+1], ah[mi], bh + 2);
                    mma_bf16(acc[mi][2*p+1], ah[mi], bl + 2);
                    mma_bf16(acc[mi][2*p+1], al[mi], bh + 2);
                }
            }
        }
    }

    const int g = lane >> 2;
    const int t = lane & 3;
    #pragma unroll
    for (int mi = 0; mi < 2; mi++) {
        #pragma unroll
        for (int ni = 0; ni < 8; ni++) {
            const size_t row0 = (size_t)(by + wm + mi * 16 + g);
            const int col = bx + wn + ni * 8 + 2 * t;
            *(float2*)(C + row0 * N + col)       = make_float2(acc[mi][ni][0], acc[mi][ni][1]);
            *(float2*)(C + (row0 + 8) * N + col) = make_float2(acc[mi][ni][2], acc[mi][ni][3]);
        }
    }
}

// ============================================================================
// GEMM fp16 2-term: C = (Ah+Al) @ Bh   (Q projection)
// ============================================================================
#define GO_A_H 0
#define GO_A_L 10240
#define GO_B_H 20480
#define GO_SZ  29184
#define GEMM_O_SMEM (2 * GO_SZ)

__global__ __launch_bounds__(256, 2)
void gemm_2t_f16(const f16* __restrict__ Ah_g, const f16* __restrict__ Al_g,
                 const f16* __restrict__ Bh_g,
                 float* __restrict__ C, int M, int N, int K)
{
    extern __shared__ char smg[];
    const uint32_t sb = smem_u32(smg);

    const int tid  = threadIdx.x;
    const int warp = tid >> 5;
    const int lane = tid & 31;
    const int wm = (warp >> 1) * 32;
    const int wn = (warp & 1) * 64;
    const int bx = blockIdx.x * 128;
    const int by = blockIdx.y * 128;

    float acc[2][8][4];
    #pragma unroll
    for (int mi = 0; mi < 2; mi++)
        #pragma unroll
        for (int ni = 0; ni < 8; ni++)
            #pragma unroll
            for (int e = 0; e < 4; e++) acc[mi][ni][e] = 0.f;

    const int ar = tid >> 1, acb = (tid & 1) * 16;
    const int brw = tid >> 3, bcb = (tid & 7) * 16;

    auto issue_tile = [&](int k0, uint32_t bufb) {
        const f16* a_h = Ah_g + (size_t)(by + ar) * K + k0 + acb;
        const f16* a_l = Al_g + (size_t)(by + ar) * K + k0 + acb;
        const uint32_t da = bufb + GO_A_H + (uint32_t)(ar * 80 + acb * 2);
        const uint32_t dal = bufb + GO_A_L + (uint32_t)(ar * 80 + acb * 2);
        cp_async16(da,       a_h);
        cp_async16(da + 16,  a_h + 8);
        cp_async16(dal,      a_l);
        cp_async16(dal + 16, a_l + 8);
        const f16* b_h = Bh_g + (size_t)(k0 + brw) * N + bx + bcb;
        const uint32_t db = bufb + GO_B_H + (uint32_t)(brw * 272 + bcb * 2);
        cp_async16(db,      b_h);
        cp_async16(db + 16, b_h + 8);
    };

    const int aoff = (wm + (lane & 15)) * ASTR + ((lane >> 4) << 3);
    const int boff = (lane & 15) * BSTR + wn + ((lane >> 4) << 3);

    const int NIT = K >> 5;
    issue_tile(0, sb);
    CP_COMMIT;

    for (int t = 0; t < NIT; t++) {
        __syncthreads();
        if (t + 1 < NIT) {
            issue_tile((t + 1) * 32, sb + ((t + 1) & 1) * GO_SZ);
            CP_COMMIT;
            CP_WAIT1;
        } else {
            CP_WAIT0;
        }
        __syncthreads();

        const uint32_t bufb = sb + (t & 1) * GO_SZ;
        const uint32_t Ah_b = bufb + GO_A_H;
        const uint32_t Al_b = bufb + GO_A_L;
        const uint32_t Bh_b = bufb + GO_B_H;

        #pragma unroll
        for (int kk = 0; kk < 32; kk += 16) {
            uint32_t ah[2][4], al[2][4];
            #pragma unroll
            for (int mi = 0; mi < 2; mi++) {
                ldmatrix_x4(ah[mi], Ah_b + (aoff + mi * 16 * ASTR + kk) * 2);
                ldmatrix_x4(al[mi], Al_b + (aoff + mi * 16 * ASTR + kk) * 2);
            }
            #pragma unroll
            for (int p = 0; p < 4; p++) {
                uint32_t bh[4];
                const uint32_t off = (boff + kk * BSTR + p * 16) * 2;
                ldmatrix_x4_trans(bh, Bh_b + off);
                #pragma unroll
                for (int mi = 0; mi < 2; mi++) {
                    mma_f16(acc[mi][2*p],   ah[mi], bh);
                    mma_f16(acc[mi][2*p],   al[mi], bh);
                    mma_f16(acc[mi][2*p+1], ah[mi], bh + 2);
                    mma_f16(acc[mi][2*p+1], al[mi], bh + 2);
                }
            }
        }
    }

    const int g = lane >> 2;
    const int t = lane & 3;
    #pragma unroll
    for (int mi = 0; mi < 2; mi++) {
        #pragma unroll
        for (int ni = 0; ni < 8; ni++) {
            const size_t row0 = (size_t)(by + wm + mi * 16 + g);
            const int col = bx + wn + ni * 8 + 2 * t;
            *(float2*)(C + row0 * N + col)       = make_float2(acc[mi][ni][0], acc[mi][ni][1]);
            *(float2*)(C + (row0 + 8) * N + col) = make_float2(acc[mi][ni][2], acc[mi][ni][3]);
        }
    }
}

// ============================================================================
// GEMM fp16 1-term: C = A @ B  (O projection: single ctx x single Wo)
// ============================================================================
#define G1_A 0
#define G1_B 10240
#define G1_SZ 18944
#define GEMM_1T_SMEM (2 * G1_SZ)

__global__ __launch_bounds__(256, 2)
void gemm_1t_f16(const f16* __restrict__ A_g, const f16* __restrict__ B_g,
                 float* __restrict__ C, int M, int N, int K)
{
    extern __shared__ char smg[];
    const uint32_t sb = smem_u32(smg);

    const int tid  = threadIdx.x;
    const int warp = tid >> 5;
    const int lane = tid & 31;
    const int wm = (warp >> 1) * 32;
    const int wn = (warp & 1) * 64;
    const int bx = blockIdx.x * 128;
    const int by = blockIdx.y * 128;

    float acc[2][8][4];
    #pragma unroll
    for (int mi = 0; mi < 2; mi++)
        #pragma unroll
        for (int ni = 0; ni < 8; ni++)
            #pragma unroll
            for (int e = 0; e < 4; e++) acc[mi][ni][e] = 0.f;

    const int ar = tid >> 1, acb = (tid & 1) * 16;
    const int brw = tid >> 3, bcb = (tid & 7) * 16;

    auto issue_tile = [&](int k0, uint32_t bufb) {
        const f16* a = A_g + (size_t)(by + ar) * K + k0 + acb;
        const uint32_t da = bufb + G1_A + (uint32_t)(ar * 80 + acb * 2);
        cp_async16(da,      a);
        cp_async16(da + 16, a + 8);
        const f16* b = B_g + (size_t)(k0 + brw) * N + bx + bcb;
        const uint32_t db = bufb + G1_B + (uint32_t)(brw * 272 + bcb * 2);
        cp_async16(db,      b);
        cp_async16(db + 16, b + 8);
    };

    const int aoff = (wm + (lane & 15)) * ASTR + ((lane >> 4) << 3);
    const int boff = (lane & 15) * BSTR + wn + ((lane >> 4) << 3);

    const int NIT = K >> 5;
    issue_tile(0, sb);
    CP_COMMIT;

    for (int t = 0; t < NIT; t++) {
        __syncthreads();
        if (t + 1 < NIT) {
            issue_tile((t + 1) * 32, sb + ((t + 1) & 1) * G1_SZ);
            CP_COMMIT;
            CP_WAIT1;
        } else {
            CP_WAIT0;
        }
        __syncthreads();

        const uint32_t bufb = sb + (t & 1) * G1_SZ;
        const uint32_t A_b = bufb + G1_A;
        const uint32_t B_b = bufb + G1_B;

        #pragma unroll
        for (int kk = 0; kk < 32; kk += 16) {
            uint32_t ah[2][4];
            #pragma unroll
            for (int mi = 0; mi < 2; mi++)
                ldmatrix_x4(ah[mi], A_b + (aoff + mi * 16 * ASTR + kk) * 2);
            #pragma unroll
            for (int p = 0; p < 4; p++) {
                uint32_t bh[4];
                const uint32_t off = (boff + kk * BSTR + p * 16) * 2;
                ldmatrix_x4_trans(bh, B_b + off);
                #pragma unroll
                for (int mi = 0; mi < 2; mi++) {
                    mma_f16(acc[mi][2*p],   ah[mi], bh);
                    mma_f16(acc[mi][2*p+1], ah[mi], bh + 2);
                }
            }
        }
    }

    const int g = lane >> 2;
    const int t = lane & 3;
    #pragma unroll
    for (int mi = 0; mi < 2; mi++) {
        #pragma unroll
        for (int ni = 0; ni < 8; ni++) {
            const size_t row0 = (size_t)(by + wm + mi * 16 + g);
            const int col = bx + wn + ni * 8 + 2 * t;
            *(float2*)(C + row0 * N + col)       = make_float2(acc[mi][ni][0], acc[mi][ni][1]);
            *(float2*)(C + (row0 + 8) * N + col) = make_float2(acc[mi][ni][2], acc[mi][ni][3]);
        }
    }
}

// ============================================================================
// RMSNorm + RoPE (Q: fp32 -> UNSCALED split fp16; K: in-place)
// ============================================================================
__global__ __launch_bounds__(128)
void rmsrope_q_kernel(const float* __restrict__ X, const float* __restrict__ w,
                      const int* __restrict__ pos,
                      f16* __restrict__ Qh, f16* __restrict__ Ql)
{
    const int blk = blockIdx.x;
    const int token = blk / NH;
    const int h     = blk % NH;
    const float* x = X + (size_t)token * QCOLS + h * HD;

    const int i = threadIdx.x;
    float v = x[i];

    float ss = v * v;
    #pragma unroll
    for (int m = 16; m; m >>= 1) ss += __shfl_xor_sync(0xffffffffu, ss, m);
    __shared__ float wsum[4];
    if ((i & 31) == 0) wsum[i >> 5] = ss;
    __syncthreads();
    float tot = wsum[0] + wsum[1] + wsum[2] + wsum[3];
    float inv = rsqrtf(tot * (1.0f / 128.0f) + 1e-6f);

    __shared__ float xs[128];
    xs[i] = v * inv * w[i];
    __syncthreads();

    const int p = pos[token];
    const int j = i & 63;
    float invf = (float)pow(1.0e6, -(double)j / 64.0);
    float f = (float)p * invf;
    float c, s;
    sincosf(f, &s, &c);
    float xi = xs[i];
    float partner = (i < 64) ? -xs[i + 64] : xs[i - 64];
    f16 hh, ll;
    split2h(xi * c + partner * s, hh, ll);
    const size_t o = (size_t)token * QCOLS + h * HD + i;
    Qh[o] = hh;
    Ql[o] = ll;
}

__global__ __launch_bounds__(128)
void rmsrope_k_kernel(float* __restrict__ KV, const float* __restrict__ w,
                      const int* __restrict__ pos)
{
    const int blk = blockIdx.x;
    const int token = blk / NKV;
    const int hk    = blk % NKV;
    float* x = KV + (size_t)token * KVW + hk * HD;

    const int i = threadIdx.x;
    float v = x[i];

    float ss = v * v;
    #pragma unroll
    for (int m = 16; m; m >>= 1) ss += __shfl_xor_sync(0xffffffffu, ss, m);
    __shared__ float wsum[4];
    if ((i & 31) == 0) wsum[i >> 5] = ss;
    __syncthreads();
    float tot = wsum[0] + wsum[1] + wsum[2] + wsum[3];
    float inv = rsqrtf(tot * (1.0f / 128.0f) + 1e-6f);

    __shared__ float xs[128];
    xs[i] = v * inv * w[i];
    __syncthreads();

    const int p = pos[token];
    const int j = i & 63;
    float invf = (float)pow(1.0e6, -(double)j / 64.0);
    float f = (float)p * invf;
    float c, s;
    sincosf(f, &s, &c);
    float xi = xs[i];
    float partner = (i < 64) ? -xs[i + 64] : xs[i - 64];
    x[i] = xi * c + partner * s;
}

// ============================================================================
// Flash attention: S = fp16 2-term (split Q x single K); PV = single-P fp16.
// Ctx written as SINGLE fp16. Br=128 (8 warps), Bc=64, 256 threads.
// ============================================================================
#define QSTR 136
#define KSTR 72
#define VSTR 136
#define AT_Q_H   0
#define AT_Q_L   (128*QSTR*2)
#define AT_BUF0  (2*128*QSTR*2)
#define AT_KH    0
#define AT_VH    (128*KSTR*2)
#define AT_BUFSZ (128*KSTR*2 + 64*VSTR*2)
#define ATTN_SMEM (AT_BUF0 + 2*AT_BUFSZ)

__global__ __launch_bounds__(256, 1)
void attn_tc_kernel(const f16* __restrict__ QhG, const f16* __restrict__ QlG,
                    const f16* __restrict__ KtG, const f16* __restrict__ VG,
                    f16* __restrict__ Ch)
{
    extern __shared__ char sma[];
    const uint32_t sb = smem_u32(sma);

    const int qt = gridDim.x - 1 - blockIdx.x;
    const int h  = blockIdx.y;
    const int b  = blockIdx.z;
    const int hk = h >> 3;

    const int tid  = threadIdx.x;
    const int warp = tid >> 5;
    const int lane = tid & 31;
    const int g  = lane >> 2;
    const int t4 = lane & 3;

    const float scale = 0.08838834764831845f;
    const int ntiles = 2 * qt + 2;

    const f16* kt_g = KtG + (size_t)(b * NKV + hk) * HD * SEQ;
    const f16* v_g  = VG + (size_t)b * SEQ * KVCOLS + hk * HD;

    const int kd = tid >> 1, kc0 = (tid & 1) * 32;
    const int vc = tid >> 2, vd0 = (tid & 3) * 32;

    auto issue_kv = [&](int jt, uint32_t bufb) {
        const f16* kh = kt_g + (size_t)kd * SEQ + jt * 64 + kc0;
        const uint32_t dk = bufb + AT_KH + (uint32_t)(kd * 144 + kc0 * 2);
        #pragma unroll
        for (int u = 0; u < 4; u++)
            cp_async16(dk + u * 16, kh + u * 8);
        const f16* vv = v_g + (size_t)(jt * 64 + vc) * KVCOLS + vd0;
        const uint32_t dv = bufb + AT_VH + (uint32_t)(vc * 272 + vd0 * 2);
        #pragma unroll
        for (int u = 0; u < 4; u++)
            cp_async16(dv + u * 16, vv + u * 8);
    };

    // prefetch Q (unscaled f16 split) + KV tile 0
    {
        const int r  = tid >> 1;
        const int c0 = (tid & 1) * 64;
        const f16* qh = QhG + ((size_t)(b * SEQ + qt * 128 + r)) * QCOLS + h * HD + c0;
        const f16* ql = QlG + ((size_t)(b * SEQ + qt * 128 + r)) * QCOLS + h * HD + c0;
        const uint32_t dqh = sb + AT_Q_H + (uint32_t)(r * QSTR * 2 + c0 * 2);
        const uint32_t dql = sb + AT_Q_L + (uint32_t)(r * QSTR * 2 + c0 * 2);
        #pragma unroll
        for (int u = 0; u < 8; u++) {
            cp_async16(dqh + u * 16, qh + u * 8);
            cp_async16(dql + u * 16, ql + u * 8);
        }
    }
    issue_kv(0, sb + AT_BUF0);
    CP_COMMIT;

    float oacc[16][4];
    #pragma unroll
    for (int nt = 0; nt < 16; nt++)
        #pragma unroll
        for (int e = 0; e < 4; e++) oacc[nt][e] = 0.f;
    float mrow0 = -1e30f, mrow1 = -1e30f, lrow0 = 0.f, lrow1 = 0.f;

    const int qrow0 = qt * 128 + warp * 16 + g;
    const int qrow1 = qrow0 + 8;
    const int warp_maxrow = qt * 128 + warp * 16 + 15;

    const uint32_t qh_base = sb + AT_Q_H + ((warp*16 + (lane & 15)) * QSTR + ((lane >> 4) << 3)) * 2;
    const uint32_t ql_base = sb + AT_Q_L + ((warp*16 + (lane & 15)) * QSTR + ((lane >> 4) << 3)) * 2;
    const uint32_t koffB = ((lane & 15) * KSTR + ((lane >> 4) << 3)) * 2;
    const uint32_t voffB = ((lane & 15) * VSTR + ((lane >> 4) << 3)) * 2;

    for (int jt = 0; jt < ntiles; jt++) {
        __syncthreads();
        if (jt + 1 < ntiles) {
            issue_kv(jt + 1, sb + AT_BUF0 + ((jt + 1) & 1) * AT_BUFSZ);
            CP_COMMIT;
            CP_WAIT1;
        } else {
            CP_WAIT0;
        }
        __syncthreads();

        if (jt * 64 > warp_maxrow) continue;

        const uint32_t bufb = sb + AT_BUF0 + (jt & 1) * AT_BUFSZ;
        const uint32_t kt_b = bufb + AT_KH + koffB;
        const uint32_t vh_b = bufb + AT_VH + voffB;

        // ---- S = Q @ Kt (fp16 2-term) ----
        float sacc[8][4];
        #pragma unroll
        for (int nt = 0; nt < 8; nt++)
            #pragma unroll
            for (int e = 0; e < 4; e++) sacc[nt][e] = 0.f;

        #pragma unroll
        for (int kk = 0; kk < 8; kk++) {
            uint32_t ah[4], al[4];
            ldmatrix_x4(ah, qh_base + kk * 16 * sizeof(f16));
            ldmatrix_x4(al, ql_base + kk * 16 * sizeof(f16));
            #pragma unroll
            for (int p = 0; p < 4; p++) {
                uint32_t bh[4];
                const uint32_t off = (kk * 16 * KSTR + p * 16) * sizeof(f16);
                ldmatrix_x4_trans(bh, kt_b + off);
                mma_f16(sacc[2*p],   ah, bh);
                mma_f16(sacc[2*p],   al, bh);
                mma_f16(sacc[2*p+1], ah, bh + 2);
                mma_f16(sacc[2*p+1], al, bh + 2);
            }
        }

        // ---- apply scale, causal mask, online softmax ----
        float mx0 = -1e30f, mx1 = -1e30f;
        #pragma unroll
        for (int nt = 0; nt < 8; nt++) {
            sacc[nt][0] *= scale;
            sacc[nt][1] *= scale;
            sacc[nt][2] *= scale;
            sacc[nt][3] *= scale;
            const int col = jt * 64 + nt * 8 + 2 * t4;
            if (col     > qrow0) sacc[nt][0] = -1e30f;
            if (col + 1 > qrow0) sacc[nt][1] = -1e30f;
            if (col     > qrow1) sacc[nt][2] = -1e30f;
            if (col + 1 > qrow1) sacc[nt][3] = -1e30f;
            mx0 = fmaxf(mx0, fmaxf(sacc[nt][0], sacc[nt][1]));
            mx1 = fmaxf(mx1, fmaxf(sacc[nt][2], sacc[nt][3]));
        }
        mx0 = fmaxf(mx0, __shfl_xor_sync(0xffffffffu, mx0, 1));
        mx0 = fmaxf(mx0, __shfl_xor_sync(0xffffffffu, mx0, 2));
        mx1 = fmaxf(mx1, __shfl_xor_sync(0xffffffffu, mx1, 1));
        mx1 = fmaxf(mx1, __shfl_xor_sync(0xffffffffu, mx1, 2));

        const float mnew0 = fmaxf(mrow0, mx0);
        const float mnew1 = fmaxf(mrow1, mx1);
        const float alpha0 = __expf(mrow0 - mnew0);
        const float alpha1 = __expf(mrow1 - mnew1);

        float rs0 = 0.f, rs1 = 0.f;
        #pragma unroll
        for (int nt = 0; nt < 8; nt++) {
            sacc[nt][0] = __expf(sacc[nt][0] - mnew0);
            sacc[nt][1] = __expf(sacc[nt][1] - mnew0);
            sacc[nt][2] = __expf(sacc[nt][2] - mnew1);
            sacc[nt][3] = __expf(sacc[nt][3] - mnew1);
            rs0 += sacc[nt][0] + sacc[nt][1];
            rs1 += sacc[nt][2] + sacc[nt][3];
        }
        rs0 += __shfl_xor_sync(0xffffffffu, rs0, 1);
        rs0 += __shfl_xor_sync(0xffffffffu, rs0, 2);
        rs1 += __shfl_xor_sync(0xffffffffu, rs1, 1);
        rs1 += __shfl_xor_sync(0xffffffffu, rs1, 2);

        lrow0 = lrow0 * alpha0 + rs0;
        lrow1 = lrow1 * alpha1 + rs1;
        mrow0 = mnew0;
        mrow1 = mnew1;

        #pragma unroll
        for (int nt = 0; nt < 16; nt++) {
            oacc[nt][0] *= alpha0;
            oacc[nt][1] *= alpha0;
            oacc[nt][2] *= alpha1;
            oacc[nt][3] *= alpha1;
        }

        // ---- O += P @ V (single-fp16 P, single V) ----
        #pragma unroll
        for (int c = 0; c < 4; c++) {
            uint32_t ph[4];
            {
                __half2 p0 = __floats2half2_rn(sacc[2*c][0],   sacc[2*c][1]);
                __half2 p1 = __floats2half2_rn(sacc[2*c][2],   sacc[2*c][3]);
                __half2 p2 = __floats2half2_rn(sacc[2*c+1][0], sacc[2*c+1][1]);
                __half2 p3 = __floats2half2_rn(sacc[2*c+1][2], sacc[2*c+1][3]);
                ph[0] = *(uint32_t*)&p0;
                ph[1] = *(uint32_t*)&p1;
                ph[2] = *(uint32_t*)&p2;
                ph[3] = *(uint32_t*)&p3;
            }
            #pragma unroll
            for (int p = 0; p < 8; p++) {
                uint32_t vh[4];
                const uint32_t off = (c * 16 * VSTR + p * 16) * sizeof(f16);
                ldmatrix_x4_trans(vh, vh_b + off);
                mma_f16(oacc[2*p],   ph, vh);
                mma_f16(oacc[2*p+1], ph, vh + 2);
            }
        }
    }

    // ---- epilogue: write single-fp16 ctx ----
    const float inv0 = 1.0f / lrow0;
    const float inv1 = 1.0f / lrow1;
    const size_t o0 = ((size_t)(b * SEQ + qrow0)) * QCOLS + h * HD;
    const size_t o1 = ((size_t)(b * SEQ + qrow1)) * QCOLS + h * HD;
    #pragma unroll
    for (int nt = 0; nt < 16; nt++) {
        const int col = nt * 8 + 2 * t4;
        __half2 c0 = __floats2half2_rn(oacc[nt][0] * inv0, oacc[nt][1] * inv0);
        __half2 c1 = __floats2half2_rn(oacc[nt][2] * inv1, oacc[nt][3] * inv1);
        *(uint32_t*)(Ch + o0 + col) = *(uint32_t*)&c0;
        *(uint32_t*)(Ch + o1 + col) = *(uint32_t*)&c1;
    }
}

// ============================================================================
// Launch
// ============================================================================
extern "C" void kernel_launch(void* const* d_in, const int* in_sizes, int n_in,
                              void* d_out, int out_size)
{
    const float* hidden = (const float*)d_in[0];
    const int*   pos    = (const int*)  d_in[2];
    const float* Wq     = (const float*)d_in[3];
    const float* Wk     = (const float*)d_in[4];
    const float* Wv     = (const float*)d_in[5];
    const float* Wo     = (const float*)d_in[6];
    const float* qw     = (const float*)d_in[7];
    const float* kw     = (const float*)d_in[8];
    float* out = (float*)d_out;

    float *Qp, *KVp;
    f16 *Hh16, *Hl16, *W16, *Qbh, *Qbl, *Ch, *Kt16, *V16;
    bf16 *Hhb, *Hlb, *Wbh, *Wbl;
    cudaGetSymbolAddress((void**)&Qp,   g_Q);
    cudaGetSymbolAddress((void**)&KVp,  g_KV);
    cudaGetSymbolAddress((void**)&Hh16, g_Hh16);
    cudaGetSymbolAddress((void**)&Hl16, g_Hl16);
    cudaGetSymbolAddress((void**)&Hhb,  g_Hhb);
    cudaGetSymbolAddress((void**)&Hlb,  g_Hlb);
    cudaGetSymbolAddress((void**)&Wbh,  g_Wbh);
    cudaGetSymbolAddress((void**)&Wbl,  g_Wbl);
    cudaGetSymbolAddress((void**)&W16,  g_W16);
    cudaGetSymbolAddress((void**)&Qbh,  g_Qbh);
    cudaGetSymbolAddress((void**)&Qbl,  g_Qbl);
    cudaGetSymbolAddress((void**)&Ch,   g_Ch);
    cudaGetSymbolAddress((void**)&Kt16, g_Kt16);
    cudaGetSymbolAddress((void**)&V16,  g_V16);

    cudaFuncSetAttribute(gemm_pre, cudaFuncAttributeMaxDynamicSharedMemorySize, GEMM_SMEM);
    cudaFuncSetAttribute(gemm_2t_f16, cudaFuncAttributeMaxDynamicSharedMemorySize, GEMM_O_SMEM);
    cudaFuncSetAttribute(gemm_1t_f16, cudaFuncAttributeMaxDynamicSharedMemorySize, GEMM_1T_SMEM);
    cudaFuncSetAttribute(attn_tc_kernel, cudaFuncAttributeMaxDynamicSharedMemorySize, ATTN_SMEM);

    // pre-split hidden (f16 + bf16 in one pass)
    split_hidden_dual<<<(NTOK*HID/4 + 255)/256, 256>>>(hidden, Hh16, Hl16, Hhb, Hlb, NTOK*HID/4);

    // Q projection (fp16 2-term)
    round_f16_mat<<<(HID*QCOLS/4 + 255)/256, 256>>>(Wq, W16, HID*QCOLS/4);
    gemm_2t_f16<<<dim3(QCOLS/128, NTOK/128), 256, GEMM_O_SMEM>>>(Hh16, Hl16, W16, Qp, NTOK, QCOLS, HID);

    // combined K|V projection (bf16 3-term, full precision)
    split_kv_w<<<(HID*KVW/4 + 255)/256, 256>>>(Wk, Wv, Wbh, Wbl);
    gemm_pre<<<dim3(KVW/128, NTOK/128), 256, GEMM_SMEM>>>(Hhb, Hlb, Wbh, Wbl, KVp, NTOK, KVW, HID);

    // RMSNorm + RoPE
    rmsrope_q_kernel<<<NTOK * NH, 128>>>(Qp, qw, pos, Qbh, Qbl);
    rmsrope_k_kernel<<<NTOK * NKV, 128>>>(KVp, kw, pos);

    // K -> single f16 transposed; V -> single f16
    round_k_trans<<<BATCH*NKV*HD, 256>>>(KVp, Kt16);
    split_v16<<<(NTOK*KVCOLS/4 + 255)/256, 256>>>(KVp, V16);

    // flash attention (S fp16 2-term, PV single-P; ctx single f16)
    attn_tc_kernel<<<dim3(SEQ/128, NH, BATCH), 256, ATTN_SMEM>>>(Qbh, Qbl, Kt16, V16, Ch);

    // output projection (fp16 1-term: single ctx x single Wo)
    round_f16_mat<<<(QCOLS*HID/4 + 255)/256, 256>>>(Wo, W16, QCOLS*HID/4);
    gemm_1t_f16<<<dim3(HID/128, NTOK/128), 256, GEMM_1T_SMEM>>>(Ch, W16, out, NTOK, HID, QCOLS);
}

// round 13
// speedup vs baseline: 1.3927x; 1.0719x over previous
#include <cuda_runtime.h>
#include <cuda_fp16.h>
#include <math.h>
#include <stdint.h>

// Problem constants
#define BATCH 2
#define SEQ   2048
#define HID   2048
#define NH    32
#define NKV   4
#define HD    128
#define NTOK  (BATCH*SEQ)          // 4096
#define QCOLS (NH*HD)              // 4096
#define KVCOLS (NKV*HD)            // 512
#define KVW   (2*KVCOLS)           // 1024 (K|V concatenated)

typedef __half f16;

// -------- scratch (device globals) --------
__device__ float g_Q [(size_t)NTOK * QCOLS];    // Q projection out (fp32)
__device__ float g_KV[(size_t)NTOK * KVW];      // K|V projection out (fp32)
__device__ f16  g_Hh16[(size_t)NTOK * HID], g_Hl16[(size_t)NTOK * HID];   // hidden f16 split
__device__ f16  g_W16[(size_t)HID * QCOLS];                               // Wq / Wkv / Wo single f16
__device__ f16  g_Qb[(size_t)NTOK * QCOLS];                               // Q normed+roped single f16
__device__ f16  g_Ch[(size_t)NTOK * QCOLS];                               // ctx single f16
__device__ f16  g_Kt16[(size_t)BATCH*NKV*HD*SEQ];                         // K transposed single f16
__device__ f16  g_V16[(size_t)NTOK * KVCOLS];                             // V single f16

// ============================================================================
// PTX helpers
// ============================================================================
__device__ __forceinline__ uint32_t smem_u32(const void* p) {
    return (uint32_t)__cvta_generic_to_shared(p);
}
__device__ __forceinline__ void ldmatrix_x4(uint32_t* r, uint32_t addr) {
    asm volatile("ldmatrix.sync.aligned.m8n8.x4.shared.b16 {%0,%1,%2,%3}, [%4];"
                 : "=r"(r[0]), "=r"(r[1]), "=r"(r[2]), "=r"(r[3]) : "r"(addr));
}
__device__ __forceinline__ void ldmatrix_x4_trans(uint32_t* r, uint32_t addr) {
    asm volatile("ldmatrix.sync.aligned.m8n8.x4.trans.shared.b16 {%0,%1,%2,%3}, [%4];"
                 : "=r"(r[0]), "=r"(r[1]), "=r"(r[2]), "=r"(r[3]) : "r"(addr));
}
__device__ __forceinline__ void mma_f16(float* d, const uint32_t* a, const uint32_t* b) {
    asm volatile("mma.sync.aligned.m16n8k16.row.col.f32.f16.f16.f32 "
                 "{%0,%1,%2,%3}, {%4,%5,%6,%7}, {%8,%9}, {%0,%1,%2,%3};"
                 : "+f"(d[0]), "+f"(d[1]), "+f"(d[2]), "+f"(d[3])
                 : "r"(a[0]), "r"(a[1]), "r"(a[2]), "r"(a[3]),
                   "r"(b[0]), "r"(b[1]));
}
__device__ __forceinline__ void split2h(float x, f16& h, f16& l) {
    h = __float2half_rn(x);
    l = __float2half_rn(x - __half2float(h));
}
__device__ __forceinline__ uint32_t pack_h2(f16 lo, f16 hi) {
    __half2 r = __halves2half2(lo, hi);
    return *(uint32_t*)&r;
}
__device__ __forceinline__ void split4_pack_h(float4 v, uint2& hh, uint2& ll) {
    f16 hx, lx, hy, ly, hz, lz, hw, lw;
    split2h(v.x, hx, lx); split2h(v.y, hy, ly);
    split2h(v.z, hz, lz); split2h(v.w, hw, lw);
    hh.x = pack_h2(hx, hy);
    hh.y = pack_h2(hz, hw);
    ll.x = pack_h2(lx, ly);
    ll.y = pack_h2(lz, lw);
}
__device__ __forceinline__ uint2 round4_f16(float4 v) {
    uint2 r;
    __half2 a = __floats2half2_rn(v.x, v.y);
    __half2 b = __floats2half2_rn(v.z, v.w);
    r.x = *(uint32_t*)&a;
    r.y = *(uint32_t*)&b;
    return r;
}
__device__ __forceinline__ void cp_async16(uint32_t dst, const void* src) {
    asm volatile("cp.async.cg.shared.global [%0], [%1], 16;" :: "r"(dst), "l"(src));
}
#define CP_COMMIT asm volatile("cp.async.commit_group;")
#define CP_WAIT0  asm volatile("cp.async.wait_group 0;" ::: "memory")
#define CP_WAIT1  asm volatile("cp.async.wait_group 1;" ::: "memory")

// ============================================================================
// Elementwise kernels
// ============================================================================
__global__ __launch_bounds__(256)
void split_hidden_h16(const float* __restrict__ src,
                      f16* __restrict__ dh, f16* __restrict__ dl, int n4)
{
    const int i = blockIdx.x * 256 + threadIdx.x;
    if (i < n4) {
        float4 v = ((const float4*)src)[i];
        uint2 hh, ll;
        split4_pack_h(v, hh, ll);
        ((uint2*)dh)[i] = hh;
        ((uint2*)dl)[i] = ll;
    }
}

__global__ __launch_bounds__(256)
void round_f16_mat(const float* __restrict__ src, f16* __restrict__ d, int n4)
{
    const int i = blockIdx.x * 256 + threadIdx.x;
    if (i < n4) ((uint2*)d)[i] = round4_f16(((const float4*)src)[i]);
}

// Wk[K][512], Wv[K][512] -> combined single f16 [K][1024]
__global__ __launch_bounds__(256)
void round_kv_w(const float* __restrict__ Wk, const float* __restrict__ Wv,
                f16* __restrict__ d)
{
    const int i = blockIdx.x * 256 + threadIdx.x;
    if (i >= HID * KVW / 4) return;
    const int row = i / (KVW / 4);
    const int c4  = (i % (KVW / 4)) * 4;
    float4 v;
    if (c4 < KVCOLS) v = *(const float4*)(Wk + (size_t)row * KVCOLS + c4);
    else             v = *(const float4*)(Wv + (size_t)row * KVCOLS + (c4 - KVCOLS));
    *(uint2*)(d + (size_t)row * KVW + c4) = round4_f16(v);
}

// V part of g_KV -> single fp16 [tok][512]
__global__ __launch_bounds__(256)
void split_v16(const float* __restrict__ KV, f16* __restrict__ d)
{
    const int i = blockIdx.x * 256 + threadIdx.x;
    if (i >= NTOK * KVCOLS / 4) return;
    const int tok = i / (KVCOLS / 4);
    const int c4  = (i % (KVCOLS / 4)) * 4;
    float4 v = *(const float4*)(KV + (size_t)tok * KVW + KVCOLS + c4);
    *(uint2*)(d + (size_t)tok * KVCOLS + c4) = round4_f16(v);
}

// K part of g_KV -> single f16 transposed [(b*NKV+hk)*128+d][tok]
__global__ __launch_bounds__(256)
void round_k_trans(const float* __restrict__ KV, f16* __restrict__ d)
{
    const int blk = blockIdx.x;
    const int bhk = blk >> 7;
    const int dd  = blk & 127;
    const int b   = bhk >> 2, hk = bhk & 3;
    const int t0  = threadIdx.x * 8;
    const float* src = KV + ((size_t)b * SEQ + t0) * KVW + hk * HD + dd;
    __align__(16) f16 h8[8];
    #pragma unroll
    for (int j = 0; j < 8; j++) h8[j] = __float2half_rn(src[(size_t)j * KVW]);
    const size_t o = ((size_t)bhk * HD + dd) * SEQ + t0;
    *(uint4*)&d[o] = *(uint4*)h8;
}

// ============================================================================
// Shared GEMM tile constants
// ============================================================================
#define ASTR 40
#define BSTR 136

// ============================================================================
// GEMM fp16 2-term: C = (Ah+Al) @ Bh   (KV projection)
// ============================================================================
#define GO_A_H 0
#define GO_A_L 10240
#define GO_B_H 20480
#define GO_SZ  29184
#define GEMM_2T_SMEM (2 * GO_SZ)

__global__ __launch_bounds__(256, 2)
void gemm_2t_f16(const f16* __restrict__ Ah_g, const f16* __restrict__ Al_g,
                 const f16* __restrict__ Bh_g,
                 float* __restrict__ C, int M, int N, int K)
{
    extern __shared__ char smg[];
    const uint32_t sb = smem_u32(smg);

    const int tid  = threadIdx.x;
    const int warp = tid >> 5;
    const int lane = tid & 31;
    const int wm = (warp >> 1) * 32;
    const int wn = (warp & 1) * 64;
    const int bx = blockIdx.x * 128;
    const int by = blockIdx.y * 128;

    float acc[2][8][4];
    #pragma unroll
    for (int mi = 0; mi < 2; mi++)
        #pragma unroll
        for (int ni = 0; ni < 8; ni++)
            #pragma unroll
            for (int e = 0; e < 4; e++) acc[mi][ni][e] = 0.f;

    const int ar = tid >> 1, acb = (tid & 1) * 16;
    const int brw = tid >> 3, bcb = (tid & 7) * 16;

    auto issue_tile = [&](int k0, uint32_t bufb) {
        const f16* a_h = Ah_g + (size_t)(by + ar) * K + k0 + acb;
        const f16* a_l = Al_g + (size_t)(by + ar) * K + k0 + acb;
        const uint32_t da = bufb + GO_A_H + (uint32_t)(ar * 80 + acb * 2);
        const uint32_t dal = bufb + GO_A_L + (uint32_t)(ar * 80 + acb * 2);
        cp_async16(da,       a_h);
        cp_async16(da + 16,  a_h + 8);
        cp_async16(dal,      a_l);
        cp_async16(dal + 16, a_l + 8);
        const f16* b_h = Bh_g + (size_t)(k0 + brw) * N + bx + bcb;
        const uint32_t db = bufb + GO_B_H + (uint32_t)(brw * 272 + bcb * 2);
        cp_async16(db,      b_h);
        cp_async16(db + 16, b_h + 8);
    };

    const int aoff = (wm + (lane & 15)) * ASTR + ((lane >> 4) << 3);
    const int boff = (lane & 15) * BSTR + wn + ((lane >> 4) << 3);

    const int NIT = K >> 5;
    issue_tile(0, sb);
    CP_COMMIT;

    for (int t = 0; t < NIT; t++) {
        __syncthreads();
        if (t + 1 < NIT) {
            issue_tile((t + 1) * 32, sb + ((t + 1) & 1) * GO_SZ);
            CP_COMMIT;
            CP_WAIT1;
        } else {
            CP_WAIT0;
        }
        __syncthreads();

        const uint32_t bufb = sb + (t & 1) * GO_SZ;
        const uint32_t Ah_b = bufb + GO_A_H;
        const uint32_t Al_b = bufb + GO_A_L;
        const uint32_t Bh_b = bufb + GO_B_H;

        #pragma unroll
        for (int kk = 0; kk < 32; kk += 16) {
            uint32_t ah[2][4], al[2][4];
            #pragma unroll
            for (int mi = 0; mi < 2; mi++) {
                ldmatrix_x4(ah[mi], Ah_b + (aoff + mi * 16 * ASTR + kk) * 2);
                ldmatrix_x4(al[mi], Al_b + (aoff + mi * 16 * ASTR + kk) * 2);
            }
            #pragma unroll
            for (int p = 0; p < 4; p++) {
                uint32_t bh[4];
                const uint32_t off = (boff + kk * BSTR + p * 16) * 2;
                ldmatrix_x4_trans(bh, Bh_b + off);
                #pragma unroll
                for (int mi = 0; mi < 2; mi++) {
                    mma_f16(acc[mi][2*p],   ah[mi], bh);
                    mma_f16(acc[mi][2*p],   al[mi], bh);
                    mma_f16(acc[mi][2*p+1], ah[mi], bh + 2);
                    mma_f16(acc[mi][2*p+1], al[mi], bh + 2);
                }
            }
        }
    }

    const int g = lane >> 2;
    const int t = lane & 3;
    #pragma unroll
    for (int mi = 0; mi < 2; mi++) {
        #pragma unroll
        for (int ni = 0; ni < 8; ni++) {
            const size_t row0 = (size_t)(by + wm + mi * 16 + g);
            const int col = bx + wn + ni * 8 + 2 * t;
            *(float2*)(C + row0 * N + col)       = make_float2(acc[mi][ni][0], acc[mi][ni][1]);
            *(float2*)(C + (row0 + 8) * N + col) = make_float2(acc[mi][ni][2], acc[mi][ni][3]);
        }
    }
}

// ============================================================================
// GEMM fp16 1-term: C = A @ B  (Q projection, O projection)
// ============================================================================
#define G1_A 0
#define G1_B 10240
#define G1_SZ 18944
#define GEMM_1T_SMEM (2 * G1_SZ)

__global__ __launch_bounds__(256, 2)
void gemm_1t_f16(const f16* __restrict__ A_g, const f16* __restrict__ B_g,
                 float* __restrict__ C, int M, int N, int K)
{
    extern __shared__ char smg[];
    const uint32_t sb = smem_u32(smg);

    const int tid  = threadIdx.x;
    const int warp = tid >> 5;
    const int lane = tid & 31;
    const int wm = (warp >> 1) * 32;
    const int wn = (warp & 1) * 64;
    const int bx = blockIdx.x * 128;
    const int by = blockIdx.y * 128;

    float acc[2][8][4];
    #pragma unroll
    for (int mi = 0; mi < 2; mi++)
        #pragma unroll
        for (int ni = 0; ni < 8; ni++)
            #pragma unroll
            for (int e = 0; e < 4; e++) acc[mi][ni][e] = 0.f;

    const int ar = tid >> 1, acb = (tid & 1) * 16;
    const int brw = tid >> 3, bcb = (tid & 7) * 16;

    auto issue_tile = [&](int k0, uint32_t bufb) {
        const f16* a = A_g + (size_t)(by + ar) * K + k0 + acb;
        const uint32_t da = bufb + G1_A + (uint32_t)(ar * 80 + acb * 2);
        cp_async16(da,      a);
        cp_async16(da + 16, a + 8);
        const f16* b = B_g + (size_t)(k0 + brw) * N + bx + bcb;
        const uint32_t db = bufb + G1_B + (uint32_t)(brw * 272 + bcb * 2);
        cp_async16(db,      b);
        cp_async16(db + 16, b + 8);
    };

    const int aoff = (wm + (lane & 15)) * ASTR + ((lane >> 4) << 3);
    const int boff = (lane & 15) * BSTR + wn + ((lane >> 4) << 3);

    const int NIT = K >> 5;
    issue_tile(0, sb);
    CP_COMMIT;

    for (int t = 0; t < NIT; t++) {
        __syncthreads();
        if (t + 1 < NIT) {
            issue_tile((t + 1) * 32, sb + ((t + 1) & 1) * G1_SZ);
            CP_COMMIT;
            CP_WAIT1;
        } else {
            CP_WAIT0;
        }
        __syncthreads();

        const uint32_t bufb = sb + (t & 1) * G1_SZ;
        const uint32_t A_b = bufb + G1_A;
        const uint32_t B_b = bufb + G1_B;

        #pragma unroll
        for (int kk = 0; kk < 32; kk += 16) {
            uint32_t ah[2][4];
            #pragma unroll
            for (int mi = 0; mi < 2; mi++)
                ldmatrix_x4(ah[mi], A_b + (aoff + mi * 16 * ASTR + kk) * 2);
            #pragma unroll
            for (int p = 0; p < 4; p++) {
                uint32_t bh[4];
                const uint32_t off = (boff + kk * BSTR + p * 16) * 2;
                ldmatrix_x4_trans(bh, B_b + off);
                #pragma unroll
                for (int mi = 0; mi < 2; mi++) {
                    mma_f16(acc[mi][2*p],   ah[mi], bh);
                    mma_f16(acc[mi][2*p+1], ah[mi], bh + 2);
                }
            }
        }
    }

    const int g = lane >> 2;
    const int t = lane & 3;
    #pragma unroll
    for (int mi = 0; mi < 2; mi++) {
        #pragma unroll
        for (int ni = 0; ni < 8; ni++) {
            const size_t row0 = (size_t)(by + wm + mi * 16 + g);
            const int col = bx + wn + ni * 8 + 2 * t;
            *(float2*)(C + row0 * N + col)       = make_float2(acc[mi][ni][0], acc[mi][ni][1]);
            *(float2*)(C + (row0 + 8) * N + col) = make_float2(acc[mi][ni][2], acc[mi][ni][3]);
        }
    }
}

// ============================================================================
// RMSNorm + RoPE (Q: fp32 -> single f16 unscaled; K: in-place)
// ============================================================================
__global__ __launch_bounds__(128)
void rmsrope_q_kernel(const float* __restrict__ X, const float* __restrict__ w,
                      const int* __restrict__ pos, f16* __restrict__ Qb)
{
    const int blk = blockIdx.x;
    const int token = blk / NH;
    const int h     = blk % NH;
    const float* x = X + (size_t)token * QCOLS + h * HD;

    const int i = threadIdx.x;
    float v = x[i];

    float ss = v * v;
    #pragma unroll
    for (int m = 16; m; m >>= 1) ss += __shfl_xor_sync(0xffffffffu, ss, m);
    __shared__ float wsum[4];
    if ((i & 31) == 0) wsum[i >> 5] = ss;
    __syncthreads();
    float tot = wsum[0] + wsum[1] + wsum[2] + wsum[3];
    float inv = rsqrtf(tot * (1.0f / 128.0f) + 1e-6f);

    __shared__ float xs[128];
    xs[i] = v * inv * w[i];
    __syncthreads();

    const int p = pos[token];
    const int j = i & 63;
    float invf = (float)pow(1.0e6, -(double)j / 64.0);
    float f = (float)p * invf;
    float c, s;
    sincosf(f, &s, &c);
    float xi = xs[i];
    float partner = (i < 64) ? -xs[i + 64] : xs[i - 64];
    Qb[(size_t)token * QCOLS + h * HD + i] = __float2half_rn(xi * c + partner * s);
}

__global__ __launch_bounds__(128)
void rmsrope_k_kernel(float* __restrict__ KV, const float* __restrict__ w,
                      const int* __restrict__ pos)
{
    const int blk = blockIdx.x;
    const int token = blk / NKV;
    const int hk    = blk % NKV;
    float* x = KV + (size_t)token * KVW + hk * HD;

    const int i = threadIdx.x;
    float v = x[i];

    float ss = v * v;
    #pragma unroll
    for (int m = 16; m; m >>= 1) ss += __shfl_xor_sync(0xffffffffu, ss, m);
    __shared__ float wsum[4];
    if ((i & 31) == 0) wsum[i >> 5] = ss;
    __syncthreads();
    float tot = wsum[0] + wsum[1] + wsum[2] + wsum[3];
    float inv = rsqrtf(tot * (1.0f / 128.0f) + 1e-6f);

    __shared__ float xs[128];
    xs[i] = v * inv * w[i];
    __syncthreads();

    const int p = pos[token];
    const int j = i & 63;
    float invf = (float)pow(1.0e6, -(double)j / 64.0);
    float f = (float)p * invf;
    float c, s;
    sincosf(f, &s, &c);
    float xi = xs[i];
    float partner = (i < 64) ? -xs[i + 64] : xs[i - 64];
    x[i] = xi * c + partner * s;
}

// ============================================================================
// Flash attention: S = fp16 1-term; PV = fp16 1-term; ctx single f16.
// Br=128 (8 warps), Bc=64, 256 threads, cp.async double-buffered.
// ============================================================================
#define QSTR 136
#define KSTR 72
#define VSTR 136
#define AT_Q     0
#define AT_BUF0  (128*QSTR*2)
#define AT_KH    0
#define AT_VH    (128*KSTR*2)
#define AT_BUFSZ (128*KSTR*2 + 64*VSTR*2)
#define ATTN_SMEM (AT_BUF0 + 2*AT_BUFSZ)

__global__ __launch_bounds__(256, 1)
void attn_tc_kernel(const f16* __restrict__ QbG,
                    const f16* __restrict__ KtG, const f16* __restrict__ VG,
                    f16* __restrict__ Ch)
{
    extern __shared__ char sma[];
    const uint32_t sb = smem_u32(sma);

    const int qt = gridDim.x - 1 - blockIdx.x;
    const int h  = blockIdx.y;
    const int b  = blockIdx.z;
    const int hk = h >> 3;

    const int tid  = threadIdx.x;
    const int warp = tid >> 5;
    const int lane = tid & 31;
    const int g  = lane >> 2;
    const int t4 = lane & 3;

    const float scale = 0.08838834764831845f;
    const int ntiles = 2 * qt + 2;

    const f16* kt_g = KtG + (size_t)(b * NKV + hk) * HD * SEQ;
    const f16* v_g  = VG + (size_t)b * SEQ * KVCOLS + hk * HD;

    const int kd = tid >> 1, kc0 = (tid & 1) * 32;
    const int vc = tid >> 2, vd0 = (tid & 3) * 32;

    auto issue_kv = [&](int jt, uint32_t bufb) {
        const f16* kh = kt_g + (size_t)kd * SEQ + jt * 64 + kc0;
        const uint32_t dk = bufb + AT_KH + (uint32_t)(kd * 144 + kc0 * 2);
        #pragma unroll
        for (int u = 0; u < 4; u++)
            cp_async16(dk + u * 16, kh + u * 8);
        const f16* vv = v_g + (size_t)(jt * 64 + vc) * KVCOLS + vd0;
        const uint32_t dv = bufb + AT_VH + (uint32_t)(vc * 272 + vd0 * 2);
        #pragma unroll
        for (int u = 0; u < 4; u++)
            cp_async16(dv + u * 16, vv + u * 8);
    };

    // prefetch Q (single f16) + KV tile 0
    {
        const int r  = tid >> 1;
        const int c0 = (tid & 1) * 64;
        const f16* q = QbG + ((size_t)(b * SEQ + qt * 128 + r)) * QCOLS + h * HD + c0;
        const uint32_t dq = sb + AT_Q + (uint32_t)(r * QSTR * 2 + c0 * 2);
        #pragma unroll
        for (int u = 0; u < 8; u++)
            cp_async16(dq + u * 16, q + u * 8);
    }
    issue_kv(0, sb + AT_BUF0);
    CP_COMMIT;

    float oacc[16][4];
    #pragma unroll
    for (int nt = 0; nt < 16; nt++)
        #pragma unroll
        for (int e = 0; e < 4; e++) oacc[nt][e] = 0.f;
    float mrow0 = -1e30f, mrow1 = -1e30f, lrow0 = 0.f, lrow1 = 0.f;

    const int qrow0 = qt * 128 + warp * 16 + g;
    const int qrow1 = qrow0 + 8;
    const int warp_maxrow = qt * 128 + warp * 16 + 15;

    const uint32_t q_base = sb + AT_Q + ((warp*16 + (lane & 15)) * QSTR + ((lane >> 4) << 3)) * 2;
    const uint32_t koffB = ((lane & 15) * KSTR + ((lane >> 4) << 3)) * 2;
    const uint32_t voffB = ((lane & 15) * VSTR + ((lane >> 4) << 3)) * 2;

    for (int jt = 0; jt < ntiles; jt++) {
        __syncthreads();
        if (jt + 1 < ntiles) {
            issue_kv(jt + 1, sb + AT_BUF0 + ((jt + 1) & 1) * AT_BUFSZ);
            CP_COMMIT;
            CP_WAIT1;
        } else {
            CP_WAIT0;
        }
        __syncthreads();

        if (jt * 64 > warp_maxrow) continue;

        const uint32_t bufb = sb + AT_BUF0 + (jt & 1) * AT_BUFSZ;
        const uint32_t kt_b = bufb + AT_KH + koffB;
        const uint32_t vh_b = bufb + AT_VH + voffB;

        // ---- S = Q @ Kt (fp16 1-term) ----
        float sacc[8][4];
        #pragma unroll
        for (int nt = 0; nt < 8; nt++)
            #pragma unroll
            for (int e = 0; e < 4; e++) sacc[nt][e] = 0.f;

        #pragma unroll
        for (int kk = 0; kk < 8; kk++) {
            uint32_t ah[4];
            ldmatrix_x4(ah, q_base + kk * 16 * sizeof(f16));
            #pragma unroll
            for (int p = 0; p < 4; p++) {
                uint32_t bh[4];
                const uint32_t off = (kk * 16 * KSTR + p * 16) * sizeof(f16);
                ldmatrix_x4_trans(bh, kt_b + off);
                mma_f16(sacc[2*p],   ah, bh);
                mma_f16(sacc[2*p+1], ah, bh + 2);
            }
        }

        // ---- apply scale, causal mask, online softmax ----
        float mx0 = -1e30f, mx1 = -1e30f;
        #pragma unroll
        for (int nt = 0; nt < 8; nt++) {
            sacc[nt][0] *= scale;
            sacc[nt][1] *= scale;
            sacc[nt][2] *= scale;
            sacc[nt][3] *= scale;
            const int col = jt * 64 + nt * 8 + 2 * t4;
            if (col     > qrow0) sacc[nt][0] = -1e30f;
            if (col + 1 > qrow0) sacc[nt][1] = -1e30f;
            if (col     > qrow1) sacc[nt][2] = -1e30f;
            if (col + 1 > qrow1) sacc[nt][3] = -1e30f;
            mx0 = fmaxf(mx0, fmaxf(sacc[nt][0], sacc[nt][1]));
            mx1 = fmaxf(mx1, fmaxf(sacc[nt][2], sacc[nt][3]));
        }
        mx0 = fmaxf(mx0, __shfl_xor_sync(0xffffffffu, mx0, 1));
        mx0 = fmaxf(mx0, __shfl_xor_sync(0xffffffffu, mx0, 2));
        mx1 = fmaxf(mx1, __shfl_xor_sync(0xffffffffu, mx1, 1));
        mx1 = fmaxf(mx1, __shfl_xor_sync(0xffffffffu, mx1, 2));

        const float mnew0 = fmaxf(mrow0, mx0);
        const float mnew1 = fmaxf(mrow1, mx1);
        const float alpha0 = __expf(mrow0 - mnew0);
        const float alpha1 = __expf(mrow1 - mnew1);

        float rs0 = 0.f, rs1 = 0.f;
        #pragma unroll
        for (int nt = 0; nt < 8; nt++) {
            sacc[nt][0] = __expf(sacc[nt][0] - mnew0);
            sacc[nt][1] = __expf(sacc[nt][1] - mnew0);
            sacc[nt][2] = __expf(sacc[nt][2] - mnew1);
            sacc[nt][3] = __expf(sacc[nt][3] - mnew1);
            rs0 += sacc[nt][0] + sacc[nt][1];
            rs1 += sacc[nt][2] + sacc[nt][3];
        }
        rs0 += __shfl_xor_sync(0xffffffffu, rs0, 1);
        rs0 += __shfl_xor_sync(0xffffffffu, rs0, 2);
        rs1 += __shfl_xor_sync(0xffffffffu, rs1, 1);
        rs1 += __shfl_xor_sync(0xffffffffu, rs1, 2);

        lrow0 = lrow0 * alpha0 + rs0;
        lrow1 = lrow1 * alpha1 + rs1;
        mrow0 = mnew0;
        mrow1 = mnew1;

        #pragma unroll
        for (int nt = 0; nt < 16; nt++) {
            oacc[nt][0] *= alpha0;
            oacc[nt][1] *= alpha0;
            oacc[nt][2] *= alpha1;
            oacc[nt][3] *= alpha1;
        }

        // ---- O += P @ V (single-fp16 P, single V) ----
        #pragma unroll
        for (int c = 0; c < 4; c++) {
            uint32_t ph[4];
            {
                __half2 p0 = __floats2half2_rn(sacc[2*c][0],   sacc[2*c][1]);
                __half2 p1 = __floats2half2_rn(sacc[2*c][2],   sacc[2*c][3]);
                __half2 p2 = __floats2half2_rn(sacc[2*c+1][0], sacc[2*c+1][1]);
                __half2 p3 = __floats2half2_rn(sacc[2*c+1][2], sacc[2*c+1][3]);
                ph[0] = *(uint32_t*)&p0;
                ph[1] = *(uint32_t*)&p1;
                ph[2] = *(uint32_t*)&p2;
                ph[3] = *(uint32_t*)&p3;
            }
            #pragma unroll
            for (int p = 0; p < 8; p++) {
                uint32_t vh[4];
                const uint32_t off = (c * 16 * VSTR + p * 16) * sizeof(f16);
                ldmatrix_x4_trans(vh, vh_b + off);
                mma_f16(oacc[2*p],   ph, vh);
                mma_f16(oacc[2*p+1], ph, vh + 2);
            }
        }
    }

    // ---- epilogue: write single-fp16 ctx ----
    const float inv0 = 1.0f / lrow0;
    const float inv1 = 1.0f / lrow1;
    const size_t o0 = ((size_t)(b * SEQ + qrow0)) * QCOLS + h * HD;
    const size_t o1 = ((size_t)(b * SEQ + qrow1)) * QCOLS + h * HD;
    #pragma unroll
    for (int nt = 0; nt < 16; nt++) {
        const int col = nt * 8 + 2 * t4;
        __half2 c0 = __floats2half2_rn(oacc[nt][0] * inv0, oacc[nt][1] * inv0);
        __half2 c1 = __floats2half2_rn(oacc[nt][2] * inv1, oacc[nt][3] * inv1);
        *(uint32_t*)(Ch + o0 + col) = *(uint32_t*)&c0;
        *(uint32_t*)(Ch + o1 + col) = *(uint32_t*)&c1;
    }
}

// ============================================================================
// Launch
// ============================================================================
extern "C" void kernel_launch(void* const* d_in, const int* in_sizes, int n_in,
                              void* d_out, int out_size)
{
    const float* hidden = (const float*)d_in[0];
    const int*   pos    = (const int*)  d_in[2];
    const float* Wq     = (const float*)d_in[3];
    const float* Wk     = (const float*)d_in[4];
    const float* Wv     = (const float*)d_in[5];
    const float* Wo     = (const float*)d_in[6];
    const float* qw     = (const float*)d_in[7];
    const float* kw     = (const float*)d_in[8];
    float* out = (float*)d_out;

    float *Qp, *KVp;
    f16 *Hh16, *Hl16, *W16, *Qb, *Ch, *Kt16, *V16;
    cudaGetSymbolAddress((void**)&Qp,   g_Q);
    cudaGetSymbolAddress((void**)&KVp,  g_KV);
    cudaGetSymbolAddress((void**)&Hh16, g_Hh16);
    cudaGetSymbolAddress((void**)&Hl16, g_Hl16);
    cudaGetSymbolAddress((void**)&W16,  g_W16);
    cudaGetSymbolAddress((void**)&Qb,   g_Qb);
    cudaGetSymbolAddress((void**)&Ch,   g_Ch);
    cudaGetSymbolAddress((void**)&Kt16, g_Kt16);
    cudaGetSymbolAddress((void**)&V16,  g_V16);

    cudaFuncSetAttribute(gemm_2t_f16, cudaFuncAttributeMaxDynamicSharedMemorySize, GEMM_2T_SMEM);
    cudaFuncSetAttribute(gemm_1t_f16, cudaFuncAttributeMaxDynamicSharedMemorySize, GEMM_1T_SMEM);
    cudaFuncSetAttribute(attn_tc_kernel, cudaFuncAttributeMaxDynamicSharedMemorySize, ATTN_SMEM);

    // pre-split hidden (f16 hi/lo)
    split_hidden_h16<<<(NTOK*HID/4 + 255)/256, 256>>>(hidden, Hh16, Hl16, NTOK*HID/4);

    // Q projection (fp16 1-term: single hidden x single Wq)
    round_f16_mat<<<(HID*QCOLS/4 + 255)/256, 256>>>(Wq, W16, HID*QCOLS/4);
    gemm_1t_f16<<<dim3(QCOLS/128, NTOK/128), 256, GEMM_1T_SMEM>>>(Hh16, W16, Qp, NTOK, QCOLS, HID);

    // combined K|V projection (fp16 2-term: split hidden x single Wkv)
    round_kv_w<<<(HID*KVW/4 + 255)/256, 256>>>(Wk, Wv, W16);
    gemm_2t_f16<<<dim3(KVW/128, NTOK/128), 256, GEMM_2T_SMEM>>>(Hh16, Hl16, W16, KVp, NTOK, KVW, HID);

    // RMSNorm + RoPE
    rmsrope_q_kernel<<<NTOK * NH, 128>>>(Qp, qw, pos, Qb);
    rmsrope_k_kernel<<<NTOK * NKV, 128>>>(KVp, kw, pos);

    // K -> single f16 transposed; V -> single f16
    round_k_trans<<<BATCH*NKV*HD, 256>>>(KVp, Kt16);
    split_v16<<<(NTOK*KVCOLS/4 + 255)/256, 256>>>(KVp, V16);

    // flash attention (all fp16 1-term)
    attn_tc_kernel<<<dim3(SEQ/128, NH, BATCH), 256, ATTN_SMEM>>>(Qb, Kt16, V16, Ch);

    // output projection (fp16 1-term)
    round_f16_mat<<<(QCOLS*HID/4 + 255)/256, 256>>>(Wo, W16, QCOLS*HID/4);
    gemm_1t_f16<<<dim3(HID/128, NTOK/128), 256, GEMM_1T_SMEM>>>(Ch, W16, out, NTOK, HID, QCOLS);
}

// round 14
// speedup vs baseline: 1.3992x; 1.0046x over previous
#include <cuda_runtime.h>
#include <cuda_fp16.h>
#include <math.h>
#include <stdint.h>

// Problem constants
#define BATCH 2
#define SEQ   2048
#define HID   2048
#define NH    32
#define NKV   4
#define HD    128
#define NTOK  (BATCH*SEQ)          // 4096
#define QCOLS (NH*HD)              // 4096
#define KVCOLS (NKV*HD)            // 512
#define QKVW  (QCOLS + 2*KVCOLS)   // 5120 (Q|K|V concatenated)

typedef __half f16;

// -------- scratch (device globals) --------
__device__ float g_QKV[(size_t)NTOK * QKVW];    // Q|K|V projection out (fp32), 80 MiB
__device__ f16  g_H16[(size_t)NTOK * HID];      // hidden single f16
__device__ f16  g_W16[(size_t)HID * QKVW];      // Wqkv (or Wo) single f16
__device__ f16  g_Qb[(size_t)NTOK * QCOLS];     // Q normed+roped single f16
__device__ f16  g_Ch[(size_t)NTOK * QCOLS];     // ctx single f16
__device__ f16  g_Kt16[(size_t)BATCH*NKV*HD*SEQ]; // K transposed single f16
__device__ f16  g_V16[(size_t)NTOK * KVCOLS];   // V single f16

// ============================================================================
// PTX helpers
// ============================================================================
__device__ __forceinline__ uint32_t smem_u32(const void* p) {
    return (uint32_t)__cvta_generic_to_shared(p);
}
__device__ __forceinline__ void ldmatrix_x4(uint32_t* r, uint32_t addr) {
    asm volatile("ldmatrix.sync.aligned.m8n8.x4.shared.b16 {%0,%1,%2,%3}, [%4];"
                 : "=r"(r[0]), "=r"(r[1]), "=r"(r[2]), "=r"(r[3]) : "r"(addr));
}
__device__ __forceinline__ void ldmatrix_x4_trans(uint32_t* r, uint32_t addr) {
    asm volatile("ldmatrix.sync.aligned.m8n8.x4.trans.shared.b16 {%0,%1,%2,%3}, [%4];"
                 : "=r"(r[0]), "=r"(r[1]), "=r"(r[2]), "=r"(r[3]) : "r"(addr));
}
__device__ __forceinline__ void mma_f16(float* d, const uint32_t* a, const uint32_t* b) {
    asm volatile("mma.sync.aligned.m16n8k16.row.col.f32.f16.f16.f32 "
                 "{%0,%1,%2,%3}, {%4,%5,%6,%7}, {%8,%9}, {%0,%1,%2,%3};"
                 : "+f"(d[0]), "+f"(d[1]), "+f"(d[2]), "+f"(d[3])
                 : "r"(a[0]), "r"(a[1]), "r"(a[2]), "r"(a[3]),
                   "r"(b[0]), "r"(b[1]));
}
__device__ __forceinline__ uint2 round4_f16(float4 v) {
    uint2 r;
    __half2 a = __floats2half2_rn(v.x, v.y);
    __half2 b = __floats2half2_rn(v.z, v.w);
    r.x = *(uint32_t*)&a;
    r.y = *(uint32_t*)&b;
    return r;
}
__device__ __forceinline__ void cp_async16(uint32_t dst, const void* src) {
    asm volatile("cp.async.cg.shared.global [%0], [%1], 16;" :: "r"(dst), "l"(src));
}
#define CP_COMMIT asm volatile("cp.async.commit_group;")
#define CP_WAIT0  asm volatile("cp.async.wait_group 0;" ::: "memory")
#define CP_WAIT1  asm volatile("cp.async.wait_group 1;" ::: "memory")

// ============================================================================
// Elementwise kernels
// ============================================================================
__global__ __launch_bounds__(256)
void round_f16_mat(const float* __restrict__ src, f16* __restrict__ d, int n4)
{
    const int i = blockIdx.x * 256 + threadIdx.x;
    if (i < n4) ((uint2*)d)[i] = round4_f16(((const float4*)src)[i]);
}

// Wq[K][4096], Wk[K][512], Wv[K][512] -> combined single f16 [K][5120]
__global__ __launch_bounds__(256)
void round_qkv_w(const float* __restrict__ Wq, const float* __restrict__ Wk,
                 const float* __restrict__ Wv, f16* __restrict__ d)
{
    const int i = blockIdx.x * 256 + threadIdx.x;
    if (i >= HID * QKVW / 4) return;
    const int row = i / (QKVW / 4);
    const int c4  = (i % (QKVW / 4)) * 4;
    float4 v;
    if (c4 < QCOLS)               v = *(const float4*)(Wq + (size_t)row * QCOLS + c4);
    else if (c4 < QCOLS + KVCOLS) v = *(const float4*)(Wk + (size_t)row * KVCOLS + (c4 - QCOLS));
    else                          v = *(const float4*)(Wv + (size_t)row * KVCOLS + (c4 - QCOLS - KVCOLS));
    *(uint2*)(d + (size_t)row * QKVW + c4) = round4_f16(v);
}

// V cols of g_QKV -> single fp16 [tok][512]
__global__ __launch_bounds__(256)
void split_v16(const float* __restrict__ QKV, f16* __restrict__ d)
{
    const int i = blockIdx.x * 256 + threadIdx.x;
    if (i >= NTOK * KVCOLS / 4) return;
    const int tok = i / (KVCOLS / 4);
    const int c4  = (i % (KVCOLS / 4)) * 4;
    float4 v = *(const float4*)(QKV + (size_t)tok * QKVW + QCOLS + KVCOLS + c4);
    *(uint2*)(d + (size_t)tok * KVCOLS + c4) = round4_f16(v);
}

// K cols of g_QKV -> single f16 transposed [(b*NKV+hk)*128+d][tok]
__global__ __launch_bounds__(256)
void round_k_trans(const float* __restrict__ QKV, f16* __restrict__ d)
{
    const int blk = blockIdx.x;
    const int bhk = blk >> 7;
    const int dd  = blk & 127;
    const int b   = bhk >> 2, hk = bhk & 3;
    const int t0  = threadIdx.x * 8;
    const float* src = QKV + ((size_t)b * SEQ + t0) * QKVW + QCOLS + hk * HD + dd;
    __align__(16) f16 h8[8];
    #pragma unroll
    for (int j = 0; j < 8; j++) h8[j] = __float2half_rn(src[(size_t)j * QKVW]);
    const size_t o = ((size_t)bhk * HD + dd) * SEQ + t0;
    *(uint4*)&d[o] = *(uint4*)h8;
}

// ============================================================================
// GEMM fp16 1-term: C = A @ B  (QKV projection, O projection)
// ============================================================================
#define ASTR 40
#define BSTR 136
#define G1_A 0
#define G1_B 10240
#define G1_SZ 18944
#define GEMM_1T_SMEM (2 * G1_SZ)

__global__ __launch_bounds__(256, 2)
void gemm_1t_f16(const f16* __restrict__ A_g, const f16* __restrict__ B_g,
                 float* __restrict__ C, int M, int N, int K)
{
    extern __shared__ char smg[];
    const uint32_t sb = smem_u32(smg);

    const int tid  = threadIdx.x;
    const int warp = tid >> 5;
    const int lane = tid & 31;
    const int wm = (warp >> 1) * 32;
    const int wn = (warp & 1) * 64;
    const int bx = blockIdx.x * 128;
    const int by = blockIdx.y * 128;

    float acc[2][8][4];
    #pragma unroll
    for (int mi = 0; mi < 2; mi++)
        #pragma unroll
        for (int ni = 0; ni < 8; ni++)
            #pragma unroll
            for (int e = 0; e < 4; e++) acc[mi][ni][e] = 0.f;

    const int ar = tid >> 1, acb = (tid & 1) * 16;
    const int brw = tid >> 3, bcb = (tid & 7) * 16;

    auto issue_tile = [&](int k0, uint32_t bufb) {
        const f16* a = A_g + (size_t)(by + ar) * K + k0 + acb;
        const uint32_t da = bufb + G1_A + (uint32_t)(ar * 80 + acb * 2);
        cp_async16(da,      a);
        cp_async16(da + 16, a + 8);
        const f16* b = B_g + (size_t)(k0 + brw) * N + bx + bcb;
        const uint32_t db = bufb + G1_B + (uint32_t)(brw * 272 + bcb * 2);
        cp_async16(db,      b);
        cp_async16(db + 16, b + 8);
    };

    const int aoff = (wm + (lane & 15)) * ASTR + ((lane >> 4) << 3);
    const int boff = (lane & 15) * BSTR + wn + ((lane >> 4) << 3);

    const int NIT = K >> 5;
    issue_tile(0, sb);
    CP_COMMIT;

    for (int t = 0; t < NIT; t++) {
        __syncthreads();
        if (t + 1 < NIT) {
            issue_tile((t + 1) * 32, sb + ((t + 1) & 1) * G1_SZ);
            CP_COMMIT;
            CP_WAIT1;
        } else {
            CP_WAIT0;
        }
        __syncthreads();

        const uint32_t bufb = sb + (t & 1) * G1_SZ;
        const uint32_t A_b = bufb + G1_A;
        const uint32_t B_b = bufb + G1_B;

        #pragma unroll
        for (int kk = 0; kk < 32; kk += 16) {
            uint32_t ah[2][4];
            #pragma unroll
            for (int mi = 0; mi < 2; mi++)
                ldmatrix_x4(ah[mi], A_b + (aoff + mi * 16 * ASTR + kk) * 2);
            #pragma unroll
            for (int p = 0; p < 4; p++) {
                uint32_t bh[4];
                const uint32_t off = (boff + kk * BSTR + p * 16) * 2;
                ldmatrix_x4_trans(bh, B_b + off);
                #pragma unroll
                for (int mi = 0; mi < 2; mi++) {
                    mma_f16(acc[mi][2*p],   ah[mi], bh);
                    mma_f16(acc[mi][2*p+1], ah[mi], bh + 2);
                }
            }
        }
    }

    const int g = lane >> 2;
    const int t = lane & 3;
    #pragma unroll
    for (int mi = 0; mi < 2; mi++) {
        #pragma unroll
        for (int ni = 0; ni < 8; ni++) {
            const size_t row0 = (size_t)(by + wm + mi * 16 + g);
            const int col = bx + wn + ni * 8 + 2 * t;
            *(float2*)(C + row0 * N + col)       = make_float2(acc[mi][ni][0], acc[mi][ni][1]);
            *(float2*)(C + (row0 + 8) * N + col) = make_float2(acc[mi][ni][2], acc[mi][ni][3]);
        }
    }
}

// ============================================================================
// RMSNorm + RoPE (Q: fp32(QKV) -> single f16; K: in-place in QKV)
// ============================================================================
__global__ __launch_bounds__(128)
void rmsrope_q_kernel(const float* __restrict__ QKV, const float* __restrict__ w,
                      const int* __restrict__ pos, f16* __restrict__ Qb)
{
    const int blk = blockIdx.x;
    const int token = blk / NH;
    const int h     = blk % NH;
    const float* x = QKV + (size_t)token * QKVW + h * HD;

    const int i = threadIdx.x;
    float v = x[i];

    float ss = v * v;
    #pragma unroll
    for (int m = 16; m; m >>= 1) ss += __shfl_xor_sync(0xffffffffu, ss, m);
    __shared__ float wsum[4];
    if ((i & 31) == 0) wsum[i >> 5] = ss;
    __syncthreads();
    float tot = wsum[0] + wsum[1] + wsum[2] + wsum[3];
    float inv = rsqrtf(tot * (1.0f / 128.0f) + 1e-6f);

    __shared__ float xs[128];
    xs[i] = v * inv * w[i];
    __syncthreads();

    const int p = pos[token];
    const int j = i & 63;
    float invf = (float)pow(1.0e6, -(double)j / 64.0);
    float f = (float)p * invf;
    float c, s;
    sincosf(f, &s, &c);
    float xi = xs[i];
    float partner = (i < 64) ? -xs[i + 64] : xs[i - 64];
    Qb[(size_t)token * QCOLS + h * HD + i] = __float2half_rn(xi * c + partner * s);
}

__global__ __launch_bounds__(128)
void rmsrope_k_kernel(float* __restrict__ QKV, const float* __restrict__ w,
                      const int* __restrict__ pos)
{
    const int blk = blockIdx.x;
    const int token = blk / NKV;
    const int hk    = blk % NKV;
    float* x = QKV + (size_t)token * QKVW + QCOLS + hk * HD;

    const int i = threadIdx.x;
    float v = x[i];

    float ss = v * v;
    #pragma unroll
    for (int m = 16; m; m >>= 1) ss += __shfl_xor_sync(0xffffffffu, ss, m);
    __shared__ float wsum[4];
    if ((i & 31) == 0) wsum[i >> 5] = ss;
    __syncthreads();
    float tot = wsum[0] + wsum[1] + wsum[2] + wsum[3];
    float inv = rsqrtf(tot * (1.0f / 128.0f) + 1e-6f);

    __shared__ float xs[128];
    xs[i] = v * inv * w[i];
    __syncthreads();

    const int p = pos[token];
    const int j = i & 63;
    float invf = (float)pow(1.0e6, -(double)j / 64.0);
    float f = (float)p * invf;
    float c, s;
    sincosf(f, &s, &c);
    float xi = xs[i];
    float partner = (i < 64) ? -xs[i + 64] : xs[i - 64];
    x[i] = xi * c + partner * s;
}

// ============================================================================
// Flash attention: fp16 1-term, Br=128, Bc=128, 256 threads.
// smem: Q 34KB + 2 x (K 34KB + V 34KB) = 170KB.
// ============================================================================
#define QSTR 136
#define KSTR 136
#define VSTR 136
#define AT_Q     0
#define AT_BUF0  (128*QSTR*2)
#define AT_KH    0
#define AT_VH    (128*KSTR*2)
#define AT_BUFSZ (128*KSTR*2 + 128*VSTR*2)
#define ATTN_SMEM (AT_BUF0 + 2*AT_BUFSZ)

__global__ __launch_bounds__(256, 1)
void attn_tc_kernel(const f16* __restrict__ QbG,
                    const f16* __restrict__ KtG, const f16* __restrict__ VG,
                    f16* __restrict__ Ch)
{
    extern __shared__ char sma[];
    const uint32_t sb = smem_u32(sma);

    const int qt = gridDim.x - 1 - blockIdx.x;
    const int h  = blockIdx.y;
    const int b  = blockIdx.z;
    const int hk = h >> 3;

    const int tid  = threadIdx.x;
    const int warp = tid >> 5;
    const int lane = tid & 31;
    const int g  = lane >> 2;
    const int t4 = lane & 3;

    const float scale = 0.08838834764831845f;
    const int ntiles = qt + 1;   // k-tiles of 128

    const f16* kt_g = KtG + (size_t)(b * NKV + hk) * HD * SEQ;
    const f16* v_g  = VG + (size_t)b * SEQ * KVCOLS + hk * HD;

    // loader mapping: 256 threads, each 128 bytes (8 x cp.async16)
    const int kd = tid >> 1, kc0 = (tid & 1) * 64;    // K: d-row (0..127), token base
    const int vc = tid >> 1, vd0 = (tid & 1) * 64;    // V: token-row (0..127), d base

    auto issue_kv = [&](int jt, uint32_t bufb) {
        const f16* kh = kt_g + (size_t)kd * SEQ + jt * 128 + kc0;
        const uint32_t dk = bufb + AT_KH + (uint32_t)(kd * 272 + kc0 * 2);
        #pragma unroll
        for (int u = 0; u < 8; u++)
            cp_async16(dk + u * 16, kh + u * 8);
        const f16* vv = v_g + (size_t)(jt * 128 + vc) * KVCOLS + vd0;
        const uint32_t dv = bufb + AT_VH + (uint32_t)(vc * 272 + vd0 * 2);
        #pragma unroll
        for (int u = 0; u < 8; u++)
            cp_async16(dv + u * 16, vv + u * 8);
    };

    // prefetch Q + KV tile 0
    {
        const int r  = tid >> 1;
        const int c0 = (tid & 1) * 64;
        const f16* q = QbG + ((size_t)(b * SEQ + qt * 128 + r)) * QCOLS + h * HD + c0;
        const uint32_t dq = sb + AT_Q + (uint32_t)(r * QSTR * 2 + c0 * 2);
        #pragma unroll
        for (int u = 0; u < 8; u++)
            cp_async16(dq + u * 16, q + u * 8);
    }
    issue_kv(0, sb + AT_BUF0);
    CP_COMMIT;

    float oacc[16][4];
    #pragma unroll
    for (int nt = 0; nt < 16; nt++)
        #pragma unroll
        for (int e = 0; e < 4; e++) oacc[nt][e] = 0.f;
    float mrow0 = -1e30f, mrow1 = -1e30f, lrow0 = 0.f, lrow1 = 0.f;

    const int qrow0 = qt * 128 + warp * 16 + g;
    const int qrow1 = qrow0 + 8;

    const uint32_t q_base = sb + AT_Q + ((warp*16 + (lane & 15)) * QSTR + ((lane >> 4) << 3)) * 2;
    const uint32_t koffB = ((lane & 15) * KSTR + ((lane >> 4) << 3)) * 2;
    const uint32_t voffB = ((lane & 15) * VSTR + ((lane >> 4) << 3)) * 2;

    for (int jt = 0; jt < ntiles; jt++) {
        __syncthreads();
        if (jt + 1 < ntiles) {
            issue_kv(jt + 1, sb + AT_BUF0 + ((jt + 1) & 1) * AT_BUFSZ);
            CP_COMMIT;
            CP_WAIT1;
        } else {
            CP_WAIT0;
        }
        __syncthreads();

        const uint32_t bufb = sb + AT_BUF0 + (jt & 1) * AT_BUFSZ;
        const uint32_t kt_b = bufb + AT_KH + koffB;
        const uint32_t vh_b = bufb + AT_VH + voffB;
        const bool diag = (jt == qt);   // only diagonal tile needs masking

        // ---- S = Q @ Kt (fp16 1-term, 16 n-tiles) ----
        float sacc[16][4];
        #pragma unroll
        for (int nt = 0; nt < 16; nt++)
            #pragma unroll
            for (int e = 0; e < 4; e++) sacc[nt][e] = 0.f;

        #pragma unroll
        for (int kk = 0; kk < 8; kk++) {
            uint32_t ah[4];
            ldmatrix_x4(ah, q_base + kk * 16 * sizeof(f16));
            #pragma unroll
            for (int p = 0; p < 8; p++) {
                uint32_t bh[4];
                const uint32_t off = (kk * 16 * KSTR + p * 16) * sizeof(f16);
                ldmatrix_x4_trans(bh, kt_b + off);
                mma_f16(sacc[2*p],   ah, bh);
                mma_f16(sacc[2*p+1], ah, bh + 2);
            }
        }

        // ---- apply scale, causal mask (diag tile only), online softmax ----
        float mx0 = -1e30f, mx1 = -1e30f;
        #pragma unroll
        for (int nt = 0; nt < 16; nt++) {
            sacc[nt][0] *= scale;
            sacc[nt][1] *= scale;
            sacc[nt][2] *= scale;
            sacc[nt][3] *= scale;
            if (diag) {
                const int col = jt * 128 + nt * 8 + 2 * t4;
                if (col     > qrow0) sacc[nt][0] = -1e30f;
                if (col + 1 > qrow0) sacc[nt][1] = -1e30f;
                if (col     > qrow1) sacc[nt][2] = -1e30f;
                if (col + 1 > qrow1) sacc[nt][3] = -1e30f;
            }
            mx0 = fmaxf(mx0, fmaxf(sacc[nt][0], sacc[nt][1]));
            mx1 = fmaxf(mx1, fmaxf(sacc[nt][2], sacc[nt][3]));
        }
        mx0 = fmaxf(mx0, __shfl_xor_sync(0xffffffffu, mx0, 1));
        mx0 = fmaxf(mx0, __shfl_xor_sync(0xffffffffu, mx0, 2));
        mx1 = fmaxf(mx1, __shfl_xor_sync(0xffffffffu, mx1, 1));
        mx1 = fmaxf(mx1, __shfl_xor_sync(0xffffffffu, mx1, 2));

        const float mnew0 = fmaxf(mrow0, mx0);
        const float mnew1 = fmaxf(mrow1, mx1);
        const float alpha0 = __expf(mrow0 - mnew0);
        const float alpha1 = __expf(mrow1 - mnew1);

        float rs0 = 0.f, rs1 = 0.f;
        #pragma unroll
        for (int nt = 0; nt < 16; nt++) {
            sacc[nt][0] = __expf(sacc[nt][0] - mnew0);
            sacc[nt][1] = __expf(sacc[nt][1] - mnew0);
            sacc[nt][2] = __expf(sacc[nt][2] - mnew1);
            sacc[nt][3] = __expf(sacc[nt][3] - mnew1);
            rs0 += sacc[nt][0] + sacc[nt][1];
            rs1 += sacc[nt][2] + sacc[nt][3];
        }
        rs0 += __shfl_xor_sync(0xffffffffu, rs0, 1);
        rs0 += __shfl_xor_sync(0xffffffffu, rs0, 2);
        rs1 += __shfl_xor_sync(0xffffffffu, rs1, 1);
        rs1 += __shfl_xor_sync(0xffffffffu, rs1, 2);

        lrow0 = lrow0 * alpha0 + rs0;
        lrow1 = lrow1 * alpha1 + rs1;
        mrow0 = mnew0;
        mrow1 = mnew1;

        #pragma unroll
        for (int nt = 0; nt < 16; nt++) {
            oacc[nt][0] *= alpha0;
            oacc[nt][1] *= alpha0;
            oacc[nt][2] *= alpha1;
            oacc[nt][3] *= alpha1;
        }

        // ---- O += P @ V (single-fp16 P, single V; 8 k16 chunks) ----
        #pragma unroll
        for (int c = 0; c < 8; c++) {
            uint32_t ph[4];
            {
                __half2 p0 = __floats2half2_rn(sacc[2*c][0],   sacc[2*c][1]);
                __half2 p1 = __floats2half2_rn(sacc[2*c][2],   sacc[2*c][3]);
                __half2 p2 = __floats2half2_rn(sacc[2*c+1][0], sacc[2*c+1][1]);
                __half2 p3 = __floats2half2_rn(sacc[2*c+1][2], sacc[2*c+1][3]);
                ph[0] = *(uint32_t*)&p0;
                ph[1] = *(uint32_t*)&p1;
                ph[2] = *(uint32_t*)&p2;
                ph[3] = *(uint32_t*)&p3;
            }
            #pragma unroll
            for (int p = 0; p < 8; p++) {
                uint32_t vh[4];
                const uint32_t off = (c * 16 * VSTR + p * 16) * sizeof(f16);
                ldmatrix_x4_trans(vh, vh_b + off);
                mma_f16(oacc[2*p],   ph, vh);
                mma_f16(oacc[2*p+1], ph, vh + 2);
            }
        }
    }

    // ---- epilogue: write single-fp16 ctx ----
    const float inv0 = 1.0f / lrow0;
    const float inv1 = 1.0f / lrow1;
    const size_t o0 = ((size_t)(b * SEQ + qrow0)) * QCOLS + h * HD;
    const size_t o1 = ((size_t)(b * SEQ + qrow1)) * QCOLS + h * HD;
    #pragma unroll
    for (int nt = 0; nt < 16; nt++) {
        const int col = nt * 8 + 2 * t4;
        __half2 c0 = __floats2half2_rn(oacc[nt][0] * inv0, oacc[nt][1] * inv0);
        __half2 c1 = __floats2half2_rn(oacc[nt][2] * inv1, oacc[nt][3] * inv1);
        *(uint32_t*)(Ch + o0 + col) = *(uint32_t*)&c0;
        *(uint32_t*)(Ch + o1 + col) = *(uint32_t*)&c1;
    }
}

// ============================================================================
// Launch
// ============================================================================
extern "C" void kernel_launch(void* const* d_in, const int* in_sizes, int n_in,
                              void* d_out, int out_size)
{
    const float* hidden = (const float*)d_in[0];
    const int*   pos    = (const int*)  d_in[2];
    const float* Wq     = (const float*)d_in[3];
    const float* Wk     = (const float*)d_in[4];
    const float* Wv     = (const float*)d_in[5];
    const float* Wo     = (const float*)d_in[6];
    const float* qw     = (const float*)d_in[7];
    const float* kw     = (const float*)d_in[8];
    float* out = (float*)d_out;

    float *QKVp;
    f16 *H16, *W16, *Qb, *Ch, *Kt16, *V16;
    cudaGetSymbolAddress((void**)&QKVp, g_QKV);
    cudaGetSymbolAddress((void**)&H16,  g_H16);
    cudaGetSymbolAddress((void**)&W16,  g_W16);
    cudaGetSymbolAddress((void**)&Qb,   g_Qb);
    cudaGetSymbolAddress((void**)&Ch,   g_Ch);
    cudaGetSymbolAddress((void**)&Kt16, g_Kt16);
    cudaGetSymbolAddress((void**)&V16,  g_V16);

    cudaFuncSetAttribute(gemm_1t_f16, cudaFuncAttributeMaxDynamicSharedMemorySize, GEMM_1T_SMEM);
    cudaFuncSetAttribute(attn_tc_kernel, cudaFuncAttributeMaxDynamicSharedMemorySize, ATTN_SMEM);

    // hidden + QKV weights -> single f16
    round_f16_mat<<<(NTOK*HID/4 + 255)/256, 256>>>(hidden, H16, NTOK*HID/4);
    round_qkv_w<<<(HID*QKVW/4 + 255)/256, 256>>>(Wq, Wk, Wv, W16);

    // merged Q|K|V projection (one launch, 1280 CTAs)
    gemm_1t_f16<<<dim3(QKVW/128, NTOK/128), 256, GEMM_1T_SMEM>>>(H16, W16, QKVp, NTOK, QKVW, HID);

    // RMSNorm + RoPE
    rmsrope_q_kernel<<<NTOK * NH, 128>>>(QKVp, qw, pos, Qb);
    rmsrope_k_kernel<<<NTOK * NKV, 128>>>(QKVp, kw, pos);

    // K -> single f16 transposed; V -> single f16
    round_k_trans<<<BATCH*NKV*HD, 256>>>(QKVp, Kt16);
    split_v16<<<(NTOK*KVCOLS/4 + 255)/256, 256>>>(QKVp, V16);

    // flash attention (fp16 1-term, Bc=128)
    attn_tc_kernel<<<dim3(SEQ/128, NH, BATCH), 256, ATTN_SMEM>>>(Qb, Kt16, V16, Ch);

    // output projection (fp16 1-term)
    round_f16_mat<<<(QCOLS*HID/4 + 255)/256, 256>>>(Wo, W16, QCOLS*HID/4);
    gemm_1t_f16<<<dim3(HID/128, NTOK/128), 256, GEMM_1T_SMEM>>>(Ch, W16, out, NTOK, HID, QCOLS);
}

// round 15
// speedup vs baseline: 5.1638x; 3.6906x over previous
#include <cuda_runtime.h>
#include <cuda_fp16.h>
#include <math.h>
#include <stdint.h>

// Problem constants
#define BATCH 2
#define SEQ   2048
#define HID   2048
#define NH    32
#define NKV   4
#define HD    128
#define NTOK  (BATCH*SEQ)          // 4096
#define QCOLS (NH*HD)              // 4096
#define KVCOLS (NKV*HD)            // 512
#define QKVW  (QCOLS + 2*KVCOLS)   // 5120 (Q|K|V concatenated)

typedef __half f16;

// -------- scratch (device globals) --------
__device__ float g_QKV[(size_t)NTOK * QKVW];    // Q|K|V projection out (fp32)
__device__ f16  g_H16[(size_t)NTOK * HID];      // hidden single f16
__device__ f16  g_W16[(size_t)HID * QKVW];      // Wqkv (or Wo) single f16
__device__ f16  g_Qb[(size_t)NTOK * QCOLS];     // Q normed+roped single f16
__device__ f16  g_Ch[(size_t)NTOK * QCOLS];     // ctx single f16
__device__ f16  g_Kt16[(size_t)BATCH*NKV*HD*SEQ]; // K transposed single f16
__device__ f16  g_V16[(size_t)NTOK * KVCOLS];   // V single f16
__device__ float g_invf[64];                    // RoPE inv_freq table

// ============================================================================
// PTX helpers
// ============================================================================
__device__ __forceinline__ uint32_t smem_u32(const void* p) {
    return (uint32_t)__cvta_generic_to_shared(p);
}
__device__ __forceinline__ void ldmatrix_x4(uint32_t* r, uint32_t addr) {
    asm volatile("ldmatrix.sync.aligned.m8n8.x4.shared.b16 {%0,%1,%2,%3}, [%4];"
                 : "=r"(r[0]), "=r"(r[1]), "=r"(r[2]), "=r"(r[3]) : "r"(addr));
}
__device__ __forceinline__ void ldmatrix_x4_trans(uint32_t* r, uint32_t addr) {
    asm volatile("ldmatrix.sync.aligned.m8n8.x4.trans.shared.b16 {%0,%1,%2,%3}, [%4];"
                 : "=r"(r[0]), "=r"(r[1]), "=r"(r[2]), "=r"(r[3]) : "r"(addr));
}
__device__ __forceinline__ void mma_f16(float* d, const uint32_t* a, const uint32_t* b) {
    asm volatile("mma.sync.aligned.m16n8k16.row.col.f32.f16.f16.f32 "
                 "{%0,%1,%2,%3}, {%4,%5,%6,%7}, {%8,%9}, {%0,%1,%2,%3};"
                 : "+f"(d[0]), "+f"(d[1]), "+f"(d[2]), "+f"(d[3])
                 : "r"(a[0]), "r"(a[1]), "r"(a[2]), "r"(a[3]),
                   "r"(b[0]), "r"(b[1]));
}
__device__ __forceinline__ uint2 round4_f16(float4 v) {
    uint2 r;
    __half2 a = __floats2half2_rn(v.x, v.y);
    __half2 b = __floats2half2_rn(v.z, v.w);
    r.x = *(uint32_t*)&a;
    r.y = *(uint32_t*)&b;
    return r;
}
__device__ __forceinline__ void cp_async16(uint32_t dst, const void* src) {
    asm volatile("cp.async.cg.shared.global [%0], [%1], 16;" :: "r"(dst), "l"(src));
}
#define CP_COMMIT asm volatile("cp.async.commit_group;")
#define CP_WAIT0  asm volatile("cp.async.wait_group 0;" ::: "memory")
#define CP_WAIT1  asm volatile("cp.async.wait_group 1;" ::: "memory")

// ============================================================================
// Init: inv_freq table (64 double-pows TOTAL, not 16.7M)
// ============================================================================
__global__ void init_invf_kernel()
{
    const int j = threadIdx.x;   // 0..63
    g_invf[j] = (float)pow(1.0e6, -(double)j / 64.0);
}

// ============================================================================
// Elementwise kernels
// ============================================================================
__global__ __launch_bounds__(256)
void round_f16_mat(const float* __restrict__ src, f16* __restrict__ d, int n4)
{
    const int i = blockIdx.x * 256 + threadIdx.x;
    if (i < n4) ((uint2*)d)[i] = round4_f16(((const float4*)src)[i]);
}

// Wq[K][4096], Wk[K][512], Wv[K][512] -> combined single f16 [K][5120]
__global__ __launch_bounds__(256)
void round_qkv_w(const float* __restrict__ Wq, const float* __restrict__ Wk,
                 const float* __restrict__ Wv, f16* __restrict__ d)
{
    const int i = blockIdx.x * 256 + threadIdx.x;
    if (i >= HID * QKVW / 4) return;
    const int row = i / (QKVW / 4);
    const int c4  = (i % (QKVW / 4)) * 4;
    float4 v;
    if (c4 < QCOLS)               v = *(const float4*)(Wq + (size_t)row * QCOLS + c4);
    else if (c4 < QCOLS + KVCOLS) v = *(const float4*)(Wk + (size_t)row * KVCOLS + (c4 - QCOLS));
    else                          v = *(const float4*)(Wv + (size_t)row * KVCOLS + (c4 - QCOLS - KVCOLS));
    *(uint2*)(d + (size_t)row * QKVW + c4) = round4_f16(v);
}

// V cols of g_QKV -> single fp16 [tok][512]
__global__ __launch_bounds__(256)
void split_v16(const float* __restrict__ QKV, f16* __restrict__ d)
{
    const int i = blockIdx.x * 256 + threadIdx.x;
    if (i >= NTOK * KVCOLS / 4) return;
    const int tok = i / (KVCOLS / 4);
    const int c4  = (i % (KVCOLS / 4)) * 4;
    float4 v = *(const float4*)(QKV + (size_t)tok * QKVW + QCOLS + KVCOLS + c4);
    *(uint2*)(d + (size_t)tok * KVCOLS + c4) = round4_f16(v);
}

// ============================================================================
// RMSNorm + RoPE, warp-per-head. Lane l holds elems d = 4l..4l+3.
// Partner (d +/- 64) lives in lane l^16, same component.
// ============================================================================
__device__ __forceinline__ float4 rmsrope_warp(float4 v, float4 wv, int p, int lane)
{
    float ss = v.x*v.x + v.y*v.y + v.z*v.z + v.w*v.w;
    #pragma unroll
    for (int m = 16; m; m >>= 1) ss += __shfl_xor_sync(0xffffffffu, ss, m);
    const float inv = rsqrtf(ss * (1.0f / 128.0f) + 1e-6f);

    float4 xs;
    xs.x = v.x * inv * wv.x;
    xs.y = v.y * inv * wv.y;
    xs.z = v.z * inv * wv.z;
    xs.w = v.w * inv * wv.w;

    float4 pr;
    pr.x = __shfl_xor_sync(0xffffffffu, xs.x, 16);
    pr.y = __shfl_xor_sync(0xffffffffu, xs.y, 16);
    pr.z = __shfl_xor_sync(0xffffffffu, xs.z, 16);
    pr.w = __shfl_xor_sync(0xffffffffu, xs.w, 16);

    const int d0 = lane * 4;
    const float sign = (d0 < 64) ? -1.0f : 1.0f;
    const int j0 = d0 & 63;
    float4 out;
    {
        float c, s;
        sincosf((float)p * g_invf[j0 + 0], &s, &c);
        out.x = xs.x * c + sign * pr.x * s;
        sincosf((float)p * g_invf[j0 + 1], &s, &c);
        out.y = xs.y * c + sign * pr.y * s;
        sincosf((float)p * g_invf[j0 + 2], &s, &c);
        out.z = xs.z * c + sign * pr.z * s;
        sincosf((float)p * g_invf[j0 + 3], &s, &c);
        out.w = xs.w * c + sign * pr.w * s;
    }
    return out;
}

// Q: one warp per (token, head); writes single f16 Qb.
__global__ __launch_bounds__(256)
void rmsrope_q_kernel(const float* __restrict__ QKV, const float* __restrict__ w,
                      const int* __restrict__ pos, f16* __restrict__ Qb)
{
    const int gw = blockIdx.x * 8 + (threadIdx.x >> 5);
    const int lane = threadIdx.x & 31;
    const int token = gw >> 5;          // / NH
    const int h     = gw & 31;          // % NH
    const int d0 = lane * 4;

    float4 v  = *(const float4*)(QKV + (size_t)token * QKVW + h * HD + d0);
    float4 wv = *(const float4*)(w + d0);
    float4 out = rmsrope_warp(v, wv, pos[token], lane);
    *(uint2*)(Qb + (size_t)token * QCOLS + h * HD + d0) = round4_f16(out);
}

// K: one warp per (token, hk); writes TRANSPOSED f16 Kt16 directly.
__global__ __launch_bounds__(256)
void rmsrope_k_kernel(const float* __restrict__ QKV, const float* __restrict__ w,
                      const int* __restrict__ pos, f16* __restrict__ Kt)
{
    const int gw = blockIdx.x * 8 + (threadIdx.x >> 5);
    const int lane = threadIdx.x & 31;
    const int token = gw >> 2;          // / NKV
    const int hk    = gw & 3;           // % NKV
    const int d0 = lane * 4;

    float4 v  = *(const float4*)(QKV + (size_t)token * QKVW + QCOLS + hk * HD + d0);
    float4 wv = *(const float4*)(w + d0);
    float4 out = rmsrope_warp(v, wv, pos[token], lane);

    const int b  = token >> 11;         // / SEQ
    const int ts = token & (SEQ - 1);
    f16* dst = Kt + ((size_t)(b * NKV + hk) * HD + d0) * SEQ + ts;
    dst[0 * SEQ] = __float2half_rn(out.x);
    dst[1 * SEQ] = __float2half_rn(out.y);
    dst[2 * SEQ] = __float2half_rn(out.z);
    dst[3 * SEQ] = __float2half_rn(out.w);
}

// ============================================================================
// GEMM fp16 1-term: C = A @ B  (QKV projection, O projection)
// ============================================================================
#define ASTR 40
#define BSTR 136
#define G1_A 0
#define G1_B 10240
#define G1_SZ 18944
#define GEMM_1T_SMEM (2 * G1_SZ)

__global__ __launch_bounds__(256, 2)
void gemm_1t_f16(const f16* __restrict__ A_g, const f16* __restrict__ B_g,
                 float* __restrict__ C, int M, int N, int K)
{
    extern __shared__ char smg[];
    const uint32_t sb = smem_u32(smg);

    const int tid  = threadIdx.x;
    const int warp = tid >> 5;
    const int lane = tid & 31;
    const int wm = (warp >> 1) * 32;
    const int wn = (warp & 1) * 64;
    const int bx = blockIdx.x * 128;
    const int by = blockIdx.y * 128;

    float acc[2][8][4];
    #pragma unroll
    for (int mi = 0; mi < 2; mi++)
        #pragma unroll
        for (int ni = 0; ni < 8; ni++)
            #pragma unroll
            for (int e = 0; e < 4; e++) acc[mi][ni][e] = 0.f;

    const int ar = tid >> 1, acb = (tid & 1) * 16;
    const int brw = tid >> 3, bcb = (tid & 7) * 16;

    auto issue_tile = [&](int k0, uint32_t bufb) {
        const f16* a = A_g + (size_t)(by + ar) * K + k0 + acb;
        const uint32_t da = bufb + G1_A + (uint32_t)(ar * 80 + acb * 2);
        cp_async16(da,      a);
        cp_async16(da + 16, a + 8);
        const f16* b = B_g + (size_t)(k0 + brw) * N + bx + bcb;
        const uint32_t db = bufb + G1_B + (uint32_t)(brw * 272 + bcb * 2);
        cp_async16(db,      b);
        cp_async16(db + 16, b + 8);
    };

    const int aoff = (wm + (lane & 15)) * ASTR + ((lane >> 4) << 3);
    const int boff = (lane & 15) * BSTR + wn + ((lane >> 4) << 3);

    const int NIT = K >> 5;
    issue_tile(0, sb);
    CP_COMMIT;

    for (int t = 0; t < NIT; t++) {
        __syncthreads();
        if (t + 1 < NIT) {
            issue_tile((t + 1) * 32, sb + ((t + 1) & 1) * G1_SZ);
            CP_COMMIT;
            CP_WAIT1;
        } else {
            CP_WAIT0;
        }
        __syncthreads();

        const uint32_t bufb = sb + (t & 1) * G1_SZ;
        const uint32_t A_b = bufb + G1_A;
        const uint32_t B_b = bufb + G1_B;

        #pragma unroll
        for (int kk = 0; kk < 32; kk += 16) {
            uint32_t ah[2][4];
            #pragma unroll
            for (int mi = 0; mi < 2; mi++)
                ldmatrix_x4(ah[mi], A_b + (aoff + mi * 16 * ASTR + kk) * 2);
            #pragma unroll
            for (int p = 0; p < 4; p++) {
                uint32_t bh[4];
                const uint32_t off = (boff + kk * BSTR + p * 16) * 2;
                ldmatrix_x4_trans(bh, B_b + off);
                #pragma unroll
                for (int mi = 0; mi < 2; mi++) {
                    mma_f16(acc[mi][2*p],   ah[mi], bh);
                    mma_f16(acc[mi][2*p+1], ah[mi], bh + 2);
                }
            }
        }
    }

    const int g = lane >> 2;
    const int t = lane & 3;
    #pragma unroll
    for (int mi = 0; mi < 2; mi++) {
        #pragma unroll
        for (int ni = 0; ni < 8; ni++) {
            const size_t row0 = (size_t)(by + wm + mi * 16 + g);
            const int col = bx + wn + ni * 8 + 2 * t;
            *(float2*)(C + row0 * N + col)       = make_float2(acc[mi][ni][0], acc[mi][ni][1]);
            *(float2*)(C + (row0 + 8) * N + col) = make_float2(acc[mi][ni][2], acc[mi][ni][3]);
        }
    }
}

// ============================================================================
// Flash attention: fp16 1-term, Br=128, Bc=128, 256 threads.
// ============================================================================
#define QSTR 136
#define KSTR 136
#define VSTR 136
#define AT_Q     0
#define AT_BUF0  (128*QSTR*2)
#define AT_KH    0
#define AT_VH    (128*KSTR*2)
#define AT_BUFSZ (128*KSTR*2 + 128*VSTR*2)
#define ATTN_SMEM (AT_BUF0 + 2*AT_BUFSZ)

__global__ __launch_bounds__(256, 1)
void attn_tc_kernel(const f16* __restrict__ QbG,
                    const f16* __restrict__ KtG, const f16* __restrict__ VG,
                    f16* __restrict__ Ch)
{
    extern __shared__ char sma[];
    const uint32_t sb = smem_u32(sma);

    const int qt = gridDim.x - 1 - blockIdx.x;
    const int h  = blockIdx.y;
    const int b  = blockIdx.z;
    const int hk = h >> 3;

    const int tid  = threadIdx.x;
    const int warp = tid >> 5;
    const int lane = tid & 31;
    const int g  = lane >> 2;
    const int t4 = lane & 3;

    const float scale = 0.08838834764831845f;
    const int ntiles = qt + 1;

    const f16* kt_g = KtG + (size_t)(b * NKV + hk) * HD * SEQ;
    const f16* v_g  = VG + (size_t)b * SEQ * KVCOLS + hk * HD;

    const int kd = tid >> 1, kc0 = (tid & 1) * 64;
    const int vc = tid >> 1, vd0 = (tid & 1) * 64;

    auto issue_kv = [&](int jt, uint32_t bufb) {
        const f16* kh = kt_g + (size_t)kd * SEQ + jt * 128 + kc0;
        const uint32_t dk = bufb + AT_KH + (uint32_t)(kd * 272 + kc0 * 2);
        #pragma unroll
        for (int u = 0; u < 8; u++)
            cp_async16(dk + u * 16, kh + u * 8);
        const f16* vv = v_g + (size_t)(jt * 128 + vc) * KVCOLS + vd0;
        const uint32_t dv = bufb + AT_VH + (uint32_t)(vc * 272 + vd0 * 2);
        #pragma unroll
        for (int u = 0; u < 8; u++)
            cp_async16(dv + u * 16, vv + u * 8);
    };

    {
        const int r  = tid >> 1;
        const int c0 = (tid & 1) * 64;
        const f16* q = QbG + ((size_t)(b * SEQ + qt * 128 + r)) * QCOLS + h * HD + c0;
        const uint32_t dq = sb + AT_Q + (uint32_t)(r * QSTR * 2 + c0 * 2);
        #pragma unroll
        for (int u = 0; u < 8; u++)
            cp_async16(dq + u * 16, q + u * 8);
    }
    issue_kv(0, sb + AT_BUF0);
    CP_COMMIT;

    float oacc[16][4];
    #pragma unroll
    for (int nt = 0; nt < 16; nt++)
        #pragma unroll
        for (int e = 0; e < 4; e++) oacc[nt][e] = 0.f;
    float mrow0 = -1e30f, mrow1 = -1e30f, lrow0 = 0.f, lrow1 = 0.f;

    const int qrow0 = qt * 128 + warp * 16 + g;
    const int qrow1 = qrow0 + 8;

    const uint32_t q_base = sb + AT_Q + ((warp*16 + (lane & 15)) * QSTR + ((lane >> 4) << 3)) * 2;
    const uint32_t koffB = ((lane & 15) * KSTR + ((lane >> 4) << 3)) * 2;
    const uint32_t voffB = ((lane & 15) * VSTR + ((lane >> 4) << 3)) * 2;

    for (int jt = 0; jt < ntiles; jt++) {
        __syncthreads();
        if (jt + 1 < ntiles) {
            issue_kv(jt + 1, sb + AT_BUF0 + ((jt + 1) & 1) * AT_BUFSZ);
            CP_COMMIT;
            CP_WAIT1;
        } else {
            CP_WAIT0;
        }
        __syncthreads();

        const uint32_t bufb = sb + AT_BUF0 + (jt & 1) * AT_BUFSZ;
        const uint32_t kt_b = bufb + AT_KH + koffB;
        const uint32_t vh_b = bufb + AT_VH + voffB;
        const bool diag = (jt == qt);

        // ---- S = Q @ Kt ----
        float sacc[16][4];
        #pragma unroll
        for (int nt = 0; nt < 16; nt++)
            #pragma unroll
            for (int e = 0; e < 4; e++) sacc[nt][e] = 0.f;

        #pragma unroll
        for (int kk = 0; kk < 8; kk++) {
            uint32_t ah[4];
            ldmatrix_x4(ah, q_base + kk * 16 * sizeof(f16));
            #pragma unroll
            for (int p = 0; p < 8; p++) {
                uint32_t bh[4];
                const uint32_t off = (kk * 16 * KSTR + p * 16) * sizeof(f16);
                ldmatrix_x4_trans(bh, kt_b + off);
                mma_f16(sacc[2*p],   ah, bh);
                mma_f16(sacc[2*p+1], ah, bh + 2);
            }
        }

        // ---- scale, causal mask (diag only), online softmax ----
        float mx0 = -1e30f, mx1 = -1e30f;
        #pragma unroll
        for (int nt = 0; nt < 16; nt++) {
            sacc[nt][0] *= scale;
            sacc[nt][1] *= scale;
            sacc[nt][2] *= scale;
            sacc[nt][3] *= scale;
            if (diag) {
                const int col = jt * 128 + nt * 8 + 2 * t4;
                if (col     > qrow0) sacc[nt][0] = -1e30f;
                if (col + 1 > qrow0) sacc[nt][1] = -1e30f;
                if (col     > qrow1) sacc[nt][2] = -1e30f;
                if (col + 1 > qrow1) sacc[nt][3] = -1e30f;
            }
            mx0 = fmaxf(mx0, fmaxf(sacc[nt][0], sacc[nt][1]));
            mx1 = fmaxf(mx1, fmaxf(sacc[nt][2], sacc[nt][3]));
        }
        mx0 = fmaxf(mx0, __shfl_xor_sync(0xffffffffu, mx0, 1));
        mx0 = fmaxf(mx0, __shfl_xor_sync(0xffffffffu, mx0, 2));
        mx1 = fmaxf(mx1, __shfl_xor_sync(0xffffffffu, mx1, 1));
        mx1 = fmaxf(mx1, __shfl_xor_sync(0xffffffffu, mx1, 2));

        const float mnew0 = fmaxf(mrow0, mx0);
        const float mnew1 = fmaxf(mrow1, mx1);
        const float alpha0 = __expf(mrow0 - mnew0);
        const float alpha1 = __expf(mrow1 - mnew1);

        float rs0 = 0.f, rs1 = 0.f;
        #pragma unroll
        for (int nt = 0; nt < 16; nt++) {
            sacc[nt][0] = __expf(sacc[nt][0] - mnew0);
            sacc[nt][1] = __expf(sacc[nt][1] - mnew0);
            sacc[nt][2] = __expf(sacc[nt][2] - mnew1);
            sacc[nt][3] = __expf(sacc[nt][3] - mnew1);
            rs0 += sacc[nt][0] + sacc[nt][1];
            rs1 += sacc[nt][2] + sacc[nt][3];
        }
        rs0 += __shfl_xor_sync(0xffffffffu, rs0, 1);
        rs0 += __shfl_xor_sync(0xffffffffu, rs0, 2);
        rs1 += __shfl_xor_sync(0xffffffffu, rs1, 1);
        rs1 += __shfl_xor_sync(0xffffffffu, rs1, 2);

        lrow0 = lrow0 * alpha0 + rs0;
        lrow1 = lrow1 * alpha1 + rs1;
        mrow0 = mnew0;
        mrow1 = mnew1;

        #pragma unroll
        for (int nt = 0; nt < 16; nt++) {
            oacc[nt][0] *= alpha0;
            oacc[nt][1] *= alpha0;
            oacc[nt][2] *= alpha1;
            oacc[nt][3] *= alpha1;
        }

        // ---- O += P @ V ----
        #pragma unroll
        for (int c = 0; c < 8; c++) {
            uint32_t ph[4];
            {
                __half2 p0 = __floats2half2_rn(sacc[2*c][0],   sacc[2*c][1]);
                __half2 p1 = __floats2half2_rn(sacc[2*c][2],   sacc[2*c][3]);
                __half2 p2 = __floats2half2_rn(sacc[2*c+1][0], sacc[2*c+1][1]);
                __half2 p3 = __floats2half2_rn(sacc[2*c+1][2], sacc[2*c+1][3]);
                ph[0] = *(uint32_t*)&p0;
                ph[1] = *(uint32_t*)&p1;
                ph[2] = *(uint32_t*)&p2;
                ph[3] = *(uint32_t*)&p3;
            }
            #pragma unroll
            for (int p = 0; p < 8; p++) {
                uint32_t vh[4];
                const uint32_t off = (c * 16 * VSTR + p * 16) * sizeof(f16);
                ldmatrix_x4_trans(vh, vh_b + off);
                mma_f16(oacc[2*p],   ph, vh);
                mma_f16(oacc[2*p+1], ph, vh + 2);
            }
        }
    }

    // ---- epilogue ----
    const float inv0 = 1.0f / lrow0;
    const float inv1 = 1.0f / lrow1;
    const size_t o0 = ((size_t)(b * SEQ + qrow0)) * QCOLS + h * HD;
    const size_t o1 = ((size_t)(b * SEQ + qrow1)) * QCOLS + h * HD;
    #pragma unroll
    for (int nt = 0; nt < 16; nt++) {
        const int col = nt * 8 + 2 * t4;
        __half2 c0 = __floats2half2_rn(oacc[nt][0] * inv0, oacc[nt][1] * inv0);
        __half2 c1 = __floats2half2_rn(oacc[nt][2] * inv1, oacc[nt][3] * inv1);
        *(uint32_t*)(Ch + o0 + col) = *(uint32_t*)&c0;
        *(uint32_t*)(Ch + o1 + col) = *(uint32_t*)&c1;
    }
}

// ============================================================================
// Launch
// ============================================================================
extern "C" void kernel_launch(void* const* d_in, const int* in_sizes, int n_in,
                              void* d_out, int out_size)
{
    const float* hidden = (const float*)d_in[0];
    const int*   pos    = (const int*)  d_in[2];
    const float* Wq     = (const float*)d_in[3];
    const float* Wk     = (const float*)d_in[4];
    const float* Wv     = (const float*)d_in[5];
    const float* Wo     = (const float*)d_in[6];
    const float* qw     = (const float*)d_in[7];
    const float* kw     = (const float*)d_in[8];
    float* out = (float*)d_out;

    float *QKVp;
    f16 *H16, *W16, *Qb, *Ch, *Kt16, *V16;
    cudaGetSymbolAddress((void**)&QKVp, g_QKV);
    cudaGetSymbolAddress((void**)&H16,  g_H16);
    cudaGetSymbolAddress((void**)&W16,  g_W16);
    cudaGetSymbolAddress((void**)&Qb,   g_Qb);
    cudaGetSymbolAddress((void**)&Ch,   g_Ch);
    cudaGetSymbolAddress((void**)&Kt16, g_Kt16);
    cudaGetSymbolAddress((void**)&V16,  g_V16);

    cudaFuncSetAttribute(gemm_1t_f16, cudaFuncAttributeMaxDynamicSharedMemorySize, GEMM_1T_SMEM);
    cudaFuncSetAttribute(attn_tc_kernel, cudaFuncAttributeMaxDynamicSharedMemorySize, ATTN_SMEM);

    // inv_freq table (64 double-pows total)
    init_invf_kernel<<<1, 64>>>();

    // hidden + QKV weights -> single f16
    round_f16_mat<<<(NTOK*HID/4 + 255)/256, 256>>>(hidden, H16, NTOK*HID/4);
    round_qkv_w<<<(HID*QKVW/4 + 255)/256, 256>>>(Wq, Wk, Wv, W16);

    // merged Q|K|V projection
    gemm_1t_f16<<<dim3(QKVW/128, NTOK/128), 256, GEMM_1T_SMEM>>>(H16, W16, QKVp, NTOK, QKVW, HID);

    // RMSNorm + RoPE (warp-per-head; K writes transposed f16 directly)
    rmsrope_q_kernel<<<NTOK * NH / 8, 256>>>(QKVp, qw, pos, Qb);
    rmsrope_k_kernel<<<NTOK * NKV / 8, 256>>>(QKVp, kw, pos, Kt16);

    // V -> single f16
    split_v16<<<(NTOK*KVCOLS/4 + 255)/256, 256>>>(QKVp, V16);

    // flash attention
    attn_tc_kernel<<<dim3(SEQ/128, NH, BATCH), 256, ATTN_SMEM>>>(Qb, Kt16, V16, Ch);

    // output projection
    round_f16_mat<<<(QCOLS*HID/4 + 255)/256, 256>>>(Wo, W16, QCOLS*HID/4);
    gemm_1t_f16<<<dim3(HID/128, NTOK/128), 256, GEMM_1T_SMEM>>>(Ch, W16, out, NTOK, HID, QCOLS);
}

// round 16
// speedup vs baseline: 5.3480x; 1.0357x over previous
#include <cuda_runtime.h>
#include <cuda_fp16.h>
#include <math.h>
#include <stdint.h>

// Problem constants
#define BATCH 2
#define SEQ   2048
#define HID   2048
#define NH    32
#define NKV   4
#define HD    128
#define NTOK  (BATCH*SEQ)          // 4096
#define QCOLS (NH*HD)              // 4096
#define KVCOLS (NKV*HD)            // 512
#define QKVW  (QCOLS + 2*KVCOLS)   // 5120 (Q|K|V concatenated)

typedef __half f16;

// -------- scratch (device globals) --------
__device__ float g_QKV[(size_t)NTOK * QKVW];
__device__ f16  g_H16[(size_t)NTOK * HID];
__device__ f16  g_W16[(size_t)HID * QKVW];
__device__ f16  g_Qb[(size_t)NTOK * QCOLS];
__device__ f16  g_Ch[(size_t)NTOK * QCOLS];
__device__ f16  g_Kt16[(size_t)BATCH*NKV*HD*SEQ];
__device__ f16  g_V16[(size_t)NTOK * KVCOLS];
__device__ float g_invf[64];

// ============================================================================
// PTX helpers
// ============================================================================
__device__ __forceinline__ uint32_t smem_u32(const void* p) {
    return (uint32_t)__cvta_generic_to_shared(p);
}
__device__ __forceinline__ void ldmatrix_x4(uint32_t* r, uint32_t addr) {
    asm volatile("ldmatrix.sync.aligned.m8n8.x4.shared.b16 {%0,%1,%2,%3}, [%4];"
                 : "=r"(r[0]), "=r"(r[1]), "=r"(r[2]), "=r"(r[3]) : "r"(addr));
}
__device__ __forceinline__ void ldmatrix_x4_trans(uint32_t* r, uint32_t addr) {
    asm volatile("ldmatrix.sync.aligned.m8n8.x4.trans.shared.b16 {%0,%1,%2,%3}, [%4];"
                 : "=r"(r[0]), "=r"(r[1]), "=r"(r[2]), "=r"(r[3]) : "r"(addr));
}
__device__ __forceinline__ void mma_f16(float* d, const uint32_t* a, const uint32_t* b) {
    asm volatile("mma.sync.aligned.m16n8k16.row.col.f32.f16.f16.f32 "
                 "{%0,%1,%2,%3}, {%4,%5,%6,%7}, {%8,%9}, {%0,%1,%2,%3};"
                 : "+f"(d[0]), "+f"(d[1]), "+f"(d[2]), "+f"(d[3])
                 : "r"(a[0]), "r"(a[1]), "r"(a[2]), "r"(a[3]),
                   "r"(b[0]), "r"(b[1]));
}
__device__ __forceinline__ uint2 round4_f16(float4 v) {
    uint2 r;
    __half2 a = __floats2half2_rn(v.x, v.y);
    __half2 b = __floats2half2_rn(v.z, v.w);
    r.x = *(uint32_t*)&a;
    r.y = *(uint32_t*)&b;
    return r;
}
__device__ __forceinline__ void cp_async16(uint32_t dst, const void* src) {
    asm volatile("cp.async.cg.shared.global [%0], [%1], 16;" :: "r"(dst), "l"(src));
}
#define CP_COMMIT asm volatile("cp.async.commit_group;")
#define CP_WAIT0  asm volatile("cp.async.wait_group 0;" ::: "memory")
#define CP_WAIT1  asm volatile("cp.async.wait_group 1;" ::: "memory")

// ============================================================================
// Init: inv_freq table
// ============================================================================
__global__ void init_invf_kernel()
{
    const int j = threadIdx.x;
    g_invf[j] = (float)pow(1.0e6, -(double)j / 64.0);
}

// ============================================================================
// Elementwise kernels
// ============================================================================
__global__ __launch_bounds__(256)
void round_f16_mat(const float* __restrict__ src, f16* __restrict__ d, int n4)
{
    const int i = blockIdx.x * 256 + threadIdx.x;
    if (i < n4) ((uint2*)d)[i] = round4_f16(((const float4*)src)[i]);
}

__global__ __launch_bounds__(256)
void round_qkv_w(const float* __restrict__ Wq, const float* __restrict__ Wk,
                 const float* __restrict__ Wv, f16* __restrict__ d)
{
    const int i = blockIdx.x * 256 + threadIdx.x;
    if (i >= HID * QKVW / 4) return;
    const int row = i / (QKVW / 4);
    const int c4  = (i % (QKVW / 4)) * 4;
    float4 v;
    if (c4 < QCOLS)               v = *(const float4*)(Wq + (size_t)row * QCOLS + c4);
    else if (c4 < QCOLS + KVCOLS) v = *(const float4*)(Wk + (size_t)row * KVCOLS + (c4 - QCOLS));
    else                          v = *(const float4*)(Wv + (size_t)row * KVCOLS + (c4 - QCOLS - KVCOLS));
    *(uint2*)(d + (size_t)row * QKVW + c4) = round4_f16(v);
}

__global__ __launch_bounds__(256)
void split_v16(const float* __restrict__ QKV, f16* __restrict__ d)
{
    const int i = blockIdx.x * 256 + threadIdx.x;
    if (i >= NTOK * KVCOLS / 4) return;
    const int tok = i / (KVCOLS / 4);
    const int c4  = (i % (KVCOLS / 4)) * 4;
    float4 v = *(const float4*)(QKV + (size_t)tok * QKVW + QCOLS + KVCOLS + c4);
    *(uint2*)(d + (size_t)tok * KVCOLS + c4) = round4_f16(v);
}

// ============================================================================
// RMSNorm + RoPE, warp-per-head.
// ============================================================================
__device__ __forceinline__ float4 rmsrope_warp(float4 v, float4 wv, int p, int lane)
{
    float ss = v.x*v.x + v.y*v.y + v.z*v.z + v.w*v.w;
    #pragma unroll
    for (int m = 16; m; m >>= 1) ss += __shfl_xor_sync(0xffffffffu, ss, m);
    const float inv = rsqrtf(ss * (1.0f / 128.0f) + 1e-6f);

    float4 xs;
    xs.x = v.x * inv * wv.x;
    xs.y = v.y * inv * wv.y;
    xs.z = v.z * inv * wv.z;
    xs.w = v.w * inv * wv.w;

    float4 pr;
    pr.x = __shfl_xor_sync(0xffffffffu, xs.x, 16);
    pr.y = __shfl_xor_sync(0xffffffffu, xs.y, 16);
    pr.z = __shfl_xor_sync(0xffffffffu, xs.z, 16);
    pr.w = __shfl_xor_sync(0xffffffffu, xs.w, 16);

    const int d0 = lane * 4;
    const float sign = (d0 < 64) ? -1.0f : 1.0f;
    const int j0 = d0 & 63;
    float4 out;
    {
        float c, s;
        sincosf((float)p * g_invf[j0 + 0], &s, &c);
        out.x = xs.x * c + sign * pr.x * s;
        sincosf((float)p * g_invf[j0 + 1], &s, &c);
        out.y = xs.y * c + sign * pr.y * s;
        sincosf((float)p * g_invf[j0 + 2], &s, &c);
        out.z = xs.z * c + sign * pr.z * s;
        sincosf((float)p * g_invf[j0 + 3], &s, &c);
        out.w = xs.w * c + sign * pr.w * s;
    }
    return out;
}

__global__ __launch_bounds__(256)
void rmsrope_q_kernel(const float* __restrict__ QKV, const float* __restrict__ w,
                      const int* __restrict__ pos, f16* __restrict__ Qb)
{
    const int gw = blockIdx.x * 8 + (threadIdx.x >> 5);
    const int lane = threadIdx.x & 31;
    const int token = gw >> 5;
    const int h     = gw & 31;
    const int d0 = lane * 4;

    float4 v  = *(const float4*)(QKV + (size_t)token * QKVW + h * HD + d0);
    float4 wv = *(const float4*)(w + d0);
    float4 out = rmsrope_warp(v, wv, pos[token], lane);
    *(uint2*)(Qb + (size_t)token * QCOLS + h * HD + d0) = round4_f16(out);
}

__global__ __launch_bounds__(256)
void rmsrope_k_kernel(const float* __restrict__ QKV, const float* __restrict__ w,
                      const int* __restrict__ pos, f16* __restrict__ Kt)
{
    const int gw = blockIdx.x * 8 + (threadIdx.x >> 5);
    const int lane = threadIdx.x & 31;
    const int token = gw >> 2;
    const int hk    = gw & 3;
    const int d0 = lane * 4;

    float4 v  = *(const float4*)(QKV + (size_t)token * QKVW + QCOLS + hk * HD + d0);
    float4 wv = *(const float4*)(w + d0);
    float4 out = rmsrope_warp(v, wv, pos[token], lane);

    const int b  = token >> 11;
    const int ts = token & (SEQ - 1);
    f16* dst = Kt + ((size_t)(b * NKV + hk) * HD + d0) * SEQ + ts;
    dst[0 * SEQ] = __float2half_rn(out.x);
    dst[1 * SEQ] = __float2half_rn(out.y);
    dst[2 * SEQ] = __float2half_rn(out.z);
    dst[3 * SEQ] = __float2half_rn(out.w);
}

// ============================================================================
// GEMM fp16 1-term, TRIPLE-buffered, 1 barrier per k-tile.
// ============================================================================
#define ASTR 40
#define BSTR 136
#define G1_A 0
#define G1_B 10240
#define G1_SZ 18944
#define GEMM_1T_SMEM (3 * G1_SZ)

__global__ __launch_bounds__(256, 2)
void gemm_1t_f16(const f16* __restrict__ A_g, const f16* __restrict__ B_g,
                 float* __restrict__ C, int M, int N, int K)
{
    extern __shared__ char smg[];
    const uint32_t sb = smem_u32(smg);

    const int tid  = threadIdx.x;
    const int warp = tid >> 5;
    const int lane = tid & 31;
    const int wm = (warp >> 1) * 32;
    const int wn = (warp & 1) * 64;
    const int bx = blockIdx.x * 128;
    const int by = blockIdx.y * 128;

    float acc[2][8][4];
    #pragma unroll
    for (int mi = 0; mi < 2; mi++)
        #pragma unroll
        for (int ni = 0; ni < 8; ni++)
            #pragma unroll
            for (int e = 0; e < 4; e++) acc[mi][ni][e] = 0.f;

    const int ar = tid >> 1, acb = (tid & 1) * 16;
    const int brw = tid >> 3, bcb = (tid & 7) * 16;

    auto issue_tile = [&](int k0, uint32_t bufb) {
        const f16* a = A_g + (size_t)(by + ar) * K + k0 + acb;
        const uint32_t da = bufb + G1_A + (uint32_t)(ar * 80 + acb * 2);
        cp_async16(da,      a);
        cp_async16(da + 16, a + 8);
        const f16* b = B_g + (size_t)(k0 + brw) * N + bx + bcb;
        const uint32_t db = bufb + G1_B + (uint32_t)(brw * 272 + bcb * 2);
        cp_async16(db,      b);
        cp_async16(db + 16, b + 8);
    };

    const int aoff = (wm + (lane & 15)) * ASTR + ((lane >> 4) << 3);
    const int boff = (lane & 15) * BSTR + wn + ((lane >> 4) << 3);

    const int NIT = K >> 5;   // >= 64 for all our shapes

    // prologue: 2 tiles in flight
    issue_tile(0, sb);
    CP_COMMIT;
    issue_tile(32, sb + G1_SZ);
    CP_COMMIT;

    int bufidx = 0;
    for (int t = 0; t < NIT; t++) {
        // tile t complete (t+1 may still be in flight)
        if (t + 1 < NIT) { CP_WAIT1; } else { CP_WAIT0; }
        __syncthreads();   // tile t visible to all; compute t-1 done everywhere

        // issue tile t+2 into the buffer freed by compute t-1
        if (t + 2 < NIT) {
            int nb = bufidx + 2;
            if (nb >= 3) nb -= 3;
            issue_tile((t + 2) * 32, sb + nb * G1_SZ);
            CP_COMMIT;
        }

        const uint32_t bufb = sb + bufidx * G1_SZ;
        const uint32_t A_b = bufb + G1_A;
        const uint32_t B_b = bufb + G1_B;

        #pragma unroll
        for (int kk = 0; kk < 32; kk += 16) {
            uint32_t ah[2][4];
            #pragma unroll
            for (int mi = 0; mi < 2; mi++)
                ldmatrix_x4(ah[mi], A_b + (aoff + mi * 16 * ASTR + kk) * 2);
            #pragma unroll
            for (int p = 0; p < 4; p++) {
                uint32_t bh[4];
                const uint32_t off = (boff + kk * BSTR + p * 16) * 2;
                ldmatrix_x4_trans(bh, B_b + off);
                #pragma unroll
                for (int mi = 0; mi < 2; mi++) {
                    mma_f16(acc[mi][2*p],   ah[mi], bh);
                    mma_f16(acc[mi][2*p+1], ah[mi], bh + 2);
                }
            }
        }

        if (++bufidx == 3) bufidx = 0;
    }

    const int g = lane >> 2;
    const int t = lane & 3;
    #pragma unroll
    for (int mi = 0; mi < 2; mi++) {
        #pragma unroll
        for (int ni = 0; ni < 8; ni++) {
            const size_t row0 = (size_t)(by + wm + mi * 16 + g);
            const int col = bx + wn + ni * 8 + 2 * t;
            *(float2*)(C + row0 * N + col)       = make_float2(acc[mi][ni][0], acc[mi][ni][1]);
            *(float2*)(C + (row0 + 8) * N + col) = make_float2(acc[mi][ni][2], acc[mi][ni][3]);
        }
    }
}

// ============================================================================
// Flash attention: fp16 1-term, Br=128, Bc=128, 1 barrier per k-tile.
// ============================================================================
#define QSTR 136
#define KSTR 136
#define VSTR 136
#define AT_Q     0
#define AT_BUF0  (128*QSTR*2)
#define AT_KH    0
#define AT_VH    (128*KSTR*2)
#define AT_BUFSZ (128*KSTR*2 + 128*VSTR*2)
#define ATTN_SMEM (AT_BUF0 + 2*AT_BUFSZ)

__global__ __launch_bounds__(256, 1)
void attn_tc_kernel(const f16* __restrict__ QbG,
                    const f16* __restrict__ KtG, const f16* __restrict__ VG,
                    f16* __restrict__ Ch)
{
    extern __shared__ char sma[];
    const uint32_t sb = smem_u32(sma);

    const int qt = gridDim.x - 1 - blockIdx.x;
    const int h  = blockIdx.y;
    const int b  = blockIdx.z;
    const int hk = h >> 3;

    const int tid  = threadIdx.x;
    const int warp = tid >> 5;
    const int lane = tid & 31;
    const int g  = lane >> 2;
    const int t4 = lane & 3;

    const float scale = 0.08838834764831845f;
    const int ntiles = qt + 1;

    const f16* kt_g = KtG + (size_t)(b * NKV + hk) * HD * SEQ;
    const f16* v_g  = VG + (size_t)b * SEQ * KVCOLS + hk * HD;

    const int kd = tid >> 1, kc0 = (tid & 1) * 64;
    const int vc = tid >> 1, vd0 = (tid & 1) * 64;

    auto issue_kv = [&](int jt, uint32_t bufb) {
        const f16* kh = kt_g + (size_t)kd * SEQ + jt * 128 + kc0;
        const uint32_t dk = bufb + AT_KH + (uint32_t)(kd * 272 + kc0 * 2);
        #pragma unroll
        for (int u = 0; u < 8; u++)
            cp_async16(dk + u * 16, kh + u * 8);
        const f16* vv = v_g + (size_t)(jt * 128 + vc) * KVCOLS + vd0;
        const uint32_t dv = bufb + AT_VH + (uint32_t)(vc * 272 + vd0 * 2);
        #pragma unroll
        for (int u = 0; u < 8; u++)
            cp_async16(dv + u * 16, vv + u * 8);
    };

    {
        const int r  = tid >> 1;
        const int c0 = (tid & 1) * 64;
        const f16* q = QbG + ((size_t)(b * SEQ + qt * 128 + r)) * QCOLS + h * HD + c0;
        const uint32_t dq = sb + AT_Q + (uint32_t)(r * QSTR * 2 + c0 * 2);
        #pragma unroll
        for (int u = 0; u < 8; u++)
            cp_async16(dq + u * 16, q + u * 8);
    }
    issue_kv(0, sb + AT_BUF0);
    CP_COMMIT;

    float oacc[16][4];
    #pragma unroll
    for (int nt = 0; nt < 16; nt++)
        #pragma unroll
        for (int e = 0; e < 4; e++) oacc[nt][e] = 0.f;
    float mrow0 = -1e30f, mrow1 = -1e30f, lrow0 = 0.f, lrow1 = 0.f;

    const int qrow0 = qt * 128 + warp * 16 + g;
    const int qrow1 = qrow0 + 8;

    const uint32_t q_base = sb + AT_Q + ((warp*16 + (lane & 15)) * QSTR + ((lane >> 4) << 3)) * 2;
    const uint32_t koffB = ((lane & 15) * KSTR + ((lane >> 4) << 3)) * 2;
    const uint32_t voffB = ((lane & 15) * VSTR + ((lane >> 4) << 3)) * 2;

    for (int jt = 0; jt < ntiles; jt++) {
        CP_WAIT0;           // tile jt (and Q on jt==0) complete
        __syncthreads();    // visible to all; compute jt-1 done everywhere
        if (jt + 1 < ntiles) {
            issue_kv(jt + 1, sb + AT_BUF0 + ((jt + 1) & 1) * AT_BUFSZ);
            CP_COMMIT;
        }

        const uint32_t bufb = sb + AT_BUF0 + (jt & 1) * AT_BUFSZ;
        const uint32_t kt_b = bufb + AT_KH + koffB;
        const uint32_t vh_b = bufb + AT_VH + voffB;
        const bool diag = (jt == qt);

        // ---- S = Q @ Kt ----
        float sacc[16][4];
        #pragma unroll
        for (int nt = 0; nt < 16; nt++)
            #pragma unroll
            for (int e = 0; e < 4; e++) sacc[nt][e] = 0.f;

        #pragma unroll
        for (int kk = 0; kk < 8; kk++) {
            uint32_t ah[4];
            ldmatrix_x4(ah, q_base + kk * 16 * sizeof(f16));
            #pragma unroll
            for (int p = 0; p < 8; p++) {
                uint32_t bh[4];
                const uint32_t off = (kk * 16 * KSTR + p * 16) * sizeof(f16);
                ldmatrix_x4_trans(bh, kt_b + off);
                mma_f16(sacc[2*p],   ah, bh);
                mma_f16(sacc[2*p+1], ah, bh + 2);
            }
        }

        // ---- scale, causal mask (diag only), online softmax ----
        float mx0 = -1e30f, mx1 = -1e30f;
        #pragma unroll
        for (int nt = 0; nt < 16; nt++) {
            sacc[nt][0] *= scale;
            sacc[nt][1] *= scale;
            sacc[nt][2] *= scale;
            sacc[nt][3] *= scale;
            if (diag) {
                const int col = jt * 128 + nt * 8 + 2 * t4;
                if (col     > qrow0) sacc[nt][0] = -1e30f;
                if (col + 1 > qrow0) sacc[nt][1] = -1e30f;
                if (col     > qrow1) sacc[nt][2] = -1e30f;
                if (col + 1 > qrow1) sacc[nt][3] = -1e30f;
            }
            mx0 = fmaxf(mx0, fmaxf(sacc[nt][0], sacc[nt][1]));
            mx1 = fmaxf(mx1, fmaxf(sacc[nt][2], sacc[nt][3]));
        }
        mx0 = fmaxf(mx0, __shfl_xor_sync(0xffffffffu, mx0, 1));
        mx0 = fmaxf(mx0, __shfl_xor_sync(0xffffffffu, mx0, 2));
        mx1 = fmaxf(mx1, __shfl_xor_sync(0xffffffffu, mx1, 1));
        mx1 = fmaxf(mx1, __shfl_xor_sync(0xffffffffu, mx1, 2));

        const float mnew0 = fmaxf(mrow0, mx0);
        const float mnew1 = fmaxf(mrow1, mx1);
        const float alpha0 = __expf(mrow0 - mnew0);
        const float alpha1 = __expf(mrow1 - mnew1);

        float rs0 = 0.f, rs1 = 0.f;
        #pragma unroll
        for (int nt = 0; nt < 16; nt++) {
            sacc[nt][0] = __expf(sacc[nt][0] - mnew0);
            sacc[nt][1] = __expf(sacc[nt][1] - mnew0);
            sacc[nt][2] = __expf(sacc[nt][2] - mnew1);
            sacc[nt][3] = __expf(sacc[nt][3] - mnew1);
            rs0 += sacc[nt][0] + sacc[nt][1];
            rs1 += sacc[nt][2] + sacc[nt][3];
        }
        rs0 += __shfl_xor_sync(0xffffffffu, rs0, 1);
        rs0 += __shfl_xor_sync(0xffffffffu, rs0, 2);
        rs1 += __shfl_xor_sync(0xffffffffu, rs1, 1);
        rs1 += __shfl_xor_sync(0xffffffffu, rs1, 2);

        lrow0 = lrow0 * alpha0 + rs0;
        lrow1 = lrow1 * alpha1 + rs1;
        mrow0 = mnew0;
        mrow1 = mnew1;

        #pragma unroll
        for (int nt = 0; nt < 16; nt++) {
            oacc[nt][0] *= alpha0;
            oacc[nt][1] *= alpha0;
            oacc[nt][2] *= alpha1;
            oacc[nt][3] *= alpha1;
        }

        // ---- O += P @ V ----
        #pragma unroll
        for (int c = 0; c < 8; c++) {
            uint32_t ph[4];
            {
                __half2 p0 = __floats2half2_rn(sacc[2*c][0],   sacc[2*c][1]);
                __half2 p1 = __floats2half2_rn(sacc[2*c][2],   sacc[2*c][3]);
                __half2 p2 = __floats2half2_rn(sacc[2*c+1][0], sacc[2*c+1][1]);
                __half2 p3 = __floats2half2_rn(sacc[2*c+1][2], sacc[2*c+1][3]);
                ph[0] = *(uint32_t*)&p0;
                ph[1] = *(uint32_t*)&p1;
                ph[2] = *(uint32_t*)&p2;
                ph[3] = *(uint32_t*)&p3;
            }
            #pragma unroll
            for (int p = 0; p < 8; p++) {
                uint32_t vh[4];
                const uint32_t off = (c * 16 * VSTR + p * 16) * sizeof(f16);
                ldmatrix_x4_trans(vh, vh_b + off);
                mma_f16(oacc[2*p],   ph, vh);
                mma_f16(oacc[2*p+1], ph, vh + 2);
            }
        }
    }

    // ---- epilogue ----
    const float inv0 = 1.0f / lrow0;
    const float inv1 = 1.0f / lrow1;
    const size_t o0 = ((size_t)(b * SEQ + qrow0)) * QCOLS + h * HD;
    const size_t o1 = ((size_t)(b * SEQ + qrow1)) * QCOLS + h * HD;
    #pragma unroll
    for (int nt = 0; nt < 16; nt++) {
        const int col = nt * 8 + 2 * t4;
        __half2 c0 = __floats2half2_rn(oacc[nt][0] * inv0, oacc[nt][1] * inv0);
        __half2 c1 = __floats2half2_rn(oacc[nt][2] * inv1, oacc[nt][3] * inv1);
        *(uint32_t*)(Ch + o0 + col) = *(uint32_t*)&c0;
        *(uint32_t*)(Ch + o1 + col) = *(uint32_t*)&c1;
    }
}

// ============================================================================
// Launch
// ============================================================================
extern "C" void kernel_launch(void* const* d_in, const int* in_sizes, int n_in,
                              void* d_out, int out_size)
{
    const float* hidden = (const float*)d_in[0];
    const int*   pos    = (const int*)  d_in[2];
    const float* Wq     = (const float*)d_in[3];
    const float* Wk     = (const float*)d_in[4];
    const float* Wv     = (const float*)d_in[5];
    const float* Wo     = (const float*)d_in[6];
    const float* qw     = (const float*)d_in[7];
    const float* kw     = (const float*)d_in[8];
    float* out = (float*)d_out;

    float *QKVp;
    f16 *H16, *W16, *Qb, *Ch, *Kt16, *V16;
    cudaGetSymbolAddress((void**)&QKVp, g_QKV);
    cudaGetSymbolAddress((void**)&H16,  g_H16);
    cudaGetSymbolAddress((void**)&W16,  g_W16);
    cudaGetSymbolAddress((void**)&Qb,   g_Qb);
    cudaGetSymbolAddress((void**)&Ch,   g_Ch);
    cudaGetSymbolAddress((void**)&Kt16, g_Kt16);
    cudaGetSymbolAddress((void**)&V16,  g_V16);

    cudaFuncSetAttribute(gemm_1t_f16, cudaFuncAttributeMaxDynamicSharedMemorySize, GEMM_1T_SMEM);
    cudaFuncSetAttribute(attn_tc_kernel, cudaFuncAttributeMaxDynamicSharedMemorySize, ATTN_SMEM);

    init_invf_kernel<<<1, 64>>>();

    round_f16_mat<<<(NTOK*HID/4 + 255)/256, 256>>>(hidden, H16, NTOK*HID/4);
    round_qkv_w<<<(HID*QKVW/4 + 255)/256, 256>>>(Wq, Wk, Wv, W16);

    gemm_1t_f16<<<dim3(QKVW/128, NTOK/128), 256, GEMM_1T_SMEM>>>(H16, W16, QKVp, NTOK, QKVW, HID);

    rmsrope_q_kernel<<<NTOK * NH / 8, 256>>>(QKVp, qw, pos, Qb);
    rmsrope_k_kernel<<<NTOK * NKV / 8, 256>>>(QKVp, kw, pos, Kt16);
    split_v16<<<(NTOK*KVCOLS/4 + 255)/256, 256>>>(QKVp, V16);

    attn_tc_kernel<<<dim3(SEQ/128, NH, BATCH), 256, ATTN_SMEM>>>(Qb, Kt16, V16, Ch);

    round_f16_mat<<<(QCOLS*HID/4 + 255)/256, 256>>>(Wo, W16, QCOLS*HID/4);
    gemm_1t_f16<<<dim3(HID/128, NTOK/128), 256, GEMM_1T_SMEM>>>(Ch, W16, out, NTOK, HID, QCOLS);
}

// round 17
// speedup vs baseline: 5.5420x; 1.0363x over previous
#include <cuda_runtime.h>
#include <cuda_fp16.h>
#include <math.h>
#include <stdint.h>

// Problem constants
#define BATCH 2
#define SEQ   2048
#define HID   2048
#define NH    32
#define NKV   4
#define HD    128
#define NTOK  (BATCH*SEQ)          // 4096
#define QCOLS (NH*HD)              // 4096
#define KVCOLS (NKV*HD)            // 512
#define QKVW  (QCOLS + 2*KVCOLS)   // 5120 (Q|K|V concatenated)

typedef __half f16;

// -------- scratch (device globals) --------
__device__ float g_QKV[(size_t)NTOK * QKVW];
__device__ f16  g_H16[(size_t)NTOK * HID];
__device__ f16  g_W16[(size_t)HID * QKVW];
__device__ f16  g_Qb[(size_t)NTOK * QCOLS];
__device__ f16  g_Ch[(size_t)NTOK * QCOLS];
__device__ f16  g_Kt16[(size_t)BATCH*NKV*HD*SEQ];
__device__ f16  g_V16[(size_t)NTOK * KVCOLS];
__device__ float g_invf[64];

// ============================================================================
// PTX helpers
// ============================================================================
__device__ __forceinline__ uint32_t smem_u32(const void* p) {
    return (uint32_t)__cvta_generic_to_shared(p);
}
__device__ __forceinline__ void ldmatrix_x4(uint32_t* r, uint32_t addr) {
    asm volatile("ldmatrix.sync.aligned.m8n8.x4.shared.b16 {%0,%1,%2,%3}, [%4];"
                 : "=r"(r[0]), "=r"(r[1]), "=r"(r[2]), "=r"(r[3]) : "r"(addr));
}
__device__ __forceinline__ void ldmatrix_x4_trans(uint32_t* r, uint32_t addr) {
    asm volatile("ldmatrix.sync.aligned.m8n8.x4.trans.shared.b16 {%0,%1,%2,%3}, [%4];"
                 : "=r"(r[0]), "=r"(r[1]), "=r"(r[2]), "=r"(r[3]) : "r"(addr));
}
__device__ __forceinline__ void mma_f16(float* d, const uint32_t* a, const uint32_t* b) {
    asm volatile("mma.sync.aligned.m16n8k16.row.col.f32.f16.f16.f32 "
                 "{%0,%1,%2,%3}, {%4,%5,%6,%7}, {%8,%9}, {%0,%1,%2,%3};"
                 : "+f"(d[0]), "+f"(d[1]), "+f"(d[2]), "+f"(d[3])
                 : "r"(a[0]), "r"(a[1]), "r"(a[2]), "r"(a[3]),
                   "r"(b[0]), "r"(b[1]));
}
__device__ __forceinline__ uint2 round4_f16(float4 v) {
    uint2 r;
    __half2 a = __floats2half2_rn(v.x, v.y);
    __half2 b = __floats2half2_rn(v.z, v.w);
    r.x = *(uint32_t*)&a;
    r.y = *(uint32_t*)&b;
    return r;
}
__device__ __forceinline__ void cp_async16(uint32_t dst, const void* src) {
    asm volatile("cp.async.cg.shared.global [%0], [%1], 16;" :: "r"(dst), "l"(src));
}
#define CP_COMMIT asm volatile("cp.async.commit_group;")
#define CP_WAIT0  asm volatile("cp.async.wait_group 0;" ::: "memory")
#define CP_WAIT1  asm volatile("cp.async.wait_group 1;" ::: "memory")

// ============================================================================
// Init: inv_freq table
// ============================================================================
__global__ void init_invf_kernel()
{
    const int j = threadIdx.x;
    g_invf[j] = (float)pow(1.0e6, -(double)j / 64.0);
}

// ============================================================================
// Elementwise kernels
// ============================================================================
__global__ __launch_bounds__(256)
void round_f16_mat(const float* __restrict__ src, f16* __restrict__ d, int n4)
{
    const int i = blockIdx.x * 256 + threadIdx.x;
    if (i < n4) ((uint2*)d)[i] = round4_f16(((const float4*)src)[i]);
}

__global__ __launch_bounds__(256)
void round_qkv_w(const float* __restrict__ Wq, const float* __restrict__ Wk,
                 const float* __restrict__ Wv, f16* __restrict__ d)
{
    const int i = blockIdx.x * 256 + threadIdx.x;
    if (i >= HID * QKVW / 4) return;
    const int row = i / (QKVW / 4);
    const int c4  = (i % (QKVW / 4)) * 4;
    float4 v;
    if (c4 < QCOLS)               v = *(const float4*)(Wq + (size_t)row * QCOLS + c4);
    else if (c4 < QCOLS + KVCOLS) v = *(const float4*)(Wk + (size_t)row * KVCOLS + (c4 - QCOLS));
    else                          v = *(const float4*)(Wv + (size_t)row * KVCOLS + (c4 - QCOLS - KVCOLS));
    *(uint2*)(d + (size_t)row * QKVW + c4) = round4_f16(v);
}

__global__ __launch_bounds__(256)
void split_v16(const float* __restrict__ QKV, f16* __restrict__ d)
{
    const int i = blockIdx.x * 256 + threadIdx.x;
    if (i >= NTOK * KVCOLS / 4) return;
    const int tok = i / (KVCOLS / 4);
    const int c4  = (i % (KVCOLS / 4)) * 4;
    float4 v = *(const float4*)(QKV + (size_t)tok * QKVW + QCOLS + KVCOLS + c4);
    *(uint2*)(d + (size_t)tok * KVCOLS + c4) = round4_f16(v);
}

// ============================================================================
// RMSNorm + RoPE, warp-per-head.
// ============================================================================
__device__ __forceinline__ float4 rmsrope_warp(float4 v, float4 wv, int p, int lane)
{
    float ss = v.x*v.x + v.y*v.y + v.z*v.z + v.w*v.w;
    #pragma unroll
    for (int m = 16; m; m >>= 1) ss += __shfl_xor_sync(0xffffffffu, ss, m);
    const float inv = rsqrtf(ss * (1.0f / 128.0f) + 1e-6f);

    float4 xs;
    xs.x = v.x * inv * wv.x;
    xs.y = v.y * inv * wv.y;
    xs.z = v.z * inv * wv.z;
    xs.w = v.w * inv * wv.w;

    float4 pr;
    pr.x = __shfl_xor_sync(0xffffffffu, xs.x, 16);
    pr.y = __shfl_xor_sync(0xffffffffu, xs.y, 16);
    pr.z = __shfl_xor_sync(0xffffffffu, xs.z, 16);
    pr.w = __shfl_xor_sync(0xffffffffu, xs.w, 16);

    const int d0 = lane * 4;
    const float sign = (d0 < 64) ? -1.0f : 1.0f;
    const int j0 = d0 & 63;
    float4 out;
    {
        float c, s;
        sincosf((float)p * g_invf[j0 + 0], &s, &c);
        out.x = xs.x * c + sign * pr.x * s;
        sincosf((float)p * g_invf[j0 + 1], &s, &c);
        out.y = xs.y * c + sign * pr.y * s;
        sincosf((float)p * g_invf[j0 + 2], &s, &c);
        out.z = xs.z * c + sign * pr.z * s;
        sincosf((float)p * g_invf[j0 + 3], &s, &c);
        out.w = xs.w * c + sign * pr.w * s;
    }
    return out;
}

__global__ __launch_bounds__(256)
void rmsrope_q_kernel(const float* __restrict__ QKV, const float* __restrict__ w,
                      const int* __restrict__ pos, f16* __restrict__ Qb)
{
    const int gw = blockIdx.x * 8 + (threadIdx.x >> 5);
    const int lane = threadIdx.x & 31;
    const int token = gw >> 5;
    const int h     = gw & 31;
    const int d0 = lane * 4;

    float4 v  = *(const float4*)(QKV + (size_t)token * QKVW + h * HD + d0);
    float4 wv = *(const float4*)(w + d0);
    float4 out = rmsrope_warp(v, wv, pos[token], lane);
    *(uint2*)(Qb + (size_t)token * QCOLS + h * HD + d0) = round4_f16(out);
}

__global__ __launch_bounds__(256)
void rmsrope_k_kernel(const float* __restrict__ QKV, const float* __restrict__ w,
                      const int* __restrict__ pos, f16* __restrict__ Kt)
{
    const int gw = blockIdx.x * 8 + (threadIdx.x >> 5);
    const int lane = threadIdx.x & 31;
    const int token = gw >> 2;
    const int hk    = gw & 3;
    const int d0 = lane * 4;

    float4 v  = *(const float4*)(QKV + (size_t)token * QKVW + QCOLS + hk * HD + d0);
    float4 wv = *(const float4*)(w + d0);
    float4 out = rmsrope_warp(v, wv, pos[token], lane);

    const int b  = token >> 11;
    const int ts = token & (SEQ - 1);
    f16* dst = Kt + ((size_t)(b * NKV + hk) * HD + d0) * SEQ + ts;
    dst[0 * SEQ] = __float2half_rn(out.x);
    dst[1 * SEQ] = __float2half_rn(out.y);
    dst[2 * SEQ] = __float2half_rn(out.z);
    dst[3 * SEQ] = __float2half_rn(out.w);
}

// ============================================================================
// GEMM fp16 1-term, TRIPLE-buffered, 1 barrier per k-tile. (unchanged)
// ============================================================================
#define ASTR 40
#define BSTR 136
#define G1_A 0
#define G1_B 10240
#define G1_SZ 18944
#define GEMM_1T_SMEM (3 * G1_SZ)

__global__ __launch_bounds__(256, 2)
void gemm_1t_f16(const f16* __restrict__ A_g, const f16* __restrict__ B_g,
                 float* __restrict__ C, int M, int N, int K)
{
    extern __shared__ char smg[];
    const uint32_t sb = smem_u32(smg);

    const int tid  = threadIdx.x;
    const int warp = tid >> 5;
    const int lane = tid & 31;
    const int wm = (warp >> 1) * 32;
    const int wn = (warp & 1) * 64;
    const int bx = blockIdx.x * 128;
    const int by = blockIdx.y * 128;

    float acc[2][8][4];
    #pragma unroll
    for (int mi = 0; mi < 2; mi++)
        #pragma unroll
        for (int ni = 0; ni < 8; ni++)
            #pragma unroll
            for (int e = 0; e < 4; e++) acc[mi][ni][e] = 0.f;

    const int ar = tid >> 1, acb = (tid & 1) * 16;
    const int brw = tid >> 3, bcb = (tid & 7) * 16;

    auto issue_tile = [&](int k0, uint32_t bufb) {
        const f16* a = A_g + (size_t)(by + ar) * K + k0 + acb;
        const uint32_t da = bufb + G1_A + (uint32_t)(ar * 80 + acb * 2);
        cp_async16(da,      a);
        cp_async16(da + 16, a + 8);
        const f16* b = B_g + (size_t)(k0 + brw) * N + bx + bcb;
        const uint32_t db = bufb + G1_B + (uint32_t)(brw * 272 + bcb * 2);
        cp_async16(db,      b);
        cp_async16(db + 16, b + 8);
    };

    const int aoff = (wm + (lane & 15)) * ASTR + ((lane >> 4) << 3);
    const int boff = (lane & 15) * BSTR + wn + ((lane >> 4) << 3);

    const int NIT = K >> 5;

    issue_tile(0, sb);
    CP_COMMIT;
    issue_tile(32, sb + G1_SZ);
    CP_COMMIT;

    int bufidx = 0;
    for (int t = 0; t < NIT; t++) {
        if (t + 1 < NIT) { CP_WAIT1; } else { CP_WAIT0; }
        __syncthreads();

        if (t + 2 < NIT) {
            int nb = bufidx + 2;
            if (nb >= 3) nb -= 3;
            issue_tile((t + 2) * 32, sb + nb * G1_SZ);
            CP_COMMIT;
        }

        const uint32_t bufb = sb + bufidx * G1_SZ;
        const uint32_t A_b = bufb + G1_A;
        const uint32_t B_b = bufb + G1_B;

        #pragma unroll
        for (int kk = 0; kk < 32; kk += 16) {
            uint32_t ah[2][4];
            #pragma unroll
            for (int mi = 0; mi < 2; mi++)
                ldmatrix_x4(ah[mi], A_b + (aoff + mi * 16 * ASTR + kk) * 2);
            #pragma unroll
            for (int p = 0; p < 4; p++) {
                uint32_t bh[4];
                const uint32_t off = (boff + kk * BSTR + p * 16) * 2;
                ldmatrix_x4_trans(bh, B_b + off);
                #pragma unroll
                for (int mi = 0; mi < 2; mi++) {
                    mma_f16(acc[mi][2*p],   ah[mi], bh);
                    mma_f16(acc[mi][2*p+1], ah[mi], bh + 2);
                }
            }
        }

        if (++bufidx == 3) bufidx = 0;
    }

    const int g = lane >> 2;
    const int t = lane & 3;
    #pragma unroll
    for (int mi = 0; mi < 2; mi++) {
        #pragma unroll
        for (int ni = 0; ni < 8; ni++) {
            const size_t row0 = (size_t)(by + wm + mi * 16 + g);
            const int col = bx + wn + ni * 8 + 2 * t;
            *(float2*)(C + row0 * N + col)       = make_float2(acc[mi][ni][0], acc[mi][ni][1]);
            *(float2*)(C + (row0 + 8) * N + col) = make_float2(acc[mi][ni][2], acc[mi][ni][3]);
        }
    }
}

// ============================================================================
// Flash attention: fp16 1-term, Br=128, Bc=64, 2 CTAs/SM (104KB smem),
// single barrier per k-tile. Per-warp skip of fully-masked tiles.
// ============================================================================
#define QSTR 136
#define KSTR 72
#define VSTR 136
#define AT_Q     0
#define AT_BUF0  (128*QSTR*2)
#define AT_KH    0
#define AT_VH    (128*KSTR*2)
#define AT_BUFSZ (128*KSTR*2 + 64*VSTR*2)
#define ATTN_SMEM (AT_BUF0 + 2*AT_BUFSZ)

__global__ __launch_bounds__(256, 2)
void attn_tc_kernel(const f16* __restrict__ QbG,
                    const f16* __restrict__ KtG, const f16* __restrict__ VG,
                    f16* __restrict__ Ch)
{
    extern __shared__ char sma[];
    const uint32_t sb = smem_u32(sma);

    const int qt = gridDim.x - 1 - blockIdx.x;
    const int h  = blockIdx.y;
    const int b  = blockIdx.z;
    const int hk = h >> 3;

    const int tid  = threadIdx.x;
    const int warp = tid >> 5;
    const int lane = tid & 31;
    const int g  = lane >> 2;
    const int t4 = lane & 3;

    const float scale = 0.08838834764831845f;
    const int ntiles = 2 * qt + 2;   // k-tiles of 64

    const f16* kt_g = KtG + (size_t)(b * NKV + hk) * HD * SEQ;
    const f16* v_g  = VG + (size_t)b * SEQ * KVCOLS + hk * HD;

    const int kd = tid >> 1, kc0 = (tid & 1) * 32;    // K: d-row 0..127, tok base
    const int vc = tid >> 2, vd0 = (tid & 3) * 32;    // V: tok-row 0..63, d base

    auto issue_kv = [&](int jt, uint32_t bufb) {
        const f16* kh = kt_g + (size_t)kd * SEQ + jt * 64 + kc0;
        const uint32_t dk = bufb + AT_KH + (uint32_t)(kd * 144 + kc0 * 2);
        #pragma unroll
        for (int u = 0; u < 4; u++)
            cp_async16(dk + u * 16, kh + u * 8);
        const f16* vv = v_g + (size_t)(jt * 64 + vc) * KVCOLS + vd0;
        const uint32_t dv = bufb + AT_VH + (uint32_t)(vc * 272 + vd0 * 2);
        #pragma unroll
        for (int u = 0; u < 4; u++)
            cp_async16(dv + u * 16, vv + u * 8);
    };

    // prefetch Q + KV tile 0
    {
        const int r  = tid >> 1;
        const int c0 = (tid & 1) * 64;
        const f16* q = QbG + ((size_t)(b * SEQ + qt * 128 + r)) * QCOLS + h * HD + c0;
        const uint32_t dq = sb + AT_Q + (uint32_t)(r * QSTR * 2 + c0 * 2);
        #pragma unroll
        for (int u = 0; u < 8; u++)
            cp_async16(dq + u * 16, q + u * 8);
    }
    issue_kv(0, sb + AT_BUF0);
    CP_COMMIT;

    float oacc[16][4];
    #pragma unroll
    for (int nt = 0; nt < 16; nt++)
        #pragma unroll
        for (int e = 0; e < 4; e++) oacc[nt][e] = 0.f;
    float mrow0 = -1e30f, mrow1 = -1e30f, lrow0 = 0.f, lrow1 = 0.f;

    const int qrow0 = qt * 128 + warp * 16 + g;
    const int qrow1 = qrow0 + 8;
    const int warp_maxrow = qt * 128 + warp * 16 + 15;

    const uint32_t q_base = sb + AT_Q + ((warp*16 + (lane & 15)) * QSTR + ((lane >> 4) << 3)) * 2;
    const uint32_t koffB = ((lane & 15) * KSTR + ((lane >> 4) << 3)) * 2;
    const uint32_t voffB = ((lane & 15) * VSTR + ((lane >> 4) << 3)) * 2;

    for (int jt = 0; jt < ntiles; jt++) {
        CP_WAIT0;
        __syncthreads();
        if (jt + 1 < ntiles) {
            issue_kv(jt + 1, sb + AT_BUF0 + ((jt + 1) & 1) * AT_BUFSZ);
            CP_COMMIT;
        }

        if (jt * 64 > warp_maxrow) continue;   // fully masked for this warp

        const uint32_t bufb = sb + AT_BUF0 + (jt & 1) * AT_BUFSZ;
        const uint32_t kt_b = bufb + AT_KH + koffB;
        const uint32_t vh_b = bufb + AT_VH + voffB;
        const bool diag = (jt >= 2 * qt);      // last two tiles straddle diagonal

        // ---- S = Q @ Kt ----
        float sacc[8][4];
        #pragma unroll
        for (int nt = 0; nt < 8; nt++)
            #pragma unroll
            for (int e = 0; e < 4; e++) sacc[nt][e] = 0.f;

        #pragma unroll
        for (int kk = 0; kk < 8; kk++) {
            uint32_t ah[4];
            ldmatrix_x4(ah, q_base + kk * 16 * sizeof(f16));
            #pragma unroll
            for (int p = 0; p < 4; p++) {
                uint32_t bh[4];
                const uint32_t off = (kk * 16 * KSTR + p * 16) * sizeof(f16);
                ldmatrix_x4_trans(bh, kt_b + off);
                mma_f16(sacc[2*p],   ah, bh);
                mma_f16(sacc[2*p+1], ah, bh + 2);
            }
        }

        // ---- scale, causal mask (diag tiles only), online softmax ----
        float mx0 = -1e30f, mx1 = -1e30f;
        #pragma unroll
        for (int nt = 0; nt < 8; nt++) {
            sacc[nt][0] *= scale;
            sacc[nt][1] *= scale;
            sacc[nt][2] *= scale;
            sacc[nt][3] *= scale;
            if (diag) {
                const int col = jt * 64 + nt * 8 + 2 * t4;
                if (col     > qrow0) sacc[nt][0] = -1e30f;
                if (col + 1 > qrow0) sacc[nt][1] = -1e30f;
                if (col     > qrow1) sacc[nt][2] = -1e30f;
                if (col + 1 > qrow1) sacc[nt][3] = -1e30f;
            }
            mx0 = fmaxf(mx0, fmaxf(sacc[nt][0], sacc[nt][1]));
            mx1 = fmaxf(mx1, fmaxf(sacc[nt][2], sacc[nt][3]));
        }
        mx0 = fmaxf(mx0, __shfl_xor_sync(0xffffffffu, mx0, 1));
        mx0 = fmaxf(mx0, __shfl_xor_sync(0xffffffffu, mx0, 2));
        mx1 = fmaxf(mx1, __shfl_xor_sync(0xffffffffu, mx1, 1));
        mx1 = fmaxf(mx1, __shfl_xor_sync(0xffffffffu, mx1, 2));

        const float mnew0 = fmaxf(mrow0, mx0);
        const float mnew1 = fmaxf(mrow1, mx1);
        const float alpha0 = __expf(mrow0 - mnew0);
        const float alpha1 = __expf(mrow1 - mnew1);

        float rs0 = 0.f, rs1 = 0.f;
        #pragma unroll
        for (int nt = 0; nt < 8; nt++) {
            sacc[nt][0] = __expf(sacc[nt][0] - mnew0);
            sacc[nt][1] = __expf(sacc[nt][1] - mnew0);
            sacc[nt][2] = __expf(sacc[nt][2] - mnew1);
            sacc[nt][3] = __expf(sacc[nt][3] - mnew1);
            rs0 += sacc[nt][0] + sacc[nt][1];
            rs1 += sacc[nt][2] + sacc[nt][3];
        }
        rs0 += __shfl_xor_sync(0xffffffffu, rs0, 1);
        rs0 += __shfl_xor_sync(0xffffffffu, rs0, 2);
        rs1 += __shfl_xor_sync(0xffffffffu, rs1, 1);
        rs1 += __shfl_xor_sync(0xffffffffu, rs1, 2);

        lrow0 = lrow0 * alpha0 + rs0;
        lrow1 = lrow1 * alpha1 + rs1;
        mrow0 = mnew0;
        mrow1 = mnew1;

        #pragma unroll
        for (int nt = 0; nt < 16; nt++) {
            oacc[nt][0] *= alpha0;
            oacc[nt][1] *= alpha0;
            oacc[nt][2] *= alpha1;
            oacc[nt][3] *= alpha1;
        }

        // ---- O += P @ V ----
        #pragma unroll
        for (int c = 0; c < 4; c++) {
            uint32_t ph[4];
            {
                __half2 p0 = __floats2half2_rn(sacc[2*c][0],   sacc[2*c][1]);
                __half2 p1 = __floats2half2_rn(sacc[2*c][2],   sacc[2*c][3]);
                __half2 p2 = __floats2half2_rn(sacc[2*c+1][0], sacc[2*c+1][1]);
                __half2 p3 = __floats2half2_rn(sacc[2*c+1][2], sacc[2*c+1][3]);
                ph[0] = *(uint32_t*)&p0;
                ph[1] = *(uint32_t*)&p1;
                ph[2] = *(uint32_t*)&p2;
                ph[3] = *(uint32_t*)&p3;
            }
            #pragma unroll
            for (int p = 0; p < 8; p++) {
                uint32_t vh[4];
                const uint32_t off = (c * 16 * VSTR + p * 16) * sizeof(f16);
                ldmatrix_x4_trans(vh, vh_b + off);
                mma_f16(oacc[2*p],   ph, vh);
                mma_f16(oacc[2*p+1], ph, vh + 2);
            }
        }
    }

    // ---- epilogue ----
    const float inv0 = 1.0f / lrow0;
    const float inv1 = 1.0f / lrow1;
    const size_t o0 = ((size_t)(b * SEQ + qrow0)) * QCOLS + h * HD;
    const size_t o1 = ((size_t)(b * SEQ + qrow1)) * QCOLS + h * HD;
    #pragma unroll
    for (int nt = 0; nt < 16; nt++) {
        const int col = nt * 8 + 2 * t4;
        __half2 c0 = __floats2half2_rn(oacc[nt][0] * inv0, oacc[nt][1] * inv0);
        __half2 c1 = __floats2half2_rn(oacc[nt][2] * inv1, oacc[nt][3] * inv1);
        *(uint32_t*)(Ch + o0 + col) = *(uint32_t*)&c0;
        *(uint32_t*)(Ch + o1 + col) = *(uint32_t*)&c1;
    }
}

// ============================================================================
// Launch
// ============================================================================
extern "C" void kernel_launch(void* const* d_in, const int* in_sizes, int n_in,
                              void* d_out, int out_size)
{
    const float* hidden = (const float*)d_in[0];
    const int*   pos    = (const int*)  d_in[2];
    const float* Wq     = (const float*)d_in[3];
    const float* Wk     = (const float*)d_in[4];
    const float* Wv     = (const float*)d_in[5];
    const float* Wo     = (const float*)d_in[6];
    const float* qw     = (const float*)d_in[7];
    const float* kw     = (const float*)d_in[8];
    float* out = (float*)d_out;

    float *QKVp;
    f16 *H16, *W16, *Qb, *Ch, *Kt16, *V16;
    cudaGetSymbolAddress((void**)&QKVp, g_QKV);
    cudaGetSymbolAddress((void**)&H16,  g_H16);
    cudaGetSymbolAddress((void**)&W16,  g_W16);
    cudaGetSymbolAddress((void**)&Qb,   g_Qb);
    cudaGetSymbolAddress((void**)&Ch,   g_Ch);
    cudaGetSymbolAddress((void**)&Kt16, g_Kt16);
    cudaGetSymbolAddress((void**)&V16,  g_V16);

    cudaFuncSetAttribute(gemm_1t_f16, cudaFuncAttributeMaxDynamicSharedMemorySize, GEMM_1T_SMEM);
    cudaFuncSetAttribute(attn_tc_kernel, cudaFuncAttributeMaxDynamicSharedMemorySize, ATTN_SMEM);

    init_invf_kernel<<<1, 64>>>();

    round_f16_mat<<<(NTOK*HID/4 + 255)/256, 256>>>(hidden, H16, NTOK*HID/4);
    round_qkv_w<<<(HID*QKVW/4 + 255)/256, 256>>>(Wq, Wk, Wv, W16);

    gemm_1t_f16<<<dim3(QKVW/128, NTOK/128), 256, GEMM_1T_SMEM>>>(H16, W16, QKVp, NTOK, QKVW, HID);

    rmsrope_q_kernel<<<NTOK * NH / 8, 256>>>(QKVp, qw, pos, Qb);
    rmsrope_k_kernel<<<NTOK * NKV / 8, 256>>>(QKVp, kw, pos, Kt16);
    split_v16<<<(NTOK*KVCOLS/4 + 255)/256, 256>>>(QKVp, V16);

    attn_tc_kernel<<<dim3(SEQ/128, NH, BATCH), 256, ATTN_SMEM>>>(Qb, Kt16, V16, Ch);

    round_f16_mat<<<(QCOLS*HID/4 + 255)/256, 256>>>(Wo, W16, QCOLS*HID/4);
    gemm_1t_f16<<<dim3(HID/128, NTOK/128), 256, GEMM_1T_SMEM>>>(Ch, W16, out, NTOK, HID, QCOLS);
}